// round 6
// baseline (speedup 1.0000x reference)
#include <cuda_runtime.h>
#include <cuda_bf16.h>
#include <math.h>
#include <stdint.h>

#define B_  4
#define S_  2048
#define D_  1024
#define H_  16
#define HD_ 64
#define M_  (B_ * S_)
#define NTOT (B_ * S_ * D_)

// Scratch (allocation-free rule: __device__ globals)
__device__ float g_q[NTOT];
__device__ float g_k[NTOT];
__device__ __nv_bfloat16 g_xh[NTOT];
__device__ __nv_bfloat16 g_xl[NTOT];
__device__ __nv_bfloat16 g_wh[D_ * D_];
__device__ __nv_bfloat16 g_wl[D_ * D_];
__device__ __nv_bfloat16 g_qh[NTOT];
__device__ __nv_bfloat16 g_ql[NTOT];
__device__ __nv_bfloat16 g_kh[NTOT];
__device__ __nv_bfloat16 g_kl[NTOT];
__device__ __nv_bfloat16 g_vh[NTOT];
__device__ __nv_bfloat16 g_vl[NTOT];
__device__ float2 g_rope[S_ * 32];

// ===========================================================================
// Helpers (baseline PTX only — compute_103-safe)
// ===========================================================================
__device__ __forceinline__ uint32_t smem_to_u32(const void* p) {
    uint32_t a;
    asm("{ .reg .u64 t; cvta.to.shared.u64 t, %1; cvt.u32.u64 %0, t; }" : "=r"(a) : "l"(p));
    return a;
}
#define SMEM_SWIZZLE_128B(off) ((off) ^ (((off) >> 3) & 0x70))
#define SMEM_SWIZZLE_64B(off)  ((off) ^ (((off) >> 3) & 0x30))

__device__ __forceinline__ void cpa16(uint32_t dst, const void* src) {
    asm volatile("cp.async.cg.shared.global [%0], [%1], 16;" :: "r"(dst), "l"(src));
}
__device__ __forceinline__ void ldsm4(uint32_t& r0, uint32_t& r1, uint32_t& r2, uint32_t& r3,
                                      uint32_t addr) {
    asm volatile("ldmatrix.sync.aligned.m8n8.x4.shared.b16 {%0,%1,%2,%3}, [%4];"
        : "=r"(r0), "=r"(r1), "=r"(r2), "=r"(r3) : "r"(addr));
}
__device__ __forceinline__ void ldsm4t(uint32_t& r0, uint32_t& r1, uint32_t& r2, uint32_t& r3,
                                       uint32_t addr) {
    asm volatile("ldmatrix.sync.aligned.m8n8.x4.trans.shared.b16 {%0,%1,%2,%3}, [%4];"
        : "=r"(r0), "=r"(r1), "=r"(r2), "=r"(r3) : "r"(addr));
}
__device__ __forceinline__ void mma_bf16(float* d, const uint32_t* a,
                                         uint32_t b0, uint32_t b1) {
    asm volatile(
        "mma.sync.aligned.m16n8k16.row.col.f32.bf16.bf16.f32 "
        "{%0,%1,%2,%3}, {%4,%5,%6,%7}, {%8,%9}, {%0,%1,%2,%3};"
        : "+f"(d[0]), "+f"(d[1]), "+f"(d[2]), "+f"(d[3])
        : "r"(a[0]), "r"(a[1]), "r"(a[2]), "r"(a[3]), "r"(b0), "r"(b1));
}
__device__ __forceinline__ void split2(float f0, float f1, uint32_t& hi, uint32_t& lo) {
    __nv_bfloat16 h0 = __float2bfloat16(f0), h1 = __float2bfloat16(f1);
    __nv_bfloat16 l0 = __float2bfloat16(f0 - __bfloat162float(h0));
    __nv_bfloat16 l1 = __float2bfloat16(f1 - __bfloat162float(h1));
    __nv_bfloat162 Hh(h0, h1), Ll(l0, l1);
    hi = *(uint32_t*)&Hh; lo = *(uint32_t*)&Ll;
}

// ===========================================================================
// fp32 -> bf16 (hi, lo) split
// ===========================================================================
__global__ __launch_bounds__(256)
void split_kernel(const float* __restrict__ x,
                  __nv_bfloat16* __restrict__ h,
                  __nv_bfloat16* __restrict__ l, int n4)
{
    int i = blockIdx.x * blockDim.x + threadIdx.x;
    if (i >= n4) return;
    float4 v = ((const float4*)x)[i];
    uint32_t h01, l01, h23, l23;
    split2(v.x, v.y, h01, l01);
    split2(v.z, v.w, h23, l23);
    ((uint32_t*)h)[2 * i + 0] = h01;
    ((uint32_t*)h)[2 * i + 1] = h23;
    ((uint32_t*)l)[2 * i + 0] = l01;
    ((uint32_t*)l)[2 * i + 1] = l23;
}

// ===========================================================================
// mma.sync bf16-split GEMM. BK=32, 2 stages x 32KB -> 2 CTAs/SM.
// Templated epilogue: fp32 out, or fused bf16 hi/lo split out.
// ===========================================================================
#define T32 8192                      // 128 rows x 64 B
#define STAGE32 (4 * T32)             // 32768
#define GEMM_SMEM (2 * STAGE32)       // 65536
#define NCHUNK32 (D_ / 32)            // 32

__device__ __forceinline__ void gemm_load_chunk32(
    uint32_t sb, int stage, int k0, int tid,
    const __nv_bfloat16* Ahb, const __nv_bfloat16* Alb,
    const __nv_bfloat16* Bhb, const __nv_bfloat16* Blb)
{
    uint32_t base = sb + stage * STAGE32;
#pragma unroll
    for (int rep = 0; rep < 2; rep++) {
        int id  = tid + rep * 256;
        int row = id >> 2;           // 0..127
        int seg = id & 3;            // 16B segment within 64B row
        uint32_t soff = SMEM_SWIZZLE_64B((uint32_t)(row * 64 + seg * 16));
        size_t goff = (size_t)row * D_ + k0 + seg * 8;
        cpa16(base + 0 * T32 + soff, Ahb + goff);
        cpa16(base + 1 * T32 + soff, Alb + goff);
        cpa16(base + 2 * T32 + soff, Bhb + goff);
        cpa16(base + 3 * T32 + soff, Blb + goff);
    }
    asm volatile("cp.async.commit_group;" ::: "memory");
}

template <bool SPLIT_OUT>
__global__ __launch_bounds__(256)
void gemm_mma(const __nv_bfloat16* __restrict__ Ah, const __nv_bfloat16* __restrict__ Al,
              const __nv_bfloat16* __restrict__ Bh, const __nv_bfloat16* __restrict__ Bl,
              const float* __restrict__ bias, float* __restrict__ C,
              __nv_bfloat16* __restrict__ Ch, __nv_bfloat16* __restrict__ Cl)
{
    extern __shared__ char smem[];
    uint32_t sb = smem_to_u32(smem);
    const int tid  = threadIdx.x;
    const int wid  = tid >> 5;
    const int lane = tid & 31;
    const int warp_m = wid >> 2;
    const int warp_n = wid & 3;
    const int bn = blockIdx.x, bm = blockIdx.y;

    const __nv_bfloat16* Ahb = Ah + (size_t)(bm * 128) * D_;
    const __nv_bfloat16* Alb = Al + (size_t)(bm * 128) * D_;
    const __nv_bfloat16* Bhb = Bh + (size_t)(bn * 128) * D_;
    const __nv_bfloat16* Blb = Bl + (size_t)(bn * 128) * D_;

    float acc[4][4][4];
#pragma unroll
    for (int i = 0; i < 4; i++)
#pragma unroll
        for (int j = 0; j < 4; j++)
#pragma unroll
            for (int r = 0; r < 4; r++) acc[i][j][r] = 0.f;

    const int mat = lane >> 3;
    const int mrr = lane & 7;
    const int a_row_off = (mat & 1) * 8 + mrr;
    const int a_ks_off  = (mat >> 1) * 16;
    const int b_row_off = (mat >> 1) * 8 + mrr;
    const int b_ks_off  = (mat & 1) * 16;

    gemm_load_chunk32(sb, 0, 0, tid, Ahb, Alb, Bhb, Blb);

    for (int c = 0; c < NCHUNK32; c++) {
        int s = c & 1;
        if (c + 1 < NCHUNK32) {
            gemm_load_chunk32(sb, s ^ 1, (c + 1) * 32, tid, Ahb, Alb, Bhb, Blb);
            asm volatile("cp.async.wait_group 1;" ::: "memory");
        } else {
            asm volatile("cp.async.wait_group 0;" ::: "memory");
        }
        __syncthreads();

        uint32_t stA = sb + s * STAGE32;
#pragma unroll
        for (int ks = 0; ks < 2; ks++) {
            const int kb = ks * 32;
            uint32_t ah[4][4], al[4][4];
#pragma unroll
            for (int mt = 0; mt < 4; mt++) {
                int row = warp_m * 64 + mt * 16 + a_row_off;
                uint32_t off = SMEM_SWIZZLE_64B((uint32_t)(row * 64 + kb + a_ks_off));
                ldsm4(ah[mt][0], ah[mt][1], ah[mt][2], ah[mt][3], stA + 0 * T32 + off);
                ldsm4(al[mt][0], al[mt][1], al[mt][2], al[mt][3], stA + 1 * T32 + off);
            }
            uint32_t bh[2][4], bl[2][4];
#pragma unroll
            for (int p = 0; p < 2; p++) {
                int row = warp_n * 32 + p * 16 + b_row_off;
                uint32_t off = SMEM_SWIZZLE_64B((uint32_t)(row * 64 + kb + b_ks_off));
                ldsm4(bh[p][0], bh[p][1], bh[p][2], bh[p][3], stA + 2 * T32 + off);
                ldsm4(bl[p][0], bl[p][1], bl[p][2], bl[p][3], stA + 3 * T32 + off);
            }
#pragma unroll
            for (int mt = 0; mt < 4; mt++) {
#pragma unroll
                for (int p = 0; p < 2; p++) {
#pragma unroll
                    for (int q = 0; q < 2; q++) {
                        float* d = acc[mt][p * 2 + q];
                        mma_bf16(d, ah[mt], bh[p][q * 2], bh[p][q * 2 + 1]);
                        mma_bf16(d, ah[mt], bl[p][q * 2], bl[p][q * 2 + 1]);
                        mma_bf16(d, al[mt], bh[p][q * 2], bh[p][q * 2 + 1]);
                    }
                }
            }
        }
        __syncthreads();
    }

    const int rbase = bm * 128 + warp_m * 64 + (lane >> 2);
    const int cbase = bn * 128 + warp_n * 32 + (lane & 3) * 2;
#pragma unroll
    for (int mt = 0; mt < 4; mt++) {
#pragma unroll
        for (int nt = 0; nt < 4; nt++) {
            int col = cbase + nt * 8;
            float b0 = bias[col], b1 = bias[col + 1];
            float* d = acc[mt][nt];
            int r0 = rbase + mt * 16;
            float v00 = d[0] + b0, v01 = d[1] + b1;
            float v10 = d[2] + b0, v11 = d[3] + b1;
            if (SPLIT_OUT) {
                uint32_t hi, lo;
                split2(v00, v01, hi, lo);
                *(uint32_t*)(Ch + (size_t)r0 * D_ + col) = hi;
                *(uint32_t*)(Cl + (size_t)r0 * D_ + col) = lo;
                split2(v10, v11, hi, lo);
                *(uint32_t*)(Ch + (size_t)(r0 + 8) * D_ + col) = hi;
                *(uint32_t*)(Cl + (size_t)(r0 + 8) * D_ + col) = lo;
            } else {
                *(float2*)(C + (size_t)r0 * D_ + col)       = make_float2(v00, v01);
                *(float2*)(C + (size_t)(r0 + 8) * D_ + col) = make_float2(v10, v11);
            }
        }
    }
}

// ---------------------------------------------------------------------------
// RoPE table (fp64 for exactness)
// ---------------------------------------------------------------------------
__global__ void rope_table_kernel(float2* __restrict__ tab)
{
    int idx = blockIdx.x * blockDim.x + threadIdx.x;
    if (idx >= S_ * 32) return;
    int s = idx >> 5;
    int d = idx & 31;
    double inv = exp(-log(10000.0) * (double)d / 32.0);
    double ang = (double)s * inv;
    double sd, cd;
    sincos(ang, &sd, &cd);
    tab[idx] = make_float2((float)cd, (float)sd);
}

// ---------------------------------------------------------------------------
// Fused RoPE + bf16 hi/lo split for Q and K
// ---------------------------------------------------------------------------
__global__ __launch_bounds__(256)
void rope_split_kernel(const float* __restrict__ q, const float* __restrict__ k,
                       const float2* __restrict__ tab,
                       __nv_bfloat16* __restrict__ qh, __nv_bfloat16* __restrict__ ql,
                       __nv_bfloat16* __restrict__ kh, __nv_bfloat16* __restrict__ kl)
{
    const int half = B_ * S_ * H_ * 8;
    int idx = blockIdx.x * blockDim.x + threadIdx.x;
    if (idx >= 2 * half) return;
    const float* x = (idx < half) ? q : k;
    __nv_bfloat16* oh = (idx < half) ? qh : kh;
    __nv_bfloat16* ol = (idx < half) ? ql : kl;
    int i = (idx < half) ? idx : idx - half;

    int dv = (i & 7) << 2;
    int h  = (i >> 3) & (H_ - 1);
    int bs = i >> 7;
    int s  = bs & (S_ - 1);

    size_t base = (size_t)bs * D_ + h * HD_ + dv;
    const float* p = x + base;
    float4 a = *(const float4*)p;
    float4 b = *(const float4*)(p + 32);
    const float2* t = tab + s * 32 + dv;
    float2 t0 = t[0], t1 = t[1], t2 = t[2], t3 = t[3];

    float4 ra, rb;
    ra.x = fmaf(a.x, t0.x, -b.x * t0.y);  rb.x = fmaf(a.x, t0.y, b.x * t0.x);
    ra.y = fmaf(a.y, t1.x, -b.y * t1.y);  rb.y = fmaf(a.y, t1.y, b.y * t1.x);
    ra.z = fmaf(a.z, t2.x, -b.z * t2.y);  rb.z = fmaf(a.z, t2.y, b.z * t2.x);
    ra.w = fmaf(a.w, t3.x, -b.w * t3.y);  rb.w = fmaf(a.w, t3.y, b.w * t3.x);

    uint32_t h01, l01, h23, l23;
    split2(ra.x, ra.y, h01, l01); split2(ra.z, ra.w, h23, l23);
    *(uint32_t*)(oh + base)     = h01;  *(uint32_t*)(oh + base + 2) = h23;
    *(uint32_t*)(ol + base)     = l01;  *(uint32_t*)(ol + base + 2) = l23;
    split2(rb.x, rb.y, h01, l01); split2(rb.z, rb.w, h23, l23);
    *(uint32_t*)(oh + base + 32) = h01; *(uint32_t*)(oh + base + 34) = h23;
    *(uint32_t*)(ol + base + 32) = l01; *(uint32_t*)(ol + base + 34) = l23;
}

// ===========================================================================
// Tensor-core flash attention. BM=128, BN=64. Output: fused bf16 hi/lo split.
// ===========================================================================
#define FQH 0
#define FQL 16384
#define FST 32768
#define FKH 0
#define FKL 8192
#define FVH 16384
#define FVL 24576
#define FSTAGE 32768
#define FLASH_SMEM (32768 + 2 * FSTAGE)   // 98304

__device__ __forceinline__ void flash_load_kv(
    uint32_t sb, int stage, int kt, int tid,
    const __nv_bfloat16* Khb, const __nv_bfloat16* Klb,
    const __nv_bfloat16* Vhb, const __nv_bfloat16* Vlb)
{
    uint32_t base = sb + FST + stage * FSTAGE;
    size_t rbase = (size_t)(kt * 64) * D_;
#pragma unroll
    for (int rep = 0; rep < 2; rep++) {
        int id  = tid + rep * 256;
        int row = id >> 3;
        int seg = id & 7;
        uint32_t soff = SMEM_SWIZZLE_128B((uint32_t)(row * 128 + seg * 16));
        size_t goff = rbase + (size_t)row * D_ + seg * 8;
        cpa16(base + FKH + soff, Khb + goff);
        cpa16(base + FKL + soff, Klb + goff);
        cpa16(base + FVH + soff, Vhb + goff);
        cpa16(base + FVL + soff, Vlb + goff);
    }
    asm volatile("cp.async.commit_group;" ::: "memory");
}

__global__ __launch_bounds__(256)
void flash_mma(const __nv_bfloat16* __restrict__ Qh_g, const __nv_bfloat16* __restrict__ Ql_g,
               const __nv_bfloat16* __restrict__ Kh_g, const __nv_bfloat16* __restrict__ Kl_g,
               const __nv_bfloat16* __restrict__ Vh_g, const __nv_bfloat16* __restrict__ Vl_g,
               __nv_bfloat16* __restrict__ Oh_g, __nv_bfloat16* __restrict__ Ol_g)
{
    extern __shared__ char smem[];
    uint32_t sb = smem_to_u32(smem);
    const int tid  = threadIdx.x;
    const int wid  = tid >> 5;
    const int lane = tid & 31;
    const int qt = blockIdx.x, h = blockIdx.y, b = blockIdx.z;

    const int g = lane >> 2, c = lane & 3;
    const int mat = lane >> 3, mrr = lane & 7;
    const int a_row_off = (mat & 1) * 8 + mrr;
    const int a_ks_off  = (mat >> 1) * 16;
    const int b_row_off = (mat >> 1) * 8 + mrr;
    const int b_ks_off  = (mat & 1) * 16;
    const int v_l = lane & 7, v_half = (lane >> 3) & 1, v_quad = lane >> 4;

    const size_t hoff = (size_t)(b * S_) * D_ + h * HD_;
    const __nv_bfloat16* Qhb = Qh_g + hoff + (size_t)(qt * 128) * D_;
    const __nv_bfloat16* Qlb = Ql_g + hoff + (size_t)(qt * 128) * D_;
    const __nv_bfloat16* Khb = Kh_g + hoff;
    const __nv_bfloat16* Klb = Kl_g + hoff;
    const __nv_bfloat16* Vhb = Vh_g + hoff;
    const __nv_bfloat16* Vlb = Vl_g + hoff;

#pragma unroll
    for (int rep = 0; rep < 4; rep++) {
        int id  = tid + rep * 256;
        int row = id >> 3;
        int seg = id & 7;
        uint32_t soff = SMEM_SWIZZLE_128B((uint32_t)(row * 128 + seg * 16));
        size_t goff = (size_t)row * D_ + seg * 8;
        cpa16(sb + FQH + soff, Qhb + goff);
        cpa16(sb + FQL + soff, Qlb + goff);
    }
    asm volatile("cp.async.commit_group;" ::: "memory");

    flash_load_kv(sb, 0, 0, tid, Khb, Klb, Vhb, Vlb);
    asm volatile("cp.async.wait_group 0;" ::: "memory");
    __syncthreads();

    uint32_t qhf[4][4], qlf[4][4];
#pragma unroll
    for (int t = 0; t < 4; t++) {
        int rowA = wid * 16 + a_row_off;
        uint32_t off = SMEM_SWIZZLE_128B((uint32_t)(rowA * 128 + t * 32 + a_ks_off));
        ldsm4(qhf[t][0], qhf[t][1], qhf[t][2], qhf[t][3], sb + FQH + off);
        ldsm4(qlf[t][0], qlf[t][1], qlf[t][2], qlf[t][3], sb + FQL + off);
    }

    float mi0 = -INFINITY, mi1 = -INFINITY, li0 = 0.f, li1 = 0.f;
    float o[8][4];
#pragma unroll
    for (int j = 0; j < 8; j++)
#pragma unroll
        for (int r = 0; r < 4; r++) o[j][r] = 0.f;

    const int wrow = qt * 128 + wid * 16;
    const int ktmax = 2 * qt + 1;

    for (int kt = 0; kt <= ktmax; kt++) {
        int s = kt & 1;
        if (kt < ktmax) {
            flash_load_kv(sb, s ^ 1, kt + 1, tid, Khb, Klb, Vhb, Vlb);
            asm volatile("cp.async.wait_group 1;" ::: "memory");
        } else {
            asm volatile("cp.async.wait_group 0;" ::: "memory");
        }
        __syncthreads();

        if (kt * 64 <= wrow + 15) {
            uint32_t st = sb + FST + s * FSTAGE;
            float sc[8][4];
#pragma unroll
            for (int j = 0; j < 8; j++)
#pragma unroll
                for (int r = 0; r < 4; r++) sc[j][r] = 0.f;

#pragma unroll
            for (int t = 0; t < 4; t++) {
#pragma unroll
                for (int p = 0; p < 4; p++) {
                    uint32_t kh4[4], kl4[4];
                    int rowB = p * 16 + b_row_off;
                    uint32_t off = SMEM_SWIZZLE_128B((uint32_t)(rowB * 128 + t * 32 + b_ks_off));
                    ldsm4(kh4[0], kh4[1], kh4[2], kh4[3], st + FKH + off);
                    ldsm4(kl4[0], kl4[1], kl4[2], kl4[3], st + FKL + off);
#pragma unroll
                    for (int q = 0; q < 2; q++) {
                        float* d = sc[2 * p + q];
                        mma_bf16(d, qhf[t], kh4[q * 2], kh4[q * 2 + 1]);
                        mma_bf16(d, qhf[t], kl4[q * 2], kl4[q * 2 + 1]);
                        mma_bf16(d, qlf[t], kh4[q * 2], kh4[q * 2 + 1]);
                    }
                }
            }

            const float scale = 0.125f;
            const int row0 = wrow + g, row1 = row0 + 8;
            const bool diag = (kt * 64 + 63 > wrow);
#pragma unroll
            for (int j = 0; j < 8; j++) {
                int col0 = kt * 64 + j * 8 + 2 * c, col1 = col0 + 1;
                sc[j][0] *= scale; sc[j][1] *= scale;
                sc[j][2] *= scale; sc[j][3] *= scale;
                if (diag) {
                    if (col0 > row0) sc[j][0] = -INFINITY;
                    if (col1 > row0) sc[j][1] = -INFINITY;
                    if (col0 > row1) sc[j][2] = -INFINITY;
                    if (col1 > row1) sc[j][3] = -INFINITY;
                }
            }
            float rm0 = -INFINITY, rm1 = -INFINITY;
#pragma unroll
            for (int j = 0; j < 8; j++) {
                rm0 = fmaxf(rm0, fmaxf(sc[j][0], sc[j][1]));
                rm1 = fmaxf(rm1, fmaxf(sc[j][2], sc[j][3]));
            }
            rm0 = fmaxf(rm0, __shfl_xor_sync(0xffffffffu, rm0, 1));
            rm0 = fmaxf(rm0, __shfl_xor_sync(0xffffffffu, rm0, 2));
            rm1 = fmaxf(rm1, __shfl_xor_sync(0xffffffffu, rm1, 1));
            rm1 = fmaxf(rm1, __shfl_xor_sync(0xffffffffu, rm1, 2));

            float mn0 = fmaxf(mi0, rm0), mn1 = fmaxf(mi1, rm1);
            float al0 = __expf(mi0 - mn0), al1 = __expf(mi1 - mn1);
            float rs0 = 0.f, rs1 = 0.f;
#pragma unroll
            for (int j = 0; j < 8; j++) {
                sc[j][0] = __expf(sc[j][0] - mn0);
                sc[j][1] = __expf(sc[j][1] - mn0);
                sc[j][2] = __expf(sc[j][2] - mn1);
                sc[j][3] = __expf(sc[j][3] - mn1);
                rs0 += sc[j][0] + sc[j][1];
                rs1 += sc[j][2] + sc[j][3];
            }
            rs0 += __shfl_xor_sync(0xffffffffu, rs0, 1);
            rs0 += __shfl_xor_sync(0xffffffffu, rs0, 2);
            rs1 += __shfl_xor_sync(0xffffffffu, rs1, 1);
            rs1 += __shfl_xor_sync(0xffffffffu, rs1, 2);
            li0 = li0 * al0 + rs0; li1 = li1 * al1 + rs1;
            mi0 = mn0; mi1 = mn1;
#pragma unroll
            for (int j = 0; j < 8; j++) {
                o[j][0] *= al0; o[j][1] *= al0;
                o[j][2] *= al1; o[j][3] *= al1;
            }

            uint32_t ph[4][4], pl[4][4];
#pragma unroll
            for (int t = 0; t < 4; t++) {
                split2(sc[2 * t][0],     sc[2 * t][1],     ph[t][0], pl[t][0]);
                split2(sc[2 * t][2],     sc[2 * t][3],     ph[t][1], pl[t][1]);
                split2(sc[2 * t + 1][0], sc[2 * t + 1][1], ph[t][2], pl[t][2]);
                split2(sc[2 * t + 1][2], sc[2 * t + 1][3], ph[t][3], pl[t][3]);
            }

#pragma unroll
            for (int t = 0; t < 4; t++) {
#pragma unroll
                for (int jp = 0; jp < 4; jp++) {
                    uint32_t soff = SMEM_SWIZZLE_128B(
                        (uint32_t)((16 * t + v_half * 8 + v_l) * 128 + jp * 32 + v_quad * 16));
                    uint32_t vh4[4], vl4[4];
                    ldsm4t(vh4[0], vh4[1], vh4[2], vh4[3], st + FVH + soff);
                    ldsm4t(vl4[0], vl4[1], vl4[2], vl4[3], st + FVL + soff);
                    float* d0 = o[2 * jp];
                    float* d1 = o[2 * jp + 1];
                    mma_bf16(d0, ph[t], vh4[0], vh4[1]);
                    mma_bf16(d0, ph[t], vl4[0], vl4[1]);
                    mma_bf16(d0, pl[t], vh4[0], vh4[1]);
                    mma_bf16(d1, ph[t], vh4[2], vh4[3]);
                    mma_bf16(d1, ph[t], vl4[2], vl4[3]);
                    mma_bf16(d1, pl[t], vh4[2], vh4[3]);
                }
            }
        }
        __syncthreads();
    }

    // epilogue: normalize + bf16 hi/lo split, write directly as next GEMM's input
    float iv0 = 1.f / li0, iv1 = 1.f / li1;
    size_t r0off = ((size_t)(b * S_ + wrow + g)) * D_ + h * HD_;
    size_t r1off = r0off + 8 * D_;
#pragma unroll
    for (int j = 0; j < 8; j++) {
        int col = j * 8 + 2 * c;
        uint32_t hi, lo;
        split2(o[j][0] * iv0, o[j][1] * iv0, hi, lo);
        *(uint32_t*)(Oh_g + r0off + col) = hi;
        *(uint32_t*)(Ol_g + r0off + col) = lo;
        split2(o[j][2] * iv1, o[j][3] * iv1, hi, lo);
        *(uint32_t*)(Oh_g + r1off + col) = hi;
        *(uint32_t*)(Ol_g + r1off + col) = lo;
    }
}

// ---------------------------------------------------------------------------
extern "C" void kernel_launch(void* const* d_in, const int* in_sizes, int n_in,
                              void* d_out, int out_size)
{
    const float* Q  = (const float*)d_in[0];
    const float* K  = (const float*)d_in[1];
    const float* V  = (const float*)d_in[2];
    const float* Wq = (const float*)d_in[3];
    const float* bq = (const float*)d_in[4];
    const float* Wk = (const float*)d_in[5];
    const float* bk = (const float*)d_in[6];
    const float* Wv = (const float*)d_in[7];
    const float* bv = (const float*)d_in[8];
    const float* Wo = (const float*)d_in[9];
    const float* bo = (const float*)d_in[10];
    float* out = (float*)d_out;

    float *gq, *gk;
    float2* grope;
    __nv_bfloat16 *gxh, *gxl, *gwh, *gwl;
    __nv_bfloat16 *gqh, *gql, *gkh, *gkl, *gvh, *gvl;
    cudaGetSymbolAddress((void**)&gq, g_q);
    cudaGetSymbolAddress((void**)&gk, g_k);
    cudaGetSymbolAddress((void**)&grope, g_rope);
    cudaGetSymbolAddress((void**)&gxh, g_xh);
    cudaGetSymbolAddress((void**)&gxl, g_xl);
    cudaGetSymbolAddress((void**)&gwh, g_wh);
    cudaGetSymbolAddress((void**)&gwl, g_wl);
    cudaGetSymbolAddress((void**)&gqh, g_qh);
    cudaGetSymbolAddress((void**)&gql, g_ql);
    cudaGetSymbolAddress((void**)&gkh, g_kh);
    cudaGetSymbolAddress((void**)&gkl, g_kl);
    cudaGetSymbolAddress((void**)&gvh, g_vh);
    cudaGetSymbolAddress((void**)&gvl, g_vl);

    cudaFuncSetAttribute(gemm_mma<false>, cudaFuncAttributeMaxDynamicSharedMemorySize, GEMM_SMEM);
    cudaFuncSetAttribute(gemm_mma<true>,  cudaFuncAttributeMaxDynamicSharedMemorySize, GEMM_SMEM);
    cudaFuncSetAttribute(flash_mma, cudaFuncAttributeMaxDynamicSharedMemorySize, FLASH_SMEM);

    const int n4x = NTOT / 4;
    const int n4w = (D_ * D_) / 4;
    dim3 ggrid(D_ / 128, M_ / 128);

    rope_table_kernel<<<(S_ * 32 + 255) / 256, 256>>>(grope);

    // Q projection -> fp32 (rope needs fp32 rows)
    split_kernel<<<(n4x + 255) / 256, 256>>>(Q, gxh, gxl, n4x);
    split_kernel<<<(n4w + 255) / 256, 256>>>(Wq, gwh, gwl, n4w);
    gemm_mma<false><<<ggrid, 256, GEMM_SMEM>>>(gxh, gxl, gwh, gwl, bq, gq, nullptr, nullptr);

    // K projection -> fp32
    split_kernel<<<(n4x + 255) / 256, 256>>>(K, gxh, gxl, n4x);
    split_kernel<<<(n4w + 255) / 256, 256>>>(Wk, gwh, gwl, n4w);
    gemm_mma<false><<<ggrid, 256, GEMM_SMEM>>>(gxh, gxl, gwh, gwl, bk, gk, nullptr, nullptr);

    // V projection -> fused bf16 hi/lo
    split_kernel<<<(n4x + 255) / 256, 256>>>(V, gxh, gxl, n4x);
    split_kernel<<<(n4w + 255) / 256, 256>>>(Wv, gwh, gwl, n4w);
    gemm_mma<true><<<ggrid, 256, GEMM_SMEM>>>(gxh, gxl, gwh, gwl, bv, nullptr, gvh, gvl);

    // RoPE + split Q,K
    int items = 2 * B_ * S_ * H_ * 8;
    rope_split_kernel<<<(items + 255) / 256, 256>>>(gq, gk, grope, gqh, gql, gkh, gkl);

    // Flash -> fused bf16 hi/lo output (feeds output projection directly)
    dim3 fgrid(S_ / 128, H_, B_);
    flash_mma<<<fgrid, 256, FLASH_SMEM>>>(gqh, gql, gkh, gkl, gvh, gvl, gxh, gxl);

    // Output projection
    split_kernel<<<(n4w + 255) / 256, 256>>>(Wo, gwh, gwl, n4w);
    gemm_mma<false><<<ggrid, 256, GEMM_SMEM>>>(gxh, gxl, gwh, gwl, bo, out, nullptr, nullptr);
}

// round 7
// speedup vs baseline: 1.0979x; 1.0979x over previous
#include <cuda_runtime.h>
#include <cuda_bf16.h>
#include <math.h>
#include <stdint.h>

#define B_  4
#define S_  2048
#define D_  1024
#define H_  16
#define HD_ 64
#define M_  (B_ * S_)
#define NTOT (B_ * S_ * D_)

// Scratch (allocation-free rule: __device__ globals)
__device__ float g_q[NTOT];
__device__ float g_k[NTOT];
__device__ __nv_bfloat16 g_xh[NTOT];
__device__ __nv_bfloat16 g_xl[NTOT];
__device__ __nv_bfloat16 g_wh[D_ * D_];
__device__ __nv_bfloat16 g_wl[D_ * D_];
__device__ __nv_bfloat16 g_qh[NTOT];
__device__ __nv_bfloat16 g_ql[NTOT];
__device__ __nv_bfloat16 g_kh[NTOT];
__device__ __nv_bfloat16 g_kl[NTOT];
__device__ __nv_bfloat16 g_vh[NTOT];
__device__ __nv_bfloat16 g_vl[NTOT];
__device__ float2 g_rope[S_ * 32];

// ===========================================================================
// Helpers (baseline PTX only — compute_103-safe)
// ===========================================================================
__device__ __forceinline__ uint32_t smem_to_u32(const void* p) {
    uint32_t a;
    asm("{ .reg .u64 t; cvta.to.shared.u64 t, %1; cvt.u32.u64 %0, t; }" : "=r"(a) : "l"(p));
    return a;
}
#define SMEM_SWIZZLE_128B(off) ((off) ^ (((off) >> 3) & 0x70))

__device__ __forceinline__ void cpa16(uint32_t dst, const void* src) {
    asm volatile("cp.async.cg.shared.global [%0], [%1], 16;" :: "r"(dst), "l"(src));
}
__device__ __forceinline__ void ldsm4(uint32_t& r0, uint32_t& r1, uint32_t& r2, uint32_t& r3,
                                      uint32_t addr) {
    asm volatile("ldmatrix.sync.aligned.m8n8.x4.shared.b16 {%0,%1,%2,%3}, [%4];"
        : "=r"(r0), "=r"(r1), "=r"(r2), "=r"(r3) : "r"(addr));
}
__device__ __forceinline__ void ldsm4t(uint32_t& r0, uint32_t& r1, uint32_t& r2, uint32_t& r3,
                                       uint32_t addr) {
    asm volatile("ldmatrix.sync.aligned.m8n8.x4.trans.shared.b16 {%0,%1,%2,%3}, [%4];"
        : "=r"(r0), "=r"(r1), "=r"(r2), "=r"(r3) : "r"(addr));
}
__device__ __forceinline__ void mma_bf16(float* d, const uint32_t* a,
                                         uint32_t b0, uint32_t b1) {
    asm volatile(
        "mma.sync.aligned.m16n8k16.row.col.f32.bf16.bf16.f32 "
        "{%0,%1,%2,%3}, {%4,%5,%6,%7}, {%8,%9}, {%0,%1,%2,%3};"
        : "+f"(d[0]), "+f"(d[1]), "+f"(d[2]), "+f"(d[3])
        : "r"(a[0]), "r"(a[1]), "r"(a[2]), "r"(a[3]), "r"(b0), "r"(b1));
}
__device__ __forceinline__ void split2(float f0, float f1, uint32_t& hi, uint32_t& lo) {
    __nv_bfloat16 h0 = __float2bfloat16(f0), h1 = __float2bfloat16(f1);
    __nv_bfloat16 l0 = __float2bfloat16(f0 - __bfloat162float(h0));
    __nv_bfloat16 l1 = __float2bfloat16(f1 - __bfloat162float(h1));
    __nv_bfloat162 Hh(h0, h1), Ll(l0, l1);
    hi = *(uint32_t*)&Hh; lo = *(uint32_t*)&Ll;
}

// ===========================================================================
// fp32 -> bf16 (hi, lo) split
// ===========================================================================
__global__ __launch_bounds__(256)
void split_kernel(const float* __restrict__ x,
                  __nv_bfloat16* __restrict__ h,
                  __nv_bfloat16* __restrict__ l, int n4)
{
    int i = blockIdx.x * blockDim.x + threadIdx.x;
    if (i >= n4) return;
    float4 v = ((const float4*)x)[i];
    uint32_t h01, l01, h23, l23;
    split2(v.x, v.y, h01, l01);
    split2(v.z, v.w, h23, l23);
    ((uint32_t*)h)[2 * i + 0] = h01;
    ((uint32_t*)h)[2 * i + 1] = h23;
    ((uint32_t*)l)[2 * i + 0] = l01;
    ((uint32_t*)l)[2 * i + 1] = l23;
}

// ===========================================================================
// mma.sync bf16-split GEMM. BK=64 (proven), 3-stage cp.async pipeline.
// Templated epilogue: fp32 out, or fused bf16 hi/lo split out.
// ===========================================================================
#define TILE_BYTES 16384
#define STAGE_BYTES (4 * TILE_BYTES)       // 64 KB
#define GEMM_SMEM (3 * STAGE_BYTES)        // 192 KB (3 stages, 1 CTA/SM)
#define NCHUNK (D_ / 64)                   // 16

__device__ __forceinline__ void gemm_load_chunk(
    uint32_t sb, int stage, int k0, int tid,
    const __nv_bfloat16* Ahb, const __nv_bfloat16* Alb,
    const __nv_bfloat16* Bhb, const __nv_bfloat16* Blb)
{
    uint32_t base = sb + stage * STAGE_BYTES;
#pragma unroll
    for (int rep = 0; rep < 4; rep++) {
        int id  = tid + rep * 256;
        int row = id >> 3;
        int seg = id & 7;
        uint32_t soff = SMEM_SWIZZLE_128B((uint32_t)(row * 128 + seg * 16));
        size_t goff = (size_t)row * D_ + k0 + seg * 8;
        cpa16(base + 0 * TILE_BYTES + soff, Ahb + goff);
        cpa16(base + 1 * TILE_BYTES + soff, Alb + goff);
        cpa16(base + 2 * TILE_BYTES + soff, Bhb + goff);
        cpa16(base + 3 * TILE_BYTES + soff, Blb + goff);
    }
    asm volatile("cp.async.commit_group;" ::: "memory");
}

template <bool SPLIT_OUT>
__global__ __launch_bounds__(256, 1)
void gemm_mma(const __nv_bfloat16* __restrict__ Ah, const __nv_bfloat16* __restrict__ Al,
              const __nv_bfloat16* __restrict__ Bh, const __nv_bfloat16* __restrict__ Bl,
              const float* __restrict__ bias, float* __restrict__ C,
              __nv_bfloat16* __restrict__ Ch, __nv_bfloat16* __restrict__ Cl)
{
    extern __shared__ char smem[];
    uint32_t sb = smem_to_u32(smem);
    const int tid  = threadIdx.x;
    const int wid  = tid >> 5;
    const int lane = tid & 31;
    const int warp_m = wid >> 2;
    const int warp_n = wid & 3;
    const int bn = blockIdx.x, bm = blockIdx.y;

    const __nv_bfloat16* Ahb = Ah + (size_t)(bm * 128) * D_;
    const __nv_bfloat16* Alb = Al + (size_t)(bm * 128) * D_;
    const __nv_bfloat16* Bhb = Bh + (size_t)(bn * 128) * D_;
    const __nv_bfloat16* Blb = Bl + (size_t)(bn * 128) * D_;

    float acc[4][4][4];
#pragma unroll
    for (int i = 0; i < 4; i++)
#pragma unroll
        for (int j = 0; j < 4; j++)
#pragma unroll
            for (int r = 0; r < 4; r++) acc[i][j][r] = 0.f;

    const int mat = lane >> 3;
    const int mrr = lane & 7;
    const int a_row_off = (mat & 1) * 8 + mrr;
    const int a_ks_off  = (mat >> 1) * 16;
    const int b_row_off = (mat >> 1) * 8 + mrr;
    const int b_ks_off  = (mat & 1) * 16;

    // 3-stage pipeline: prefetch chunks 0 and 1
    gemm_load_chunk(sb, 0, 0, tid, Ahb, Alb, Bhb, Blb);
    gemm_load_chunk(sb, 1, 64, tid, Ahb, Alb, Bhb, Blb);

    int stage = 0;
    for (int c = 0; c < NCHUNK; c++) {
        if (c + 2 < NCHUNK) {
            int ls = stage + 2; if (ls >= 3) ls -= 3;
            gemm_load_chunk(sb, ls, (c + 2) * 64, tid, Ahb, Alb, Bhb, Blb);
            asm volatile("cp.async.wait_group 2;" ::: "memory");
        } else if (c + 1 < NCHUNK) {
            asm volatile("cp.async.wait_group 1;" ::: "memory");
        } else {
            asm volatile("cp.async.wait_group 0;" ::: "memory");
        }
        __syncthreads();

        uint32_t stA = sb + stage * STAGE_BYTES;
#pragma unroll
        for (int ks = 0; ks < 4; ks++) {
            const int kb = ks * 32;
            uint32_t ah[4][4], al[4][4];
#pragma unroll
            for (int mt = 0; mt < 4; mt++) {
                int row = warp_m * 64 + mt * 16 + a_row_off;
                uint32_t off = SMEM_SWIZZLE_128B((uint32_t)(row * 128 + kb + a_ks_off));
                ldsm4(ah[mt][0], ah[mt][1], ah[mt][2], ah[mt][3], stA + 0 * TILE_BYTES + off);
                ldsm4(al[mt][0], al[mt][1], al[mt][2], al[mt][3], stA + 1 * TILE_BYTES + off);
            }
            uint32_t bh[2][4], bl[2][4];
#pragma unroll
            for (int p = 0; p < 2; p++) {
                int row = warp_n * 32 + p * 16 + b_row_off;
                uint32_t off = SMEM_SWIZZLE_128B((uint32_t)(row * 128 + kb + b_ks_off));
                ldsm4(bh[p][0], bh[p][1], bh[p][2], bh[p][3], stA + 2 * TILE_BYTES + off);
                ldsm4(bl[p][0], bl[p][1], bl[p][2], bl[p][3], stA + 3 * TILE_BYTES + off);
            }
#pragma unroll
            for (int mt = 0; mt < 4; mt++) {
#pragma unroll
                for (int p = 0; p < 2; p++) {
#pragma unroll
                    for (int q = 0; q < 2; q++) {
                        float* d = acc[mt][p * 2 + q];
                        mma_bf16(d, ah[mt], bh[p][q * 2], bh[p][q * 2 + 1]);
                        mma_bf16(d, ah[mt], bl[p][q * 2], bl[p][q * 2 + 1]);
                        mma_bf16(d, al[mt], bh[p][q * 2], bh[p][q * 2 + 1]);
                    }
                }
            }
        }
        __syncthreads();
        stage++; if (stage >= 3) stage = 0;
    }

    const int rbase = bm * 128 + warp_m * 64 + (lane >> 2);
    const int cbase = bn * 128 + warp_n * 32 + (lane & 3) * 2;
#pragma unroll
    for (int mt = 0; mt < 4; mt++) {
#pragma unroll
        for (int nt = 0; nt < 4; nt++) {
            int col = cbase + nt * 8;
            float b0 = bias[col], b1 = bias[col + 1];
            float* d = acc[mt][nt];
            int r0 = rbase + mt * 16;
            float v00 = d[0] + b0, v01 = d[1] + b1;
            float v10 = d[2] + b0, v11 = d[3] + b1;
            if (SPLIT_OUT) {
                uint32_t hi, lo;
                split2(v00, v01, hi, lo);
                *(uint32_t*)(Ch + (size_t)r0 * D_ + col) = hi;
                *(uint32_t*)(Cl + (size_t)r0 * D_ + col) = lo;
                split2(v10, v11, hi, lo);
                *(uint32_t*)(Ch + (size_t)(r0 + 8) * D_ + col) = hi;
                *(uint32_t*)(Cl + (size_t)(r0 + 8) * D_ + col) = lo;
            } else {
                *(float2*)(C + (size_t)r0 * D_ + col)       = make_float2(v00, v01);
                *(float2*)(C + (size_t)(r0 + 8) * D_ + col) = make_float2(v10, v11);
            }
        }
    }
}

// ---------------------------------------------------------------------------
// RoPE table (fp64 for exactness)
// ---------------------------------------------------------------------------
__global__ void rope_table_kernel(float2* __restrict__ tab)
{
    int idx = blockIdx.x * blockDim.x + threadIdx.x;
    if (idx >= S_ * 32) return;
    int s = idx >> 5;
    int d = idx & 31;
    double inv = exp(-log(10000.0) * (double)d / 32.0);
    double ang = (double)s * inv;
    double sd, cd;
    sincos(ang, &sd, &cd);
    tab[idx] = make_float2((float)cd, (float)sd);
}

// ---------------------------------------------------------------------------
// Fused RoPE + bf16 hi/lo split for Q and K
// ---------------------------------------------------------------------------
__global__ __launch_bounds__(256)
void rope_split_kernel(const float* __restrict__ q, const float* __restrict__ k,
                       const float2* __restrict__ tab,
                       __nv_bfloat16* __restrict__ qh, __nv_bfloat16* __restrict__ ql,
                       __nv_bfloat16* __restrict__ kh, __nv_bfloat16* __restrict__ kl)
{
    const int half = B_ * S_ * H_ * 8;
    int idx = blockIdx.x * blockDim.x + threadIdx.x;
    if (idx >= 2 * half) return;
    const float* x = (idx < half) ? q : k;
    __nv_bfloat16* oh = (idx < half) ? qh : kh;
    __nv_bfloat16* ol = (idx < half) ? ql : kl;
    int i = (idx < half) ? idx : idx - half;

    int dv = (i & 7) << 2;
    int h  = (i >> 3) & (H_ - 1);
    int bs = i >> 7;
    int s  = bs & (S_ - 1);

    size_t base = (size_t)bs * D_ + h * HD_ + dv;
    const float* p = x + base;
    float4 a = *(const float4*)p;
    float4 b = *(const float4*)(p + 32);
    const float2* t = tab + s * 32 + dv;
    float2 t0 = t[0], t1 = t[1], t2 = t[2], t3 = t[3];

    float4 ra, rb;
    ra.x = fmaf(a.x, t0.x, -b.x * t0.y);  rb.x = fmaf(a.x, t0.y, b.x * t0.x);
    ra.y = fmaf(a.y, t1.x, -b.y * t1.y);  rb.y = fmaf(a.y, t1.y, b.y * t1.x);
    ra.z = fmaf(a.z, t2.x, -b.z * t2.y);  rb.z = fmaf(a.z, t2.y, b.z * t2.x);
    ra.w = fmaf(a.w, t3.x, -b.w * t3.y);  rb.w = fmaf(a.w, t3.y, b.w * t3.x);

    uint32_t h01, l01, h23, l23;
    split2(ra.x, ra.y, h01, l01); split2(ra.z, ra.w, h23, l23);
    *(uint32_t*)(oh + base)     = h01;  *(uint32_t*)(oh + base + 2) = h23;
    *(uint32_t*)(ol + base)     = l01;  *(uint32_t*)(ol + base + 2) = l23;
    split2(rb.x, rb.y, h01, l01); split2(rb.z, rb.w, h23, l23);
    *(uint32_t*)(oh + base + 32) = h01; *(uint32_t*)(oh + base + 34) = h23;
    *(uint32_t*)(ol + base + 32) = l01; *(uint32_t*)(ol + base + 34) = l23;
}

// ===========================================================================
// Tensor-core flash attention. BM=128, BN=64. Output: fused bf16 hi/lo split.
// ===========================================================================
#define FQH 0
#define FQL 16384
#define FST 32768
#define FKH 0
#define FKL 8192
#define FVH 16384
#define FVL 24576
#define FSTAGE 32768
#define FLASH_SMEM (32768 + 2 * FSTAGE)   // 98304

__device__ __forceinline__ void flash_load_kv(
    uint32_t sb, int stage, int kt, int tid,
    const __nv_bfloat16* Khb, const __nv_bfloat16* Klb,
    const __nv_bfloat16* Vhb, const __nv_bfloat16* Vlb)
{
    uint32_t base = sb + FST + stage * FSTAGE;
    size_t rbase = (size_t)(kt * 64) * D_;
#pragma unroll
    for (int rep = 0; rep < 2; rep++) {
        int id  = tid + rep * 256;
        int row = id >> 3;
        int seg = id & 7;
        uint32_t soff = SMEM_SWIZZLE_128B((uint32_t)(row * 128 + seg * 16));
        size_t goff = rbase + (size_t)row * D_ + seg * 8;
        cpa16(base + FKH + soff, Khb + goff);
        cpa16(base + FKL + soff, Klb + goff);
        cpa16(base + FVH + soff, Vhb + goff);
        cpa16(base + FVL + soff, Vlb + goff);
    }
    asm volatile("cp.async.commit_group;" ::: "memory");
}

__global__ __launch_bounds__(256)
void flash_mma(const __nv_bfloat16* __restrict__ Qh_g, const __nv_bfloat16* __restrict__ Ql_g,
               const __nv_bfloat16* __restrict__ Kh_g, const __nv_bfloat16* __restrict__ Kl_g,
               const __nv_bfloat16* __restrict__ Vh_g, const __nv_bfloat16* __restrict__ Vl_g,
               __nv_bfloat16* __restrict__ Oh_g, __nv_bfloat16* __restrict__ Ol_g)
{
    extern __shared__ char smem[];
    uint32_t sb = smem_to_u32(smem);
    const int tid  = threadIdx.x;
    const int wid  = tid >> 5;
    const int lane = tid & 31;
    const int qt = blockIdx.x, h = blockIdx.y, b = blockIdx.z;

    const int g = lane >> 2, c = lane & 3;
    const int mat = lane >> 3, mrr = lane & 7;
    const int a_row_off = (mat & 1) * 8 + mrr;
    const int a_ks_off  = (mat >> 1) * 16;
    const int b_row_off = (mat >> 1) * 8 + mrr;
    const int b_ks_off  = (mat & 1) * 16;
    const int v_l = lane & 7, v_half = (lane >> 3) & 1, v_quad = lane >> 4;

    const size_t hoff = (size_t)(b * S_) * D_ + h * HD_;
    const __nv_bfloat16* Qhb = Qh_g + hoff + (size_t)(qt * 128) * D_;
    const __nv_bfloat16* Qlb = Ql_g + hoff + (size_t)(qt * 128) * D_;
    const __nv_bfloat16* Khb = Kh_g + hoff;
    const __nv_bfloat16* Klb = Kl_g + hoff;
    const __nv_bfloat16* Vhb = Vh_g + hoff;
    const __nv_bfloat16* Vlb = Vl_g + hoff;

#pragma unroll
    for (int rep = 0; rep < 4; rep++) {
        int id  = tid + rep * 256;
        int row = id >> 3;
        int seg = id & 7;
        uint32_t soff = SMEM_SWIZZLE_128B((uint32_t)(row * 128 + seg * 16));
        size_t goff = (size_t)row * D_ + seg * 8;
        cpa16(sb + FQH + soff, Qhb + goff);
        cpa16(sb + FQL + soff, Qlb + goff);
    }
    asm volatile("cp.async.commit_group;" ::: "memory");

    flash_load_kv(sb, 0, 0, tid, Khb, Klb, Vhb, Vlb);
    asm volatile("cp.async.wait_group 0;" ::: "memory");
    __syncthreads();

    uint32_t qhf[4][4], qlf[4][4];
#pragma unroll
    for (int t = 0; t < 4; t++) {
        int rowA = wid * 16 + a_row_off;
        uint32_t off = SMEM_SWIZZLE_128B((uint32_t)(rowA * 128 + t * 32 + a_ks_off));
        ldsm4(qhf[t][0], qhf[t][1], qhf[t][2], qhf[t][3], sb + FQH + off);
        ldsm4(qlf[t][0], qlf[t][1], qlf[t][2], qlf[t][3], sb + FQL + off);
    }

    float mi0 = -INFINITY, mi1 = -INFINITY, li0 = 0.f, li1 = 0.f;
    float o[8][4];
#pragma unroll
    for (int j = 0; j < 8; j++)
#pragma unroll
        for (int r = 0; r < 4; r++) o[j][r] = 0.f;

    const int wrow = qt * 128 + wid * 16;
    const int ktmax = 2 * qt + 1;

    for (int kt = 0; kt <= ktmax; kt++) {
        int s = kt & 1;
        if (kt < ktmax) {
            flash_load_kv(sb, s ^ 1, kt + 1, tid, Khb, Klb, Vhb, Vlb);
            asm volatile("cp.async.wait_group 1;" ::: "memory");
        } else {
            asm volatile("cp.async.wait_group 0;" ::: "memory");
        }
        __syncthreads();

        if (kt * 64 <= wrow + 15) {
            uint32_t st = sb + FST + s * FSTAGE;
            float sc[8][4];
#pragma unroll
            for (int j = 0; j < 8; j++)
#pragma unroll
                for (int r = 0; r < 4; r++) sc[j][r] = 0.f;

#pragma unroll
            for (int t = 0; t < 4; t++) {
#pragma unroll
                for (int p = 0; p < 4; p++) {
                    uint32_t kh4[4], kl4[4];
                    int rowB = p * 16 + b_row_off;
                    uint32_t off = SMEM_SWIZZLE_128B((uint32_t)(rowB * 128 + t * 32 + b_ks_off));
                    ldsm4(kh4[0], kh4[1], kh4[2], kh4[3], st + FKH + off);
                    ldsm4(kl4[0], kl4[1], kl4[2], kl4[3], st + FKL + off);
#pragma unroll
                    for (int q = 0; q < 2; q++) {
                        float* d = sc[2 * p + q];
                        mma_bf16(d, qhf[t], kh4[q * 2], kh4[q * 2 + 1]);
                        mma_bf16(d, qhf[t], kl4[q * 2], kl4[q * 2 + 1]);
                        mma_bf16(d, qlf[t], kh4[q * 2], kh4[q * 2 + 1]);
                    }
                }
            }

            const float scale = 0.125f;
            const int row0 = wrow + g, row1 = row0 + 8;
            const bool diag = (kt * 64 + 63 > wrow);
#pragma unroll
            for (int j = 0; j < 8; j++) {
                int col0 = kt * 64 + j * 8 + 2 * c, col1 = col0 + 1;
                sc[j][0] *= scale; sc[j][1] *= scale;
                sc[j][2] *= scale; sc[j][3] *= scale;
                if (diag) {
                    if (col0 > row0) sc[j][0] = -INFINITY;
                    if (col1 > row0) sc[j][1] = -INFINITY;
                    if (col0 > row1) sc[j][2] = -INFINITY;
                    if (col1 > row1) sc[j][3] = -INFINITY;
                }
            }
            float rm0 = -INFINITY, rm1 = -INFINITY;
#pragma unroll
            for (int j = 0; j < 8; j++) {
                rm0 = fmaxf(rm0, fmaxf(sc[j][0], sc[j][1]));
                rm1 = fmaxf(rm1, fmaxf(sc[j][2], sc[j][3]));
            }
            rm0 = fmaxf(rm0, __shfl_xor_sync(0xffffffffu, rm0, 1));
            rm0 = fmaxf(rm0, __shfl_xor_sync(0xffffffffu, rm0, 2));
            rm1 = fmaxf(rm1, __shfl_xor_sync(0xffffffffu, rm1, 1));
            rm1 = fmaxf(rm1, __shfl_xor_sync(0xffffffffu, rm1, 2));

            float mn0 = fmaxf(mi0, rm0), mn1 = fmaxf(mi1, rm1);
            float al0 = __expf(mi0 - mn0), al1 = __expf(mi1 - mn1);
            float rs0 = 0.f, rs1 = 0.f;
#pragma unroll
            for (int j = 0; j < 8; j++) {
                sc[j][0] = __expf(sc[j][0] - mn0);
                sc[j][1] = __expf(sc[j][1] - mn0);
                sc[j][2] = __expf(sc[j][2] - mn1);
                sc[j][3] = __expf(sc[j][3] - mn1);
                rs0 += sc[j][0] + sc[j][1];
                rs1 += sc[j][2] + sc[j][3];
            }
            rs0 += __shfl_xor_sync(0xffffffffu, rs0, 1);
            rs0 += __shfl_xor_sync(0xffffffffu, rs0, 2);
            rs1 += __shfl_xor_sync(0xffffffffu, rs1, 1);
            rs1 += __shfl_xor_sync(0xffffffffu, rs1, 2);
            li0 = li0 * al0 + rs0; li1 = li1 * al1 + rs1;
            mi0 = mn0; mi1 = mn1;
#pragma unroll
            for (int j = 0; j < 8; j++) {
                o[j][0] *= al0; o[j][1] *= al0;
                o[j][2] *= al1; o[j][3] *= al1;
            }

            uint32_t ph[4][4], pl[4][4];
#pragma unroll
            for (int t = 0; t < 4; t++) {
                split2(sc[2 * t][0],     sc[2 * t][1],     ph[t][0], pl[t][0]);
                split2(sc[2 * t][2],     sc[2 * t][3],     ph[t][1], pl[t][1]);
                split2(sc[2 * t + 1][0], sc[2 * t + 1][1], ph[t][2], pl[t][2]);
                split2(sc[2 * t + 1][2], sc[2 * t + 1][3], ph[t][3], pl[t][3]);
            }

#pragma unroll
            for (int t = 0; t < 4; t++) {
#pragma unroll
                for (int jp = 0; jp < 4; jp++) {
                    uint32_t soff = SMEM_SWIZZLE_128B(
                        (uint32_t)((16 * t + v_half * 8 + v_l) * 128 + jp * 32 + v_quad * 16));
                    uint32_t vh4[4], vl4[4];
                    ldsm4t(vh4[0], vh4[1], vh4[2], vh4[3], st + FVH + soff);
                    ldsm4t(vl4[0], vl4[1], vl4[2], vl4[3], st + FVL + soff);
                    float* d0 = o[2 * jp];
                    float* d1 = o[2 * jp + 1];
                    mma_bf16(d0, ph[t], vh4[0], vh4[1]);
                    mma_bf16(d0, ph[t], vl4[0], vl4[1]);
                    mma_bf16(d0, pl[t], vh4[0], vh4[1]);
                    mma_bf16(d1, ph[t], vh4[2], vh4[3]);
                    mma_bf16(d1, ph[t], vl4[2], vl4[3]);
                    mma_bf16(d1, pl[t], vh4[2], vh4[3]);
                }
            }
        }
        __syncthreads();
    }

    float iv0 = 1.f / li0, iv1 = 1.f / li1;
    size_t r0off = ((size_t)(b * S_ + wrow + g)) * D_ + h * HD_;
    size_t r1off = r0off + 8 * D_;
#pragma unroll
    for (int j = 0; j < 8; j++) {
        int col = j * 8 + 2 * c;
        uint32_t hi, lo;
        split2(o[j][0] * iv0, o[j][1] * iv0, hi, lo);
        *(uint32_t*)(Oh_g + r0off + col) = hi;
        *(uint32_t*)(Ol_g + r0off + col) = lo;
        split2(o[j][2] * iv1, o[j][3] * iv1, hi, lo);
        *(uint32_t*)(Oh_g + r1off + col) = hi;
        *(uint32_t*)(Ol_g + r1off + col) = lo;
    }
}

// ---------------------------------------------------------------------------
extern "C" void kernel_launch(void* const* d_in, const int* in_sizes, int n_in,
                              void* d_out, int out_size)
{
    const float* Q  = (const float*)d_in[0];
    const float* K  = (const float*)d_in[1];
    const float* V  = (const float*)d_in[2];
    const float* Wq = (const float*)d_in[3];
    const float* bq = (const float*)d_in[4];
    const float* Wk = (const float*)d_in[5];
    const float* bk = (const float*)d_in[6];
    const float* Wv = (const float*)d_in[7];
    const float* bv = (const float*)d_in[8];
    const float* Wo = (const float*)d_in[9];
    const float* bo = (const float*)d_in[10];
    float* out = (float*)d_out;

    float *gq, *gk;
    float2* grope;
    __nv_bfloat16 *gxh, *gxl, *gwh, *gwl;
    __nv_bfloat16 *gqh, *gql, *gkh, *gkl, *gvh, *gvl;
    cudaGetSymbolAddress((void**)&gq, g_q);
    cudaGetSymbolAddress((void**)&gk, g_k);
    cudaGetSymbolAddress((void**)&grope, g_rope);
    cudaGetSymbolAddress((void**)&gxh, g_xh);
    cudaGetSymbolAddress((void**)&gxl, g_xl);
    cudaGetSymbolAddress((void**)&gwh, g_wh);
    cudaGetSymbolAddress((void**)&gwl, g_wl);
    cudaGetSymbolAddress((void**)&gqh, g_qh);
    cudaGetSymbolAddress((void**)&gql, g_ql);
    cudaGetSymbolAddress((void**)&gkh, g_kh);
    cudaGetSymbolAddress((void**)&gkl, g_kl);
    cudaGetSymbolAddress((void**)&gvh, g_vh);
    cudaGetSymbolAddress((void**)&gvl, g_vl);

    cudaFuncSetAttribute(gemm_mma<false>, cudaFuncAttributeMaxDynamicSharedMemorySize, GEMM_SMEM);
    cudaFuncSetAttribute(gemm_mma<true>,  cudaFuncAttributeMaxDynamicSharedMemorySize, GEMM_SMEM);
    cudaFuncSetAttribute(flash_mma, cudaFuncAttributeMaxDynamicSharedMemorySize, FLASH_SMEM);

    const int n4x = NTOT / 4;
    const int n4w = (D_ * D_) / 4;
    dim3 ggrid(D_ / 128, M_ / 128);

    rope_table_kernel<<<(S_ * 32 + 255) / 256, 256>>>(grope);

    // Q projection -> fp32 (rope needs fp32 rows)
    split_kernel<<<(n4x + 255) / 256, 256>>>(Q, gxh, gxl, n4x);
    split_kernel<<<(n4w + 255) / 256, 256>>>(Wq, gwh, gwl, n4w);
    gemm_mma<false><<<ggrid, 256, GEMM_SMEM>>>(gxh, gxl, gwh, gwl, bq, gq, nullptr, nullptr);

    // K projection -> fp32
    split_kernel<<<(n4x + 255) / 256, 256>>>(K, gxh, gxl, n4x);
    split_kernel<<<(n4w + 255) / 256, 256>>>(Wk, gwh, gwl, n4w);
    gemm_mma<false><<<ggrid, 256, GEMM_SMEM>>>(gxh, gxl, gwh, gwl, bk, gk, nullptr, nullptr);

    // V projection -> fused bf16 hi/lo
    split_kernel<<<(n4x + 255) / 256, 256>>>(V, gxh, gxl, n4x);
    split_kernel<<<(n4w + 255) / 256, 256>>>(Wv, gwh, gwl, n4w);
    gemm_mma<true><<<ggrid, 256, GEMM_SMEM>>>(gxh, gxl, gwh, gwl, bv, nullptr, gvh, gvl);

    // RoPE + split Q,K
    int items = 2 * B_ * S_ * H_ * 8;
    rope_split_kernel<<<(items + 255) / 256, 256>>>(gq, gk, grope, gqh, gql, gkh, gkl);

    // Flash -> fused bf16 hi/lo output (feeds output projection directly)
    dim3 fgrid(S_ / 128, H_, B_);
    flash_mma<<<fgrid, 256, FLASH_SMEM>>>(gqh, gql, gkh, gkl, gvh, gvl, gxh, gxl);

    // Output projection
    split_kernel<<<(n4w + 255) / 256, 256>>>(Wo, gwh, gwl, n4w);
    gemm_mma<false><<<ggrid, 256, GEMM_SMEM>>>(gxh, gxl, gwh, gwl, bo, out, nullptr, nullptr);
}

// round 8
// speedup vs baseline: 1.2511x; 1.1396x over previous
#include <cuda_runtime.h>
#include <cuda_bf16.h>
#include <cuda_fp16.h>
#include <math.h>
#include <stdint.h>

#define B_  4
#define S_  2048
#define D_  1024
#define H_  16
#define HD_ 64
#define M_  (B_ * S_)
#define NTOT (B_ * S_ * D_)

// Scratch (allocation-free rule: __device__ globals)
__device__ float g_q[NTOT];
__device__ float g_k[NTOT];
__device__ __nv_bfloat16 g_xh[NTOT];
__device__ __nv_bfloat16 g_xl[NTOT];
__device__ __nv_bfloat16 g_wh[D_ * D_];
__device__ __nv_bfloat16 g_wl[D_ * D_];
__device__ __nv_bfloat16 g_qh[NTOT];
__device__ __nv_bfloat16 g_ql[NTOT];
__device__ __nv_bfloat16 g_kh[NTOT];
__device__ __nv_bfloat16 g_kl[NTOT];
__device__ __half g_v16[NTOT];
__device__ float2 g_rope[S_ * 32];

// ===========================================================================
// Helpers (baseline PTX only — compute_103-safe)
// ===========================================================================
__device__ __forceinline__ uint32_t smem_to_u32(const void* p) {
    uint32_t a;
    asm("{ .reg .u64 t; cvta.to.shared.u64 t, %1; cvt.u32.u64 %0, t; }" : "=r"(a) : "l"(p));
    return a;
}
#define SMEM_SWIZZLE_128B(off) ((off) ^ (((off) >> 3) & 0x70))

__device__ __forceinline__ void cpa16(uint32_t dst, const void* src) {
    asm volatile("cp.async.cg.shared.global [%0], [%1], 16;" :: "r"(dst), "l"(src));
}
__device__ __forceinline__ void ldsm4(uint32_t& r0, uint32_t& r1, uint32_t& r2, uint32_t& r3,
                                      uint32_t addr) {
    asm volatile("ldmatrix.sync.aligned.m8n8.x4.shared.b16 {%0,%1,%2,%3}, [%4];"
        : "=r"(r0), "=r"(r1), "=r"(r2), "=r"(r3) : "r"(addr));
}
__device__ __forceinline__ void ldsm4t(uint32_t& r0, uint32_t& r1, uint32_t& r2, uint32_t& r3,
                                       uint32_t addr) {
    asm volatile("ldmatrix.sync.aligned.m8n8.x4.trans.shared.b16 {%0,%1,%2,%3}, [%4];"
        : "=r"(r0), "=r"(r1), "=r"(r2), "=r"(r3) : "r"(addr));
}
__device__ __forceinline__ void mma_bf16(float* d, const uint32_t* a,
                                         uint32_t b0, uint32_t b1) {
    asm volatile(
        "mma.sync.aligned.m16n8k16.row.col.f32.bf16.bf16.f32 "
        "{%0,%1,%2,%3}, {%4,%5,%6,%7}, {%8,%9}, {%0,%1,%2,%3};"
        : "+f"(d[0]), "+f"(d[1]), "+f"(d[2]), "+f"(d[3])
        : "r"(a[0]), "r"(a[1]), "r"(a[2]), "r"(a[3]), "r"(b0), "r"(b1));
}
__device__ __forceinline__ void mma_fp16(float* d, const uint32_t* a,
                                         uint32_t b0, uint32_t b1) {
    asm volatile(
        "mma.sync.aligned.m16n8k16.row.col.f32.f16.f16.f32 "
        "{%0,%1,%2,%3}, {%4,%5,%6,%7}, {%8,%9}, {%0,%1,%2,%3};"
        : "+f"(d[0]), "+f"(d[1]), "+f"(d[2]), "+f"(d[3])
        : "r"(a[0]), "r"(a[1]), "r"(a[2]), "r"(a[3]), "r"(b0), "r"(b1));
}
__device__ __forceinline__ void split2(float f0, float f1, uint32_t& hi, uint32_t& lo) {
    __nv_bfloat16 h0 = __float2bfloat16(f0), h1 = __float2bfloat16(f1);
    __nv_bfloat16 l0 = __float2bfloat16(f0 - __bfloat162float(h0));
    __nv_bfloat16 l1 = __float2bfloat16(f1 - __bfloat162float(h1));
    __nv_bfloat162 Hh(h0, h1), Ll(l0, l1);
    hi = *(uint32_t*)&Hh; lo = *(uint32_t*)&Ll;
}
__device__ __forceinline__ uint32_t pack_h2(float f0, float f1) {
    __half2 h = __floats2half2_rn(f0, f1);
    return *(uint32_t*)&h;
}

// ===========================================================================
// fp32 -> bf16 (hi, lo) split
// ===========================================================================
__global__ __launch_bounds__(256)
void split_kernel(const float* __restrict__ x,
                  __nv_bfloat16* __restrict__ h,
                  __nv_bfloat16* __restrict__ l, int n4)
{
    int i = blockIdx.x * blockDim.x + threadIdx.x;
    if (i >= n4) return;
    float4 v = ((const float4*)x)[i];
    uint32_t h01, l01, h23, l23;
    split2(v.x, v.y, h01, l01);
    split2(v.z, v.w, h23, l23);
    ((uint32_t*)h)[2 * i + 0] = h01;
    ((uint32_t*)h)[2 * i + 1] = h23;
    ((uint32_t*)l)[2 * i + 0] = l01;
    ((uint32_t*)l)[2 * i + 1] = l23;
}

// ===========================================================================
// mma.sync bf16-split GEMM. BK=64, 3-stage cp.async pipeline.
// OUTMODE: 0 = fp32 out, 2 = fp16 out (for V feeding the fp16 PV path).
// ===========================================================================
#define TILE_BYTES 16384
#define STAGE_BYTES (4 * TILE_BYTES)       // 64 KB
#define GEMM_SMEM (3 * STAGE_BYTES)        // 192 KB
#define NCHUNK (D_ / 64)                   // 16

__device__ __forceinline__ void gemm_load_chunk(
    uint32_t sb, int stage, int k0, int tid,
    const __nv_bfloat16* Ahb, const __nv_bfloat16* Alb,
    const __nv_bfloat16* Bhb, const __nv_bfloat16* Blb)
{
    uint32_t base = sb + stage * STAGE_BYTES;
#pragma unroll
    for (int rep = 0; rep < 4; rep++) {
        int id  = tid + rep * 256;
        int row = id >> 3;
        int seg = id & 7;
        uint32_t soff = SMEM_SWIZZLE_128B((uint32_t)(row * 128 + seg * 16));
        size_t goff = (size_t)row * D_ + k0 + seg * 8;
        cpa16(base + 0 * TILE_BYTES + soff, Ahb + goff);
        cpa16(base + 1 * TILE_BYTES + soff, Alb + goff);
        cpa16(base + 2 * TILE_BYTES + soff, Bhb + goff);
        cpa16(base + 3 * TILE_BYTES + soff, Blb + goff);
    }
    asm volatile("cp.async.commit_group;" ::: "memory");
}

template <int OUTMODE>
__global__ __launch_bounds__(256, 1)
void gemm_mma(const __nv_bfloat16* __restrict__ Ah, const __nv_bfloat16* __restrict__ Al,
              const __nv_bfloat16* __restrict__ Bh, const __nv_bfloat16* __restrict__ Bl,
              const float* __restrict__ bias, float* __restrict__ C,
              __half* __restrict__ C16)
{
    extern __shared__ char smem[];
    uint32_t sb = smem_to_u32(smem);
    const int tid  = threadIdx.x;
    const int wid  = tid >> 5;
    const int lane = tid & 31;
    const int warp_m = wid >> 2;
    const int warp_n = wid & 3;
    const int bn = blockIdx.x, bm = blockIdx.y;

    const __nv_bfloat16* Ahb = Ah + (size_t)(bm * 128) * D_;
    const __nv_bfloat16* Alb = Al + (size_t)(bm * 128) * D_;
    const __nv_bfloat16* Bhb = Bh + (size_t)(bn * 128) * D_;
    const __nv_bfloat16* Blb = Bl + (size_t)(bn * 128) * D_;

    float acc[4][4][4];
#pragma unroll
    for (int i = 0; i < 4; i++)
#pragma unroll
        for (int j = 0; j < 4; j++)
#pragma unroll
            for (int r = 0; r < 4; r++) acc[i][j][r] = 0.f;

    const int mat = lane >> 3;
    const int mrr = lane & 7;
    const int a_row_off = (mat & 1) * 8 + mrr;
    const int a_ks_off  = (mat >> 1) * 16;
    const int b_row_off = (mat >> 1) * 8 + mrr;
    const int b_ks_off  = (mat & 1) * 16;

    gemm_load_chunk(sb, 0, 0, tid, Ahb, Alb, Bhb, Blb);
    gemm_load_chunk(sb, 1, 64, tid, Ahb, Alb, Bhb, Blb);

    int stage = 0;
    for (int c = 0; c < NCHUNK; c++) {
        if (c + 2 < NCHUNK) {
            int ls = stage + 2; if (ls >= 3) ls -= 3;
            gemm_load_chunk(sb, ls, (c + 2) * 64, tid, Ahb, Alb, Bhb, Blb);
            asm volatile("cp.async.wait_group 2;" ::: "memory");
        } else if (c + 1 < NCHUNK) {
            asm volatile("cp.async.wait_group 1;" ::: "memory");
        } else {
            asm volatile("cp.async.wait_group 0;" ::: "memory");
        }
        __syncthreads();

        uint32_t stA = sb + stage * STAGE_BYTES;
#pragma unroll
        for (int ks = 0; ks < 4; ks++) {
            const int kb = ks * 32;
            uint32_t ah[4][4], al[4][4];
#pragma unroll
            for (int mt = 0; mt < 4; mt++) {
                int row = warp_m * 64 + mt * 16 + a_row_off;
                uint32_t off = SMEM_SWIZZLE_128B((uint32_t)(row * 128 + kb + a_ks_off));
                ldsm4(ah[mt][0], ah[mt][1], ah[mt][2], ah[mt][3], stA + 0 * TILE_BYTES + off);
                ldsm4(al[mt][0], al[mt][1], al[mt][2], al[mt][3], stA + 1 * TILE_BYTES + off);
            }
            uint32_t bh[2][4], bl[2][4];
#pragma unroll
            for (int p = 0; p < 2; p++) {
                int row = warp_n * 32 + p * 16 + b_row_off;
                uint32_t off = SMEM_SWIZZLE_128B((uint32_t)(row * 128 + kb + b_ks_off));
                ldsm4(bh[p][0], bh[p][1], bh[p][2], bh[p][3], stA + 2 * TILE_BYTES + off);
                ldsm4(bl[p][0], bl[p][1], bl[p][2], bl[p][3], stA + 3 * TILE_BYTES + off);
            }
#pragma unroll
            for (int mt = 0; mt < 4; mt++) {
#pragma unroll
                for (int p = 0; p < 2; p++) {
#pragma unroll
                    for (int q = 0; q < 2; q++) {
                        float* d = acc[mt][p * 2 + q];
                        mma_bf16(d, ah[mt], bh[p][q * 2], bh[p][q * 2 + 1]);
                        mma_bf16(d, ah[mt], bl[p][q * 2], bl[p][q * 2 + 1]);
                        mma_bf16(d, al[mt], bh[p][q * 2], bh[p][q * 2 + 1]);
                    }
                }
            }
        }
        __syncthreads();
        stage++; if (stage >= 3) stage = 0;
    }

    const int rbase = bm * 128 + warp_m * 64 + (lane >> 2);
    const int cbase = bn * 128 + warp_n * 32 + (lane & 3) * 2;
#pragma unroll
    for (int mt = 0; mt < 4; mt++) {
#pragma unroll
        for (int nt = 0; nt < 4; nt++) {
            int col = cbase + nt * 8;
            float b0 = bias[col], b1 = bias[col + 1];
            float* d = acc[mt][nt];
            int r0 = rbase + mt * 16;
            float v00 = d[0] + b0, v01 = d[1] + b1;
            float v10 = d[2] + b0, v11 = d[3] + b1;
            if (OUTMODE == 2) {
                *(uint32_t*)(C16 + (size_t)r0 * D_ + col)       = pack_h2(v00, v01);
                *(uint32_t*)(C16 + (size_t)(r0 + 8) * D_ + col) = pack_h2(v10, v11);
            } else {
                *(float2*)(C + (size_t)r0 * D_ + col)       = make_float2(v00, v01);
                *(float2*)(C + (size_t)(r0 + 8) * D_ + col) = make_float2(v10, v11);
            }
        }
    }
}

// ---------------------------------------------------------------------------
// RoPE table (fp64 for exactness)
// ---------------------------------------------------------------------------
__global__ void rope_table_kernel(float2* __restrict__ tab)
{
    int idx = blockIdx.x * blockDim.x + threadIdx.x;
    if (idx >= S_ * 32) return;
    int s = idx >> 5;
    int d = idx & 31;
    double inv = exp(-log(10000.0) * (double)d / 32.0);
    double ang = (double)s * inv;
    double sd, cd;
    sincos(ang, &sd, &cd);
    tab[idx] = make_float2((float)cd, (float)sd);
}

// ---------------------------------------------------------------------------
// Fused RoPE + bf16 hi/lo split for Q and K
// ---------------------------------------------------------------------------
__global__ __launch_bounds__(256)
void rope_split_kernel(const float* __restrict__ q, const float* __restrict__ k,
                       const float2* __restrict__ tab,
                       __nv_bfloat16* __restrict__ qh, __nv_bfloat16* __restrict__ ql,
                       __nv_bfloat16* __restrict__ kh, __nv_bfloat16* __restrict__ kl)
{
    const int half = B_ * S_ * H_ * 8;
    int idx = blockIdx.x * blockDim.x + threadIdx.x;
    if (idx >= 2 * half) return;
    const float* x = (idx < half) ? q : k;
    __nv_bfloat16* oh = (idx < half) ? qh : kh;
    __nv_bfloat16* ol = (idx < half) ? ql : kl;
    int i = (idx < half) ? idx : idx - half;

    int dv = (i & 7) << 2;
    int h  = (i >> 3) & (H_ - 1);
    int bs = i >> 7;
    int s  = bs & (S_ - 1);

    size_t base = (size_t)bs * D_ + h * HD_ + dv;
    const float* p = x + base;
    float4 a = *(const float4*)p;
    float4 b = *(const float4*)(p + 32);
    const float2* t = tab + s * 32 + dv;
    float2 t0 = t[0], t1 = t[1], t2 = t[2], t3 = t[3];

    float4 ra, rb;
    ra.x = fmaf(a.x, t0.x, -b.x * t0.y);  rb.x = fmaf(a.x, t0.y, b.x * t0.x);
    ra.y = fmaf(a.y, t1.x, -b.y * t1.y);  rb.y = fmaf(a.y, t1.y, b.y * t1.x);
    ra.z = fmaf(a.z, t2.x, -b.z * t2.y);  rb.z = fmaf(a.z, t2.y, b.z * t2.x);
    ra.w = fmaf(a.w, t3.x, -b.w * t3.y);  rb.w = fmaf(a.w, t3.y, b.w * t3.x);

    uint32_t h01, l01, h23, l23;
    split2(ra.x, ra.y, h01, l01); split2(ra.z, ra.w, h23, l23);
    *(uint32_t*)(oh + base)     = h01;  *(uint32_t*)(oh + base + 2) = h23;
    *(uint32_t*)(ol + base)     = l01;  *(uint32_t*)(ol + base + 2) = l23;
    split2(rb.x, rb.y, h01, l01); split2(rb.z, rb.w, h23, l23);
    *(uint32_t*)(oh + base + 32) = h01; *(uint32_t*)(oh + base + 34) = h23;
    *(uint32_t*)(ol + base + 32) = l01; *(uint32_t*)(ol + base + 34) = l23;
}

// ===========================================================================
// Tensor-core flash attention. BM=128, BN=64.
// QK: bf16 3-term split. PV: fp16 single-term. Output: fused bf16 hi/lo.
// ===========================================================================
#define FQH 0
#define FQL 16384
#define FST 32768
#define FKH 0
#define FKL 8192
#define FV16 16384
#define FSTAGE 24576
#define FLASH_SMEM (32768 + 2 * FSTAGE)   // 81920

__device__ __forceinline__ void flash_load_kv(
    uint32_t sb, int stage, int kt, int tid,
    const __nv_bfloat16* Khb, const __nv_bfloat16* Klb,
    const __half* Vb)
{
    uint32_t base = sb + FST + stage * FSTAGE;
    size_t rbase = (size_t)(kt * 64) * D_;
#pragma unroll
    for (int rep = 0; rep < 2; rep++) {
        int id  = tid + rep * 256;
        int row = id >> 3;
        int seg = id & 7;
        uint32_t soff = SMEM_SWIZZLE_128B((uint32_t)(row * 128 + seg * 16));
        size_t goff = rbase + (size_t)row * D_ + seg * 8;
        cpa16(base + FKH + soff, Khb + goff);
        cpa16(base + FKL + soff, Klb + goff);
        cpa16(base + FV16 + soff, Vb + goff);
    }
    asm volatile("cp.async.commit_group;" ::: "memory");
}

__global__ __launch_bounds__(256)
void flash_mma(const __nv_bfloat16* __restrict__ Qh_g, const __nv_bfloat16* __restrict__ Ql_g,
               const __nv_bfloat16* __restrict__ Kh_g, const __nv_bfloat16* __restrict__ Kl_g,
               const __half* __restrict__ V_g,
               __nv_bfloat16* __restrict__ Oh_g, __nv_bfloat16* __restrict__ Ol_g)
{
    extern __shared__ char smem[];
    uint32_t sb = smem_to_u32(smem);
    const int tid  = threadIdx.x;
    const int wid  = tid >> 5;
    const int lane = tid & 31;
    const int qt = blockIdx.x, h = blockIdx.y, b = blockIdx.z;

    const int g = lane >> 2, c = lane & 3;
    const int mat = lane >> 3, mrr = lane & 7;
    const int a_row_off = (mat & 1) * 8 + mrr;
    const int a_ks_off  = (mat >> 1) * 16;
    const int b_row_off = (mat >> 1) * 8 + mrr;
    const int b_ks_off  = (mat & 1) * 16;
    const int v_l = lane & 7, v_half = (lane >> 3) & 1, v_quad = lane >> 4;

    const size_t hoff = (size_t)(b * S_) * D_ + h * HD_;
    const __nv_bfloat16* Qhb = Qh_g + hoff + (size_t)(qt * 128) * D_;
    const __nv_bfloat16* Qlb = Ql_g + hoff + (size_t)(qt * 128) * D_;
    const __nv_bfloat16* Khb = Kh_g + hoff;
    const __nv_bfloat16* Klb = Kl_g + hoff;
    const __half* Vb = V_g + hoff;

#pragma unroll
    for (int rep = 0; rep < 4; rep++) {
        int id  = tid + rep * 256;
        int row = id >> 3;
        int seg = id & 7;
        uint32_t soff = SMEM_SWIZZLE_128B((uint32_t)(row * 128 + seg * 16));
        size_t goff = (size_t)row * D_ + seg * 8;
        cpa16(sb + FQH + soff, Qhb + goff);
        cpa16(sb + FQL + soff, Qlb + goff);
    }
    asm volatile("cp.async.commit_group;" ::: "memory");

    flash_load_kv(sb, 0, 0, tid, Khb, Klb, Vb);
    asm volatile("cp.async.wait_group 0;" ::: "memory");
    __syncthreads();

    uint32_t qhf[4][4], qlf[4][4];
#pragma unroll
    for (int t = 0; t < 4; t++) {
        int rowA = wid * 16 + a_row_off;
        uint32_t off = SMEM_SWIZZLE_128B((uint32_t)(rowA * 128 + t * 32 + a_ks_off));
        ldsm4(qhf[t][0], qhf[t][1], qhf[t][2], qhf[t][3], sb + FQH + off);
        ldsm4(qlf[t][0], qlf[t][1], qlf[t][2], qlf[t][3], sb + FQL + off);
    }

    float mi0 = -INFINITY, mi1 = -INFINITY, li0 = 0.f, li1 = 0.f;
    float o[8][4];
#pragma unroll
    for (int j = 0; j < 8; j++)
#pragma unroll
        for (int r = 0; r < 4; r++) o[j][r] = 0.f;

    const int wrow = qt * 128 + wid * 16;
    const int ktmax = 2 * qt + 1;

    for (int kt = 0; kt <= ktmax; kt++) {
        int s = kt & 1;
        if (kt < ktmax) {
            flash_load_kv(sb, s ^ 1, kt + 1, tid, Khb, Klb, Vb);
            asm volatile("cp.async.wait_group 1;" ::: "memory");
        } else {
            asm volatile("cp.async.wait_group 0;" ::: "memory");
        }
        __syncthreads();

        if (kt * 64 <= wrow + 15) {
            uint32_t st = sb + FST + s * FSTAGE;
            float sc[8][4];
#pragma unroll
            for (int j = 0; j < 8; j++)
#pragma unroll
                for (int r = 0; r < 4; r++) sc[j][r] = 0.f;

#pragma unroll
            for (int t = 0; t < 4; t++) {
#pragma unroll
                for (int p = 0; p < 4; p++) {
                    uint32_t kh4[4], kl4[4];
                    int rowB = p * 16 + b_row_off;
                    uint32_t off = SMEM_SWIZZLE_128B((uint32_t)(rowB * 128 + t * 32 + b_ks_off));
                    ldsm4(kh4[0], kh4[1], kh4[2], kh4[3], st + FKH + off);
                    ldsm4(kl4[0], kl4[1], kl4[2], kl4[3], st + FKL + off);
#pragma unroll
                    for (int q = 0; q < 2; q++) {
                        float* d = sc[2 * p + q];
                        mma_bf16(d, qhf[t], kh4[q * 2], kh4[q * 2 + 1]);
                        mma_bf16(d, qhf[t], kl4[q * 2], kl4[q * 2 + 1]);
                        mma_bf16(d, qlf[t], kh4[q * 2], kh4[q * 2 + 1]);
                    }
                }
            }

            const float scale = 0.125f;
            const int row0 = wrow + g, row1 = row0 + 8;
            const bool diag = (kt * 64 + 63 > wrow);
#pragma unroll
            for (int j = 0; j < 8; j++) {
                int col0 = kt * 64 + j * 8 + 2 * c, col1 = col0 + 1;
                sc[j][0] *= scale; sc[j][1] *= scale;
                sc[j][2] *= scale; sc[j][3] *= scale;
                if (diag) {
                    if (col0 > row0) sc[j][0] = -INFINITY;
                    if (col1 > row0) sc[j][1] = -INFINITY;
                    if (col0 > row1) sc[j][2] = -INFINITY;
                    if (col1 > row1) sc[j][3] = -INFINITY;
                }
            }
            float rm0 = -INFINITY, rm1 = -INFINITY;
#pragma unroll
            for (int j = 0; j < 8; j++) {
                rm0 = fmaxf(rm0, fmaxf(sc[j][0], sc[j][1]));
                rm1 = fmaxf(rm1, fmaxf(sc[j][2], sc[j][3]));
            }
            rm0 = fmaxf(rm0, __shfl_xor_sync(0xffffffffu, rm0, 1));
            rm0 = fmaxf(rm0, __shfl_xor_sync(0xffffffffu, rm0, 2));
            rm1 = fmaxf(rm1, __shfl_xor_sync(0xffffffffu, rm1, 1));
            rm1 = fmaxf(rm1, __shfl_xor_sync(0xffffffffu, rm1, 2));

            float mn0 = fmaxf(mi0, rm0), mn1 = fmaxf(mi1, rm1);
            float al0 = __expf(mi0 - mn0), al1 = __expf(mi1 - mn1);
            float rs0 = 0.f, rs1 = 0.f;
#pragma unroll
            for (int j = 0; j < 8; j++) {
                sc[j][0] = __expf(sc[j][0] - mn0);
                sc[j][1] = __expf(sc[j][1] - mn0);
                sc[j][2] = __expf(sc[j][2] - mn1);
                sc[j][3] = __expf(sc[j][3] - mn1);
                rs0 += sc[j][0] + sc[j][1];
                rs1 += sc[j][2] + sc[j][3];
            }
            rs0 += __shfl_xor_sync(0xffffffffu, rs0, 1);
            rs0 += __shfl_xor_sync(0xffffffffu, rs0, 2);
            rs1 += __shfl_xor_sync(0xffffffffu, rs1, 1);
            rs1 += __shfl_xor_sync(0xffffffffu, rs1, 2);
            li0 = li0 * al0 + rs0; li1 = li1 * al1 + rs1;
            mi0 = mn0; mi1 = mn1;
#pragma unroll
            for (int j = 0; j < 8; j++) {
                o[j][0] *= al0; o[j][1] *= al0;
                o[j][2] *= al1; o[j][3] *= al1;
            }

            // pack P into fp16 A-fragments (single term)
            uint32_t ph[4][4];
#pragma unroll
            for (int t = 0; t < 4; t++) {
                ph[t][0] = pack_h2(sc[2 * t][0],     sc[2 * t][1]);
                ph[t][1] = pack_h2(sc[2 * t][2],     sc[2 * t][3]);
                ph[t][2] = pack_h2(sc[2 * t + 1][0], sc[2 * t + 1][1]);
                ph[t][3] = pack_h2(sc[2 * t + 1][2], sc[2 * t + 1][3]);
            }

            // O += P V (fp16 single-term), V via ldmatrix.trans
#pragma unroll
            for (int t = 0; t < 4; t++) {
#pragma unroll
                for (int jp = 0; jp < 4; jp++) {
                    uint32_t soff = SMEM_SWIZZLE_128B(
                        (uint32_t)((16 * t + v_half * 8 + v_l) * 128 + jp * 32 + v_quad * 16));
                    uint32_t v4[4];
                    ldsm4t(v4[0], v4[1], v4[2], v4[3], st + FV16 + soff);
                    mma_fp16(o[2 * jp],     ph[t], v4[0], v4[1]);
                    mma_fp16(o[2 * jp + 1], ph[t], v4[2], v4[3]);
                }
            }
        }
        __syncthreads();
    }

    float iv0 = 1.f / li0, iv1 = 1.f / li1;
    size_t r0off = ((size_t)(b * S_ + wrow + g)) * D_ + h * HD_;
    size_t r1off = r0off + 8 * D_;
#pragma unroll
    for (int j = 0; j < 8; j++) {
        int col = j * 8 + 2 * c;
        uint32_t hi, lo;
        split2(o[j][0] * iv0, o[j][1] * iv0, hi, lo);
        *(uint32_t*)(Oh_g + r0off + col) = hi;
        *(uint32_t*)(Ol_g + r0off + col) = lo;
        split2(o[j][2] * iv1, o[j][3] * iv1, hi, lo);
        *(uint32_t*)(Oh_g + r1off + col) = hi;
        *(uint32_t*)(Ol_g + r1off + col) = lo;
    }
}

// ---------------------------------------------------------------------------
extern "C" void kernel_launch(void* const* d_in, const int* in_sizes, int n_in,
                              void* d_out, int out_size)
{
    const float* Q  = (const float*)d_in[0];
    const float* K  = (const float*)d_in[1];
    const float* V  = (const float*)d_in[2];
    const float* Wq = (const float*)d_in[3];
    const float* bq = (const float*)d_in[4];
    const float* Wk = (const float*)d_in[5];
    const float* bk = (const float*)d_in[6];
    const float* Wv = (const float*)d_in[7];
    const float* bv = (const float*)d_in[8];
    const float* Wo = (const float*)d_in[9];
    const float* bo = (const float*)d_in[10];
    float* out = (float*)d_out;

    float *gq, *gk;
    float2* grope;
    __nv_bfloat16 *gxh, *gxl, *gwh, *gwl;
    __nv_bfloat16 *gqh, *gql, *gkh, *gkl;
    __half* gv16;
    cudaGetSymbolAddress((void**)&gq, g_q);
    cudaGetSymbolAddress((void**)&gk, g_k);
    cudaGetSymbolAddress((void**)&grope, g_rope);
    cudaGetSymbolAddress((void**)&gxh, g_xh);
    cudaGetSymbolAddress((void**)&gxl, g_xl);
    cudaGetSymbolAddress((void**)&gwh, g_wh);
    cudaGetSymbolAddress((void**)&gwl, g_wl);
    cudaGetSymbolAddress((void**)&gqh, g_qh);
    cudaGetSymbolAddress((void**)&gql, g_ql);
    cudaGetSymbolAddress((void**)&gkh, g_kh);
    cudaGetSymbolAddress((void**)&gkl, g_kl);
    cudaGetSymbolAddress((void**)&gv16, g_v16);

    cudaFuncSetAttribute(gemm_mma<0>, cudaFuncAttributeMaxDynamicSharedMemorySize, GEMM_SMEM);
    cudaFuncSetAttribute(gemm_mma<2>, cudaFuncAttributeMaxDynamicSharedMemorySize, GEMM_SMEM);
    cudaFuncSetAttribute(flash_mma, cudaFuncAttributeMaxDynamicSharedMemorySize, FLASH_SMEM);

    const int n4x = NTOT / 4;
    const int n4w = (D_ * D_) / 4;
    dim3 ggrid(D_ / 128, M_ / 128);

    rope_table_kernel<<<(S_ * 32 + 255) / 256, 256>>>(grope);

    // Q projection -> fp32 (rope needs fp32 rows)
    split_kernel<<<(n4x + 255) / 256, 256>>>(Q, gxh, gxl, n4x);
    split_kernel<<<(n4w + 255) / 256, 256>>>(Wq, gwh, gwl, n4w);
    gemm_mma<0><<<ggrid, 256, GEMM_SMEM>>>(gxh, gxl, gwh, gwl, bq, gq, nullptr);

    // K projection -> fp32
    split_kernel<<<(n4x + 255) / 256, 256>>>(K, gxh, gxl, n4x);
    split_kernel<<<(n4w + 255) / 256, 256>>>(Wk, gwh, gwl, n4w);
    gemm_mma<0><<<ggrid, 256, GEMM_SMEM>>>(gxh, gxl, gwh, gwl, bk, gk, nullptr);

    // V projection -> fused fp16 out
    split_kernel<<<(n4x + 255) / 256, 256>>>(V, gxh, gxl, n4x);
    split_kernel<<<(n4w + 255) / 256, 256>>>(Wv, gwh, gwl, n4w);
    gemm_mma<2><<<ggrid, 256, GEMM_SMEM>>>(gxh, gxl, gwh, gwl, bv, nullptr, gv16);

    // RoPE + split Q,K
    int items = 2 * B_ * S_ * H_ * 8;
    rope_split_kernel<<<(items + 255) / 256, 256>>>(gq, gk, grope, gqh, gql, gkh, gkl);

    // Flash -> fused bf16 hi/lo output (feeds output projection directly)
    dim3 fgrid(S_ / 128, H_, B_);
    flash_mma<<<fgrid, 256, FLASH_SMEM>>>(gqh, gql, gkh, gkl, gv16, gxh, gxl);

    // Output projection
    split_kernel<<<(n4w + 255) / 256, 256>>>(Wo, gwh, gwl, n4w);
    gemm_mma<0><<<ggrid, 256, GEMM_SMEM>>>(gxh, gxl, gwh, gwl, bo, out, nullptr);
}

// round 9
// speedup vs baseline: 2.0351x; 1.6266x over previous
#include <cuda_runtime.h>
#include <cuda_bf16.h>
#include <cuda_fp16.h>
#include <math.h>
#include <stdint.h>

#define B_  4
#define S_  2048
#define D_  1024
#define H_  16
#define HD_ 64
#define M_  (B_ * S_)
#define NTOT (B_ * S_ * D_)

// Scratch (allocation-free rule: __device__ globals)
__device__ float g_q[NTOT];
__device__ float g_k[NTOT];
__device__ __half g_x16[NTOT];
__device__ __half g_w16[D_ * D_];
__device__ __half g_v16[NTOT];
__device__ __half g_o16[NTOT];
__device__ __nv_bfloat16 g_qh[NTOT];
__device__ __nv_bfloat16 g_ql[NTOT];
__device__ __nv_bfloat16 g_kh[NTOT];
__device__ __nv_bfloat16 g_kl[NTOT];
__device__ float2 g_rope[S_ * 32];

// ===========================================================================
// Helpers (baseline PTX only — compute_103-safe)
// ===========================================================================
__device__ __forceinline__ uint32_t smem_to_u32(const void* p) {
    uint32_t a;
    asm("{ .reg .u64 t; cvta.to.shared.u64 t, %1; cvt.u32.u64 %0, t; }" : "=r"(a) : "l"(p));
    return a;
}
#define SMEM_SWIZZLE_128B(off) ((off) ^ (((off) >> 3) & 0x70))

__device__ __forceinline__ void cpa16(uint32_t dst, const void* src) {
    asm volatile("cp.async.cg.shared.global [%0], [%1], 16;" :: "r"(dst), "l"(src));
}
__device__ __forceinline__ void ldsm4(uint32_t& r0, uint32_t& r1, uint32_t& r2, uint32_t& r3,
                                      uint32_t addr) {
    asm volatile("ldmatrix.sync.aligned.m8n8.x4.shared.b16 {%0,%1,%2,%3}, [%4];"
        : "=r"(r0), "=r"(r1), "=r"(r2), "=r"(r3) : "r"(addr));
}
__device__ __forceinline__ void ldsm4t(uint32_t& r0, uint32_t& r1, uint32_t& r2, uint32_t& r3,
                                       uint32_t addr) {
    asm volatile("ldmatrix.sync.aligned.m8n8.x4.trans.shared.b16 {%0,%1,%2,%3}, [%4];"
        : "=r"(r0), "=r"(r1), "=r"(r2), "=r"(r3) : "r"(addr));
}
__device__ __forceinline__ void mma_bf16(float* d, const uint32_t* a,
                                         uint32_t b0, uint32_t b1) {
    asm volatile(
        "mma.sync.aligned.m16n8k16.row.col.f32.bf16.bf16.f32 "
        "{%0,%1,%2,%3}, {%4,%5,%6,%7}, {%8,%9}, {%0,%1,%2,%3};"
        : "+f"(d[0]), "+f"(d[1]), "+f"(d[2]), "+f"(d[3])
        : "r"(a[0]), "r"(a[1]), "r"(a[2]), "r"(a[3]), "r"(b0), "r"(b1));
}
__device__ __forceinline__ void mma_fp16(float* d, const uint32_t* a,
                                         uint32_t b0, uint32_t b1) {
    asm volatile(
        "mma.sync.aligned.m16n8k16.row.col.f32.f16.f16.f32 "
        "{%0,%1,%2,%3}, {%4,%5,%6,%7}, {%8,%9}, {%0,%1,%2,%3};"
        : "+f"(d[0]), "+f"(d[1]), "+f"(d[2]), "+f"(d[3])
        : "r"(a[0]), "r"(a[1]), "r"(a[2]), "r"(a[3]), "r"(b0), "r"(b1));
}
__device__ __forceinline__ void split2(float f0, float f1, uint32_t& hi, uint32_t& lo) {
    __nv_bfloat16 h0 = __float2bfloat16(f0), h1 = __float2bfloat16(f1);
    __nv_bfloat16 l0 = __float2bfloat16(f0 - __bfloat162float(h0));
    __nv_bfloat16 l1 = __float2bfloat16(f1 - __bfloat162float(h1));
    __nv_bfloat162 Hh(h0, h1), Ll(l0, l1);
    hi = *(uint32_t*)&Hh; lo = *(uint32_t*)&Ll;
}
__device__ __forceinline__ uint32_t pack_h2(float f0, float f1) {
    __half2 h = __floats2half2_rn(f0, f1);
    return *(uint32_t*)&h;
}

// ===========================================================================
// fp32 -> fp16 convert (vectorized)
// ===========================================================================
__global__ __launch_bounds__(256)
void cvt16_kernel(const float* __restrict__ x, __half* __restrict__ o, int n4)
{
    int i = blockIdx.x * blockDim.x + threadIdx.x;
    if (i >= n4) return;
    float4 v = ((const float4*)x)[i];
    ((uint32_t*)o)[2 * i + 0] = pack_h2(v.x, v.y);
    ((uint32_t*)o)[2 * i + 1] = pack_h2(v.z, v.w);
}

// ===========================================================================
// Single-fp16 GEMM: C[M,N] = A[M,K] @ W[N,K]^T + bias. 128x128 tile, BK=64,
// 3-stage cp.async, 2 CTAs/SM. OUTMODE: 0 = fp32 out, 2 = fp16 out.
// ===========================================================================
#define TILE_BYTES 16384                   // 128 rows x 128 B (128x64 fp16)
#define STAGE_BYTES (2 * TILE_BYTES)       // 32 KB (A + B)
#define GEMM_SMEM (3 * STAGE_BYTES)        // 96 KB -> 2 CTAs/SM
#define NCHUNK (D_ / 64)                   // 16

__device__ __forceinline__ void gemm_load_chunk(
    uint32_t sb, int stage, int k0, int tid,
    const __half* Ab, const __half* Bb)
{
    uint32_t base = sb + stage * STAGE_BYTES;
#pragma unroll
    for (int rep = 0; rep < 4; rep++) {
        int id  = tid + rep * 256;
        int row = id >> 3;
        int seg = id & 7;
        uint32_t soff = SMEM_SWIZZLE_128B((uint32_t)(row * 128 + seg * 16));
        size_t goff = (size_t)row * D_ + k0 + seg * 8;
        cpa16(base + 0 * TILE_BYTES + soff, Ab + goff);
        cpa16(base + 1 * TILE_BYTES + soff, Bb + goff);
    }
    asm volatile("cp.async.commit_group;" ::: "memory");
}

template <int OUTMODE>
__global__ __launch_bounds__(256, 2)
void gemm_mma16(const __half* __restrict__ A, const __half* __restrict__ W,
                const float* __restrict__ bias, float* __restrict__ C,
                __half* __restrict__ C16)
{
    extern __shared__ char smem[];
    uint32_t sb = smem_to_u32(smem);
    const int tid  = threadIdx.x;
    const int wid  = tid >> 5;
    const int lane = tid & 31;
    const int warp_m = wid >> 2;
    const int warp_n = wid & 3;
    const int bn = blockIdx.x, bm = blockIdx.y;

    const __half* Ab = A + (size_t)(bm * 128) * D_;
    const __half* Bb = W + (size_t)(bn * 128) * D_;

    float acc[4][4][4];
#pragma unroll
    for (int i = 0; i < 4; i++)
#pragma unroll
        for (int j = 0; j < 4; j++)
#pragma unroll
            for (int r = 0; r < 4; r++) acc[i][j][r] = 0.f;

    const int mat = lane >> 3;
    const int mrr = lane & 7;
    const int a_row_off = (mat & 1) * 8 + mrr;
    const int a_ks_off  = (mat >> 1) * 16;
    const int b_row_off = (mat >> 1) * 8 + mrr;
    const int b_ks_off  = (mat & 1) * 16;

    gemm_load_chunk(sb, 0, 0, tid, Ab, Bb);
    gemm_load_chunk(sb, 1, 64, tid, Ab, Bb);

    int stage = 0;
    for (int c = 0; c < NCHUNK; c++) {
        if (c + 2 < NCHUNK) {
            int ls = stage + 2; if (ls >= 3) ls -= 3;
            gemm_load_chunk(sb, ls, (c + 2) * 64, tid, Ab, Bb);
            asm volatile("cp.async.wait_group 2;" ::: "memory");
        } else if (c + 1 < NCHUNK) {
            asm volatile("cp.async.wait_group 1;" ::: "memory");
        } else {
            asm volatile("cp.async.wait_group 0;" ::: "memory");
        }
        __syncthreads();

        uint32_t stA = sb + stage * STAGE_BYTES;
#pragma unroll
        for (int ks = 0; ks < 4; ks++) {
            const int kb = ks * 32;
            uint32_t ah[4][4];
#pragma unroll
            for (int mt = 0; mt < 4; mt++) {
                int row = warp_m * 64 + mt * 16 + a_row_off;
                uint32_t off = SMEM_SWIZZLE_128B((uint32_t)(row * 128 + kb + a_ks_off));
                ldsm4(ah[mt][0], ah[mt][1], ah[mt][2], ah[mt][3], stA + 0 * TILE_BYTES + off);
            }
            uint32_t bh[2][4];
#pragma unroll
            for (int p = 0; p < 2; p++) {
                int row = warp_n * 32 + p * 16 + b_row_off;
                uint32_t off = SMEM_SWIZZLE_128B((uint32_t)(row * 128 + kb + b_ks_off));
                ldsm4(bh[p][0], bh[p][1], bh[p][2], bh[p][3], stA + 1 * TILE_BYTES + off);
            }
#pragma unroll
            for (int mt = 0; mt < 4; mt++) {
#pragma unroll
                for (int p = 0; p < 2; p++) {
#pragma unroll
                    for (int q = 0; q < 2; q++) {
                        mma_fp16(acc[mt][p * 2 + q], ah[mt], bh[p][q * 2], bh[p][q * 2 + 1]);
                    }
                }
            }
        }
        __syncthreads();
        stage++; if (stage >= 3) stage = 0;
    }

    const int rbase = bm * 128 + warp_m * 64 + (lane >> 2);
    const int cbase = bn * 128 + warp_n * 32 + (lane & 3) * 2;
#pragma unroll
    for (int mt = 0; mt < 4; mt++) {
#pragma unroll
        for (int nt = 0; nt < 4; nt++) {
            int col = cbase + nt * 8;
            float b0 = bias[col], b1 = bias[col + 1];
            float* d = acc[mt][nt];
            int r0 = rbase + mt * 16;
            float v00 = d[0] + b0, v01 = d[1] + b1;
            float v10 = d[2] + b0, v11 = d[3] + b1;
            if (OUTMODE == 2) {
                *(uint32_t*)(C16 + (size_t)r0 * D_ + col)       = pack_h2(v00, v01);
                *(uint32_t*)(C16 + (size_t)(r0 + 8) * D_ + col) = pack_h2(v10, v11);
            } else {
                *(float2*)(C + (size_t)r0 * D_ + col)       = make_float2(v00, v01);
                *(float2*)(C + (size_t)(r0 + 8) * D_ + col) = make_float2(v10, v11);
            }
        }
    }
}

// ---------------------------------------------------------------------------
// RoPE table (fp64 for exactness)
// ---------------------------------------------------------------------------
__global__ void rope_table_kernel(float2* __restrict__ tab)
{
    int idx = blockIdx.x * blockDim.x + threadIdx.x;
    if (idx >= S_ * 32) return;
    int s = idx >> 5;
    int d = idx & 31;
    double inv = exp(-log(10000.0) * (double)d / 32.0);
    double ang = (double)s * inv;
    double sd, cd;
    sincos(ang, &sd, &cd);
    tab[idx] = make_float2((float)cd, (float)sd);
}

// ---------------------------------------------------------------------------
// Fused RoPE + bf16 hi/lo split for Q and K
// ---------------------------------------------------------------------------
__global__ __launch_bounds__(256)
void rope_split_kernel(const float* __restrict__ q, const float* __restrict__ k,
                       const float2* __restrict__ tab,
                       __nv_bfloat16* __restrict__ qh, __nv_bfloat16* __restrict__ ql,
                       __nv_bfloat16* __restrict__ kh, __nv_bfloat16* __restrict__ kl)
{
    const int half = B_ * S_ * H_ * 8;
    int idx = blockIdx.x * blockDim.x + threadIdx.x;
    if (idx >= 2 * half) return;
    const float* x = (idx < half) ? q : k;
    __nv_bfloat16* oh = (idx < half) ? qh : kh;
    __nv_bfloat16* ol = (idx < half) ? ql : kl;
    int i = (idx < half) ? idx : idx - half;

    int dv = (i & 7) << 2;
    int h  = (i >> 3) & (H_ - 1);
    int bs = i >> 7;
    int s  = bs & (S_ - 1);

    size_t base = (size_t)bs * D_ + h * HD_ + dv;
    const float* p = x + base;
    float4 a = *(const float4*)p;
    float4 b = *(const float4*)(p + 32);
    const float2* t = tab + s * 32 + dv;
    float2 t0 = t[0], t1 = t[1], t2 = t[2], t3 = t[3];

    float4 ra, rb;
    ra.x = fmaf(a.x, t0.x, -b.x * t0.y);  rb.x = fmaf(a.x, t0.y, b.x * t0.x);
    ra.y = fmaf(a.y, t1.x, -b.y * t1.y);  rb.y = fmaf(a.y, t1.y, b.y * t1.x);
    ra.z = fmaf(a.z, t2.x, -b.z * t2.y);  rb.z = fmaf(a.z, t2.y, b.z * t2.x);
    ra.w = fmaf(a.w, t3.x, -b.w * t3.y);  rb.w = fmaf(a.w, t3.y, b.w * t3.x);

    uint32_t h01, l01, h23, l23;
    split2(ra.x, ra.y, h01, l01); split2(ra.z, ra.w, h23, l23);
    *(uint32_t*)(oh + base)     = h01;  *(uint32_t*)(oh + base + 2) = h23;
    *(uint32_t*)(ol + base)     = l01;  *(uint32_t*)(ol + base + 2) = l23;
    split2(rb.x, rb.y, h01, l01); split2(rb.z, rb.w, h23, l23);
    *(uint32_t*)(oh + base + 32) = h01; *(uint32_t*)(oh + base + 34) = h23;
    *(uint32_t*)(ol + base + 32) = l01; *(uint32_t*)(ol + base + 34) = l23;
}

// ===========================================================================
// Tensor-core flash attention. BM=128, BN=64.
// QK: bf16 3-term split. PV: fp16 single-term. Output: fused fp16.
// ===========================================================================
#define FQH 0
#define FQL 16384
#define FST 32768
#define FKH 0
#define FKL 8192
#define FV16 16384
#define FSTAGE 24576
#define FLASH_SMEM (32768 + 2 * FSTAGE)   // 81920

__device__ __forceinline__ void flash_load_kv(
    uint32_t sb, int stage, int kt, int tid,
    const __nv_bfloat16* Khb, const __nv_bfloat16* Klb,
    const __half* Vb)
{
    uint32_t base = sb + FST + stage * FSTAGE;
    size_t rbase = (size_t)(kt * 64) * D_;
#pragma unroll
    for (int rep = 0; rep < 2; rep++) {
        int id  = tid + rep * 256;
        int row = id >> 3;
        int seg = id & 7;
        uint32_t soff = SMEM_SWIZZLE_128B((uint32_t)(row * 128 + seg * 16));
        size_t goff = rbase + (size_t)row * D_ + seg * 8;
        cpa16(base + FKH + soff, Khb + goff);
        cpa16(base + FKL + soff, Klb + goff);
        cpa16(base + FV16 + soff, Vb + goff);
    }
    asm volatile("cp.async.commit_group;" ::: "memory");
}

__global__ __launch_bounds__(256)
void flash_mma(const __nv_bfloat16* __restrict__ Qh_g, const __nv_bfloat16* __restrict__ Ql_g,
               const __nv_bfloat16* __restrict__ Kh_g, const __nv_bfloat16* __restrict__ Kl_g,
               const __half* __restrict__ V_g,
               __half* __restrict__ O_g)
{
    extern __shared__ char smem[];
    uint32_t sb = smem_to_u32(smem);
    const int tid  = threadIdx.x;
    const int wid  = tid >> 5;
    const int lane = tid & 31;
    const int qt = blockIdx.x, h = blockIdx.y, b = blockIdx.z;

    const int g = lane >> 2, c = lane & 3;
    const int mat = lane >> 3, mrr = lane & 7;
    const int a_row_off = (mat & 1) * 8 + mrr;
    const int a_ks_off  = (mat >> 1) * 16;
    const int b_row_off = (mat >> 1) * 8 + mrr;
    const int b_ks_off  = (mat & 1) * 16;
    const int v_l = lane & 7, v_half = (lane >> 3) & 1, v_quad = lane >> 4;

    const size_t hoff = (size_t)(b * S_) * D_ + h * HD_;
    const __nv_bfloat16* Qhb = Qh_g + hoff + (size_t)(qt * 128) * D_;
    const __nv_bfloat16* Qlb = Ql_g + hoff + (size_t)(qt * 128) * D_;
    const __nv_bfloat16* Khb = Kh_g + hoff;
    const __nv_bfloat16* Klb = Kl_g + hoff;
    const __half* Vb = V_g + hoff;

#pragma unroll
    for (int rep = 0; rep < 4; rep++) {
        int id  = tid + rep * 256;
        int row = id >> 3;
        int seg = id & 7;
        uint32_t soff = SMEM_SWIZZLE_128B((uint32_t)(row * 128 + seg * 16));
        size_t goff = (size_t)row * D_ + seg * 8;
        cpa16(sb + FQH + soff, Qhb + goff);
        cpa16(sb + FQL + soff, Qlb + goff);
    }
    asm volatile("cp.async.commit_group;" ::: "memory");

    flash_load_kv(sb, 0, 0, tid, Khb, Klb, Vb);
    asm volatile("cp.async.wait_group 0;" ::: "memory");
    __syncthreads();

    uint32_t qhf[4][4], qlf[4][4];
#pragma unroll
    for (int t = 0; t < 4; t++) {
        int rowA = wid * 16 + a_row_off;
        uint32_t off = SMEM_SWIZZLE_128B((uint32_t)(rowA * 128 + t * 32 + a_ks_off));
        ldsm4(qhf[t][0], qhf[t][1], qhf[t][2], qhf[t][3], sb + FQH + off);
        ldsm4(qlf[t][0], qlf[t][1], qlf[t][2], qlf[t][3], sb + FQL + off);
    }

    float mi0 = -INFINITY, mi1 = -INFINITY, li0 = 0.f, li1 = 0.f;
    float o[8][4];
#pragma unroll
    for (int j = 0; j < 8; j++)
#pragma unroll
        for (int r = 0; r < 4; r++) o[j][r] = 0.f;

    const int wrow = qt * 128 + wid * 16;
    const int ktmax = 2 * qt + 1;

    for (int kt = 0; kt <= ktmax; kt++) {
        int s = kt & 1;
        if (kt < ktmax) {
            flash_load_kv(sb, s ^ 1, kt + 1, tid, Khb, Klb, Vb);
            asm volatile("cp.async.wait_group 1;" ::: "memory");
        } else {
            asm volatile("cp.async.wait_group 0;" ::: "memory");
        }
        __syncthreads();

        if (kt * 64 <= wrow + 15) {
            uint32_t st = sb + FST + s * FSTAGE;
            float sc[8][4];
#pragma unroll
            for (int j = 0; j < 8; j++)
#pragma unroll
                for (int r = 0; r < 4; r++) sc[j][r] = 0.f;

#pragma unroll
            for (int t = 0; t < 4; t++) {
#pragma unroll
                for (int p = 0; p < 4; p++) {
                    uint32_t kh4[4], kl4[4];
                    int rowB = p * 16 + b_row_off;
                    uint32_t off = SMEM_SWIZZLE_128B((uint32_t)(rowB * 128 + t * 32 + b_ks_off));
                    ldsm4(kh4[0], kh4[1], kh4[2], kh4[3], st + FKH + off);
                    ldsm4(kl4[0], kl4[1], kl4[2], kl4[3], st + FKL + off);
#pragma unroll
                    for (int q = 0; q < 2; q++) {
                        float* d = sc[2 * p + q];
                        mma_bf16(d, qhf[t], kh4[q * 2], kh4[q * 2 + 1]);
                        mma_bf16(d, qhf[t], kl4[q * 2], kl4[q * 2 + 1]);
                        mma_bf16(d, qlf[t], kh4[q * 2], kh4[q * 2 + 1]);
                    }
                }
            }

            const float scale = 0.125f;
            const int row0 = wrow + g, row1 = row0 + 8;
            const bool diag = (kt * 64 + 63 > wrow);
#pragma unroll
            for (int j = 0; j < 8; j++) {
                int col0 = kt * 64 + j * 8 + 2 * c, col1 = col0 + 1;
                sc[j][0] *= scale; sc[j][1] *= scale;
                sc[j][2] *= scale; sc[j][3] *= scale;
                if (diag) {
                    if (col0 > row0) sc[j][0] = -INFINITY;
                    if (col1 > row0) sc[j][1] = -INFINITY;
                    if (col0 > row1) sc[j][2] = -INFINITY;
                    if (col1 > row1) sc[j][3] = -INFINITY;
                }
            }
            float rm0 = -INFINITY, rm1 = -INFINITY;
#pragma unroll
            for (int j = 0; j < 8; j++) {
                rm0 = fmaxf(rm0, fmaxf(sc[j][0], sc[j][1]));
                rm1 = fmaxf(rm1, fmaxf(sc[j][2], sc[j][3]));
            }
            rm0 = fmaxf(rm0, __shfl_xor_sync(0xffffffffu, rm0, 1));
            rm0 = fmaxf(rm0, __shfl_xor_sync(0xffffffffu, rm0, 2));
            rm1 = fmaxf(rm1, __shfl_xor_sync(0xffffffffu, rm1, 1));
            rm1 = fmaxf(rm1, __shfl_xor_sync(0xffffffffu, rm1, 2));

            float mn0 = fmaxf(mi0, rm0), mn1 = fmaxf(mi1, rm1);
            float al0 = __expf(mi0 - mn0), al1 = __expf(mi1 - mn1);
            float rs0 = 0.f, rs1 = 0.f;
#pragma unroll
            for (int j = 0; j < 8; j++) {
                sc[j][0] = __expf(sc[j][0] - mn0);
                sc[j][1] = __expf(sc[j][1] - mn0);
                sc[j][2] = __expf(sc[j][2] - mn1);
                sc[j][3] = __expf(sc[j][3] - mn1);
                rs0 += sc[j][0] + sc[j][1];
                rs1 += sc[j][2] + sc[j][3];
            }
            rs0 += __shfl_xor_sync(0xffffffffu, rs0, 1);
            rs0 += __shfl_xor_sync(0xffffffffu, rs0, 2);
            rs1 += __shfl_xor_sync(0xffffffffu, rs1, 1);
            rs1 += __shfl_xor_sync(0xffffffffu, rs1, 2);
            li0 = li0 * al0 + rs0; li1 = li1 * al1 + rs1;
            mi0 = mn0; mi1 = mn1;
#pragma unroll
            for (int j = 0; j < 8; j++) {
                o[j][0] *= al0; o[j][1] *= al0;
                o[j][2] *= al1; o[j][3] *= al1;
            }

            uint32_t ph[4][4];
#pragma unroll
            for (int t = 0; t < 4; t++) {
                ph[t][0] = pack_h2(sc[2 * t][0],     sc[2 * t][1]);
                ph[t][1] = pack_h2(sc[2 * t][2],     sc[2 * t][3]);
                ph[t][2] = pack_h2(sc[2 * t + 1][0], sc[2 * t + 1][1]);
                ph[t][3] = pack_h2(sc[2 * t + 1][2], sc[2 * t + 1][3]);
            }

#pragma unroll
            for (int t = 0; t < 4; t++) {
#pragma unroll
                for (int jp = 0; jp < 4; jp++) {
                    uint32_t soff = SMEM_SWIZZLE_128B(
                        (uint32_t)((16 * t + v_half * 8 + v_l) * 128 + jp * 32 + v_quad * 16));
                    uint32_t v4[4];
                    ldsm4t(v4[0], v4[1], v4[2], v4[3], st + FV16 + soff);
                    mma_fp16(o[2 * jp],     ph[t], v4[0], v4[1]);
                    mma_fp16(o[2 * jp + 1], ph[t], v4[2], v4[3]);
                }
            }
        }
        __syncthreads();
    }

    // epilogue: normalize + fp16, feeds output projection directly
    float iv0 = 1.f / li0, iv1 = 1.f / li1;
    size_t r0off = ((size_t)(b * S_ + wrow + g)) * D_ + h * HD_;
    size_t r1off = r0off + 8 * D_;
#pragma unroll
    for (int j = 0; j < 8; j++) {
        int col = j * 8 + 2 * c;
        *(uint32_t*)(O_g + r0off + col) = pack_h2(o[j][0] * iv0, o[j][1] * iv0);
        *(uint32_t*)(O_g + r1off + col) = pack_h2(o[j][2] * iv1, o[j][3] * iv1);
    }
}

// ---------------------------------------------------------------------------
extern "C" void kernel_launch(void* const* d_in, const int* in_sizes, int n_in,
                              void* d_out, int out_size)
{
    const float* Q  = (const float*)d_in[0];
    const float* K  = (const float*)d_in[1];
    const float* V  = (const float*)d_in[2];
    const float* Wq = (const float*)d_in[3];
    const float* bq = (const float*)d_in[4];
    const float* Wk = (const float*)d_in[5];
    const float* bk = (const float*)d_in[6];
    const float* Wv = (const float*)d_in[7];
    const float* bv = (const float*)d_in[8];
    const float* Wo = (const float*)d_in[9];
    const float* bo = (const float*)d_in[10];
    float* out = (float*)d_out;

    float *gq, *gk;
    float2* grope;
    __half *gx16, *gw16, *gv16, *go16;
    __nv_bfloat16 *gqh, *gql, *gkh, *gkl;
    cudaGetSymbolAddress((void**)&gq, g_q);
    cudaGetSymbolAddress((void**)&gk, g_k);
    cudaGetSymbolAddress((void**)&grope, g_rope);
    cudaGetSymbolAddress((void**)&gx16, g_x16);
    cudaGetSymbolAddress((void**)&gw16, g_w16);
    cudaGetSymbolAddress((void**)&gv16, g_v16);
    cudaGetSymbolAddress((void**)&go16, g_o16);
    cudaGetSymbolAddress((void**)&gqh, g_qh);
    cudaGetSymbolAddress((void**)&gql, g_ql);
    cudaGetSymbolAddress((void**)&gkh, g_kh);
    cudaGetSymbolAddress((void**)&gkl, g_kl);

    cudaFuncSetAttribute(gemm_mma16<0>, cudaFuncAttributeMaxDynamicSharedMemorySize, GEMM_SMEM);
    cudaFuncSetAttribute(gemm_mma16<2>, cudaFuncAttributeMaxDynamicSharedMemorySize, GEMM_SMEM);
    cudaFuncSetAttribute(flash_mma, cudaFuncAttributeMaxDynamicSharedMemorySize, FLASH_SMEM);

    const int n4x = NTOT / 4;
    const int n4w = (D_ * D_) / 4;
    dim3 ggrid(D_ / 128, M_ / 128);

    rope_table_kernel<<<(S_ * 32 + 255) / 256, 256>>>(grope);

    // Q projection -> fp32 (rope needs fp32 rows)
    cvt16_kernel<<<(n4x + 255) / 256, 256>>>(Q, gx16, n4x);
    cvt16_kernel<<<(n4w + 255) / 256, 256>>>(Wq, gw16, n4w);
    gemm_mma16<0><<<ggrid, 256, GEMM_SMEM>>>(gx16, gw16, bq, gq, nullptr);

    // K projection -> fp32
    cvt16_kernel<<<(n4x + 255) / 256, 256>>>(K, gx16, n4x);
    cvt16_kernel<<<(n4w + 255) / 256, 256>>>(Wk, gw16, n4w);
    gemm_mma16<0><<<ggrid, 256, GEMM_SMEM>>>(gx16, gw16, bk, gk, nullptr);

    // V projection -> fp16 out
    cvt16_kernel<<<(n4x + 255) / 256, 256>>>(V, gx16, n4x);
    cvt16_kernel<<<(n4w + 255) / 256, 256>>>(Wv, gw16, n4w);
    gemm_mma16<2><<<ggrid, 256, GEMM_SMEM>>>(gx16, gw16, bv, nullptr, gv16);

    // RoPE + split Q,K (bf16 hi/lo for flash QK)
    int items = 2 * B_ * S_ * H_ * 8;
    rope_split_kernel<<<(items + 255) / 256, 256>>>(gq, gk, grope, gqh, gql, gkh, gkl);

    // Flash -> fp16 output (feeds output projection directly)
    dim3 fgrid(S_ / 128, H_, B_);
    flash_mma<<<fgrid, 256, FLASH_SMEM>>>(gqh, gql, gkh, gkl, gv16, go16);

    // Output projection
    cvt16_kernel<<<(n4w + 255) / 256, 256>>>(Wo, gw16, n4w);
    gemm_mma16<0><<<ggrid, 256, GEMM_SMEM>>>(go16, gw16, bo, out, nullptr);
}

// round 10
// speedup vs baseline: 2.5260x; 1.2412x over previous
#include <cuda_runtime.h>
#include <cuda_fp16.h>
#include <math.h>
#include <stdint.h>

#define B_  4
#define S_  2048
#define D_  1024
#define H_  16
#define HD_ 64
#define M_  (B_ * S_)
#define NTOT (B_ * S_ * D_)

// Scratch (allocation-free rule: __device__ globals)
__device__ __half g_x16[NTOT];
__device__ __half g_w16[D_ * D_];
__device__ __half g_q16[NTOT];
__device__ __half g_k16[NTOT];
__device__ __half g_v16[NTOT];
__device__ __half g_o16[NTOT];
__device__ float2 g_rope[S_ * 32];

// ===========================================================================
// Helpers (baseline PTX only — compute_103-safe)
// ===========================================================================
__device__ __forceinline__ uint32_t smem_to_u32(const void* p) {
    uint32_t a;
    asm("{ .reg .u64 t; cvta.to.shared.u64 t, %1; cvt.u32.u64 %0, t; }" : "=r"(a) : "l"(p));
    return a;
}
#define SMEM_SWIZZLE_128B(off) ((off) ^ (((off) >> 3) & 0x70))

__device__ __forceinline__ void cpa16(uint32_t dst, const void* src) {
    asm volatile("cp.async.cg.shared.global [%0], [%1], 16;" :: "r"(dst), "l"(src));
}
__device__ __forceinline__ void ldsm4(uint32_t& r0, uint32_t& r1, uint32_t& r2, uint32_t& r3,
                                      uint32_t addr) {
    asm volatile("ldmatrix.sync.aligned.m8n8.x4.shared.b16 {%0,%1,%2,%3}, [%4];"
        : "=r"(r0), "=r"(r1), "=r"(r2), "=r"(r3) : "r"(addr));
}
__device__ __forceinline__ void ldsm4t(uint32_t& r0, uint32_t& r1, uint32_t& r2, uint32_t& r3,
                                       uint32_t addr) {
    asm volatile("ldmatrix.sync.aligned.m8n8.x4.trans.shared.b16 {%0,%1,%2,%3}, [%4];"
        : "=r"(r0), "=r"(r1), "=r"(r2), "=r"(r3) : "r"(addr));
}
__device__ __forceinline__ void mma_fp16(float* d, const uint32_t* a,
                                         uint32_t b0, uint32_t b1) {
    asm volatile(
        "mma.sync.aligned.m16n8k16.row.col.f32.f16.f16.f32 "
        "{%0,%1,%2,%3}, {%4,%5,%6,%7}, {%8,%9}, {%0,%1,%2,%3};"
        : "+f"(d[0]), "+f"(d[1]), "+f"(d[2]), "+f"(d[3])
        : "r"(a[0]), "r"(a[1]), "r"(a[2]), "r"(a[3]), "r"(b0), "r"(b1));
}
__device__ __forceinline__ uint32_t pack_h2(float f0, float f1) {
    __half2 h = __floats2half2_rn(f0, f1);
    return *(uint32_t*)&h;
}

// ===========================================================================
// fp32 -> fp16 convert (vectorized)
// ===========================================================================
__global__ __launch_bounds__(256)
void cvt16_kernel(const float* __restrict__ x, __half* __restrict__ o, int n4)
{
    int i = blockIdx.x * blockDim.x + threadIdx.x;
    if (i >= n4) return;
    float4 v = ((const float4*)x)[i];
    ((uint32_t*)o)[2 * i + 0] = pack_h2(v.x, v.y);
    ((uint32_t*)o)[2 * i + 1] = pack_h2(v.z, v.w);
}

// ===========================================================================
// Single-fp16 GEMM: C[M,N] = A[M,K] @ W[N,K]^T + bias. 128x128 tile, BK=64,
// 3-stage cp.async, 2 CTAs/SM. OUTMODE: 0 = fp32 out, 2 = fp16 out.
// ===========================================================================
#define TILE_BYTES 16384                   // 128 rows x 128 B (128x64 fp16)
#define STAGE_BYTES (2 * TILE_BYTES)       // 32 KB (A + B)
#define GEMM_SMEM (3 * STAGE_BYTES)        // 96 KB -> 2 CTAs/SM
#define NCHUNK (D_ / 64)                   // 16

__device__ __forceinline__ void gemm_load_chunk(
    uint32_t sb, int stage, int k0, int tid,
    const __half* Ab, const __half* Bb)
{
    uint32_t base = sb + stage * STAGE_BYTES;
#pragma unroll
    for (int rep = 0; rep < 4; rep++) {
        int id  = tid + rep * 256;
        int row = id >> 3;
        int seg = id & 7;
        uint32_t soff = SMEM_SWIZZLE_128B((uint32_t)(row * 128 + seg * 16));
        size_t goff = (size_t)row * D_ + k0 + seg * 8;
        cpa16(base + 0 * TILE_BYTES + soff, Ab + goff);
        cpa16(base + 1 * TILE_BYTES + soff, Bb + goff);
    }
    asm volatile("cp.async.commit_group;" ::: "memory");
}

template <int OUTMODE>
__global__ __launch_bounds__(256, 2)
void gemm_mma16(const __half* __restrict__ A, const __half* __restrict__ W,
                const float* __restrict__ bias, float* __restrict__ C,
                __half* __restrict__ C16)
{
    extern __shared__ char smem[];
    uint32_t sb = smem_to_u32(smem);
    const int tid  = threadIdx.x;
    const int wid  = tid >> 5;
    const int lane = tid & 31;
    const int warp_m = wid >> 2;
    const int warp_n = wid & 3;
    const int bn = blockIdx.x, bm = blockIdx.y;

    const __half* Ab = A + (size_t)(bm * 128) * D_;
    const __half* Bb = W + (size_t)(bn * 128) * D_;

    float acc[4][4][4];
#pragma unroll
    for (int i = 0; i < 4; i++)
#pragma unroll
        for (int j = 0; j < 4; j++)
#pragma unroll
            for (int r = 0; r < 4; r++) acc[i][j][r] = 0.f;

    const int mat = lane >> 3;
    const int mrr = lane & 7;
    const int a_row_off = (mat & 1) * 8 + mrr;
    const int a_ks_off  = (mat >> 1) * 16;
    const int b_row_off = (mat >> 1) * 8 + mrr;
    const int b_ks_off  = (mat & 1) * 16;

    gemm_load_chunk(sb, 0, 0, tid, Ab, Bb);
    gemm_load_chunk(sb, 1, 64, tid, Ab, Bb);

    int stage = 0;
    for (int c = 0; c < NCHUNK; c++) {
        if (c + 2 < NCHUNK) {
            int ls = stage + 2; if (ls >= 3) ls -= 3;
            gemm_load_chunk(sb, ls, (c + 2) * 64, tid, Ab, Bb);
            asm volatile("cp.async.wait_group 2;" ::: "memory");
        } else if (c + 1 < NCHUNK) {
            asm volatile("cp.async.wait_group 1;" ::: "memory");
        } else {
            asm volatile("cp.async.wait_group 0;" ::: "memory");
        }
        __syncthreads();

        uint32_t stA = sb + stage * STAGE_BYTES;
#pragma unroll
        for (int ks = 0; ks < 4; ks++) {
            const int kb = ks * 32;
            uint32_t ah[4][4];
#pragma unroll
            for (int mt = 0; mt < 4; mt++) {
                int row = warp_m * 64 + mt * 16 + a_row_off;
                uint32_t off = SMEM_SWIZZLE_128B((uint32_t)(row * 128 + kb + a_ks_off));
                ldsm4(ah[mt][0], ah[mt][1], ah[mt][2], ah[mt][3], stA + 0 * TILE_BYTES + off);
            }
            uint32_t bh[2][4];
#pragma unroll
            for (int p = 0; p < 2; p++) {
                int row = warp_n * 32 + p * 16 + b_row_off;
                uint32_t off = SMEM_SWIZZLE_128B((uint32_t)(row * 128 + kb + b_ks_off));
                ldsm4(bh[p][0], bh[p][1], bh[p][2], bh[p][3], stA + 1 * TILE_BYTES + off);
            }
#pragma unroll
            for (int mt = 0; mt < 4; mt++) {
#pragma unroll
                for (int p = 0; p < 2; p++) {
#pragma unroll
                    for (int q = 0; q < 2; q++) {
                        mma_fp16(acc[mt][p * 2 + q], ah[mt], bh[p][q * 2], bh[p][q * 2 + 1]);
                    }
                }
            }
        }
        __syncthreads();
        stage++; if (stage >= 3) stage = 0;
    }

    const int rbase = bm * 128 + warp_m * 64 + (lane >> 2);
    const int cbase = bn * 128 + warp_n * 32 + (lane & 3) * 2;
#pragma unroll
    for (int mt = 0; mt < 4; mt++) {
#pragma unroll
        for (int nt = 0; nt < 4; nt++) {
            int col = cbase + nt * 8;
            float b0 = bias[col], b1 = bias[col + 1];
            float* d = acc[mt][nt];
            int r0 = rbase + mt * 16;
            float v00 = d[0] + b0, v01 = d[1] + b1;
            float v10 = d[2] + b0, v11 = d[3] + b1;
            if (OUTMODE == 2) {
                *(uint32_t*)(C16 + (size_t)r0 * D_ + col)       = pack_h2(v00, v01);
                *(uint32_t*)(C16 + (size_t)(r0 + 8) * D_ + col) = pack_h2(v10, v11);
            } else {
                *(float2*)(C + (size_t)r0 * D_ + col)       = make_float2(v00, v01);
                *(float2*)(C + (size_t)(r0 + 8) * D_ + col) = make_float2(v10, v11);
            }
        }
    }
}

// ---------------------------------------------------------------------------
// RoPE table (fp64 for exactness)
// ---------------------------------------------------------------------------
__global__ void rope_table_kernel(float2* __restrict__ tab)
{
    int idx = blockIdx.x * blockDim.x + threadIdx.x;
    if (idx >= S_ * 32) return;
    int s = idx >> 5;
    int d = idx & 31;
    double inv = exp(-log(10000.0) * (double)d / 32.0);
    double ang = (double)s * inv;
    double sd, cd;
    sincos(ang, &sd, &cd);
    tab[idx] = make_float2((float)cd, (float)sd);
}

// ---------------------------------------------------------------------------
// RoPE on fp16, in place (Q and K in one launch). Math in fp32.
// Each thread: 4 consecutive d of one (bs, h) row at d and d+32.
// ---------------------------------------------------------------------------
__global__ __launch_bounds__(256)
void rope16_kernel(__half* __restrict__ q, __half* __restrict__ k,
                   const float2* __restrict__ tab)
{
    const int half = B_ * S_ * H_ * 8;
    int idx = blockIdx.x * blockDim.x + threadIdx.x;
    if (idx >= 2 * half) return;
    __half* x = (idx < half) ? q : k;
    int i = (idx < half) ? idx : idx - half;

    int dv = (i & 7) << 2;
    int h  = (i >> 3) & (H_ - 1);
    int bs = i >> 7;
    int s  = bs & (S_ - 1);

    __half* p = x + (size_t)bs * D_ + h * HD_ + dv;
    __half2 a01 = *(__half2*)p,        a23 = *(__half2*)(p + 2);
    __half2 b01 = *(__half2*)(p + 32), b23 = *(__half2*)(p + 34);
    float2 a0 = __half22float2(a01), a1 = __half22float2(a23);
    float2 b0 = __half22float2(b01), b1 = __half22float2(b23);
    const float2* t = tab + s * 32 + dv;
    float2 t0 = t[0], t1 = t[1], t2 = t[2], t3 = t[3];

    float rx0 = fmaf(a0.x, t0.x, -b0.x * t0.y), ry0 = fmaf(a0.x, t0.y, b0.x * t0.x);
    float rx1 = fmaf(a0.y, t1.x, -b0.y * t1.y), ry1 = fmaf(a0.y, t1.y, b0.y * t1.x);
    float rx2 = fmaf(a1.x, t2.x, -b1.x * t2.y), ry2 = fmaf(a1.x, t2.y, b1.x * t2.x);
    float rx3 = fmaf(a1.y, t3.x, -b1.y * t3.y), ry3 = fmaf(a1.y, t3.y, b1.y * t3.x);

    *(uint32_t*)p        = pack_h2(rx0, rx1);
    *(uint32_t*)(p + 2)  = pack_h2(rx2, rx3);
    *(uint32_t*)(p + 32) = pack_h2(ry0, ry1);
    *(uint32_t*)(p + 34) = pack_h2(ry2, ry3);
}

// ===========================================================================
// Tensor-core flash attention, all-fp16 MMA. BM=128, BN=64.
// QK: fp16 single. PV: fp16 single. Output: fp16.
// ===========================================================================
#define FQ 0
#define FST 16384
#define FK 0
#define FV 8192
#define FSTAGE 16384
#define FLASH_SMEM (16384 + 2 * FSTAGE)   // 49152

__device__ __forceinline__ void flash_load_kv(
    uint32_t sb, int stage, int kt, int tid,
    const __half* Kb, const __half* Vb)
{
    uint32_t base = sb + FST + stage * FSTAGE;
    size_t rbase = (size_t)(kt * 64) * D_;
#pragma unroll
    for (int rep = 0; rep < 2; rep++) {
        int id  = tid + rep * 256;
        int row = id >> 3;
        int seg = id & 7;
        uint32_t soff = SMEM_SWIZZLE_128B((uint32_t)(row * 128 + seg * 16));
        size_t goff = rbase + (size_t)row * D_ + seg * 8;
        cpa16(base + FK + soff, Kb + goff);
        cpa16(base + FV + soff, Vb + goff);
    }
    asm volatile("cp.async.commit_group;" ::: "memory");
}

__global__ __launch_bounds__(256, 2)
void flash_mma(const __half* __restrict__ Q_g, const __half* __restrict__ K_g,
               const __half* __restrict__ V_g, __half* __restrict__ O_g)
{
    extern __shared__ char smem[];
    uint32_t sb = smem_to_u32(smem);
    const int tid  = threadIdx.x;
    const int wid  = tid >> 5;
    const int lane = tid & 31;
    const int qt = blockIdx.x, h = blockIdx.y, b = blockIdx.z;

    const int g = lane >> 2, c = lane & 3;
    const int mat = lane >> 3, mrr = lane & 7;
    const int a_row_off = (mat & 1) * 8 + mrr;
    const int a_ks_off  = (mat >> 1) * 16;
    const int b_row_off = (mat >> 1) * 8 + mrr;
    const int b_ks_off  = (mat & 1) * 16;
    const int v_l = lane & 7, v_half = (lane >> 3) & 1, v_quad = lane >> 4;

    const size_t hoff = (size_t)(b * S_) * D_ + h * HD_;
    const __half* Qb = Q_g + hoff + (size_t)(qt * 128) * D_;
    const __half* Kb = K_g + hoff;
    const __half* Vb = V_g + hoff;

    // Q tile: 128 rows x 128 B (fp16)
#pragma unroll
    for (int rep = 0; rep < 4; rep++) {
        int id  = tid + rep * 256;
        int row = id >> 3;
        int seg = id & 7;
        uint32_t soff = SMEM_SWIZZLE_128B((uint32_t)(row * 128 + seg * 16));
        size_t goff = (size_t)row * D_ + seg * 8;
        cpa16(sb + FQ + soff, Qb + goff);
    }
    asm volatile("cp.async.commit_group;" ::: "memory");

    flash_load_kv(sb, 0, 0, tid, Kb, Vb);
    asm volatile("cp.async.wait_group 0;" ::: "memory");
    __syncthreads();

    uint32_t qf[4][4];
#pragma unroll
    for (int t = 0; t < 4; t++) {
        int rowA = wid * 16 + a_row_off;
        uint32_t off = SMEM_SWIZZLE_128B((uint32_t)(rowA * 128 + t * 32 + a_ks_off));
        ldsm4(qf[t][0], qf[t][1], qf[t][2], qf[t][3], sb + FQ + off);
    }

    float mi0 = -INFINITY, mi1 = -INFINITY, li0 = 0.f, li1 = 0.f;
    float o[8][4];
#pragma unroll
    for (int j = 0; j < 8; j++)
#pragma unroll
        for (int r = 0; r < 4; r++) o[j][r] = 0.f;

    const int wrow = qt * 128 + wid * 16;
    const int ktmax = 2 * qt + 1;

    for (int kt = 0; kt <= ktmax; kt++) {
        int s = kt & 1;
        if (kt < ktmax) {
            flash_load_kv(sb, s ^ 1, kt + 1, tid, Kb, Vb);
            asm volatile("cp.async.wait_group 1;" ::: "memory");
        } else {
            asm volatile("cp.async.wait_group 0;" ::: "memory");
        }
        __syncthreads();

        if (kt * 64 <= wrow + 15) {
            uint32_t st = sb + FST + s * FSTAGE;
            float sc[8][4];
#pragma unroll
            for (int j = 0; j < 8; j++)
#pragma unroll
                for (int r = 0; r < 4; r++) sc[j][r] = 0.f;

            // S = Q K^T (single fp16)
#pragma unroll
            for (int t = 0; t < 4; t++) {
#pragma unroll
                for (int p = 0; p < 4; p++) {
                    uint32_t k4[4];
                    int rowB = p * 16 + b_row_off;
                    uint32_t off = SMEM_SWIZZLE_128B((uint32_t)(rowB * 128 + t * 32 + b_ks_off));
                    ldsm4(k4[0], k4[1], k4[2], k4[3], st + FK + off);
                    mma_fp16(sc[2 * p],     qf[t], k4[0], k4[1]);
                    mma_fp16(sc[2 * p + 1], qf[t], k4[2], k4[3]);
                }
            }

            const float scale = 0.125f;
            const int row0 = wrow + g, row1 = row0 + 8;
            const bool diag = (kt * 64 + 63 > wrow);
#pragma unroll
            for (int j = 0; j < 8; j++) {
                int col0 = kt * 64 + j * 8 + 2 * c, col1 = col0 + 1;
                sc[j][0] *= scale; sc[j][1] *= scale;
                sc[j][2] *= scale; sc[j][3] *= scale;
                if (diag) {
                    if (col0 > row0) sc[j][0] = -INFINITY;
                    if (col1 > row0) sc[j][1] = -INFINITY;
                    if (col0 > row1) sc[j][2] = -INFINITY;
                    if (col1 > row1) sc[j][3] = -INFINITY;
                }
            }
            float rm0 = -INFINITY, rm1 = -INFINITY;
#pragma unroll
            for (int j = 0; j < 8; j++) {
                rm0 = fmaxf(rm0, fmaxf(sc[j][0], sc[j][1]));
                rm1 = fmaxf(rm1, fmaxf(sc[j][2], sc[j][3]));
            }
            rm0 = fmaxf(rm0, __shfl_xor_sync(0xffffffffu, rm0, 1));
            rm0 = fmaxf(rm0, __shfl_xor_sync(0xffffffffu, rm0, 2));
            rm1 = fmaxf(rm1, __shfl_xor_sync(0xffffffffu, rm1, 1));
            rm1 = fmaxf(rm1, __shfl_xor_sync(0xffffffffu, rm1, 2));

            float mn0 = fmaxf(mi0, rm0), mn1 = fmaxf(mi1, rm1);
            float al0 = __expf(mi0 - mn0), al1 = __expf(mi1 - mn1);
            float rs0 = 0.f, rs1 = 0.f;
#pragma unroll
            for (int j = 0; j < 8; j++) {
                sc[j][0] = __expf(sc[j][0] - mn0);
                sc[j][1] = __expf(sc[j][1] - mn0);
                sc[j][2] = __expf(sc[j][2] - mn1);
                sc[j][3] = __expf(sc[j][3] - mn1);
                rs0 += sc[j][0] + sc[j][1];
                rs1 += sc[j][2] + sc[j][3];
            }
            rs0 += __shfl_xor_sync(0xffffffffu, rs0, 1);
            rs0 += __shfl_xor_sync(0xffffffffu, rs0, 2);
            rs1 += __shfl_xor_sync(0xffffffffu, rs1, 1);
            rs1 += __shfl_xor_sync(0xffffffffu, rs1, 2);
            li0 = li0 * al0 + rs0; li1 = li1 * al1 + rs1;
            mi0 = mn0; mi1 = mn1;
#pragma unroll
            for (int j = 0; j < 8; j++) {
                o[j][0] *= al0; o[j][1] *= al0;
                o[j][2] *= al1; o[j][3] *= al1;
            }

            uint32_t ph[4][4];
#pragma unroll
            for (int t = 0; t < 4; t++) {
                ph[t][0] = pack_h2(sc[2 * t][0],     sc[2 * t][1]);
                ph[t][1] = pack_h2(sc[2 * t][2],     sc[2 * t][3]);
                ph[t][2] = pack_h2(sc[2 * t + 1][0], sc[2 * t + 1][1]);
                ph[t][3] = pack_h2(sc[2 * t + 1][2], sc[2 * t + 1][3]);
            }

#pragma unroll
            for (int t = 0; t < 4; t++) {
#pragma unroll
                for (int jp = 0; jp < 4; jp++) {
                    uint32_t soff = SMEM_SWIZZLE_128B(
                        (uint32_t)((16 * t + v_half * 8 + v_l) * 128 + jp * 32 + v_quad * 16));
                    uint32_t v4[4];
                    ldsm4t(v4[0], v4[1], v4[2], v4[3], st + FV + soff);
                    mma_fp16(o[2 * jp],     ph[t], v4[0], v4[1]);
                    mma_fp16(o[2 * jp + 1], ph[t], v4[2], v4[3]);
                }
            }
        }
        __syncthreads();
    }

    // epilogue: normalize + fp16, feeds output projection directly
    float iv0 = 1.f / li0, iv1 = 1.f / li1;
    size_t r0off = ((size_t)(b * S_ + wrow + g)) * D_ + h * HD_;
    size_t r1off = r0off + 8 * D_;
#pragma unroll
    for (int j = 0; j < 8; j++) {
        int col = j * 8 + 2 * c;
        *(uint32_t*)(O_g + r0off + col) = pack_h2(o[j][0] * iv0, o[j][1] * iv0);
        *(uint32_t*)(O_g + r1off + col) = pack_h2(o[j][2] * iv1, o[j][3] * iv1);
    }
}

// ---------------------------------------------------------------------------
extern "C" void kernel_launch(void* const* d_in, const int* in_sizes, int n_in,
                              void* d_out, int out_size)
{
    const float* Q  = (const float*)d_in[0];
    const float* K  = (const float*)d_in[1];
    const float* V  = (const float*)d_in[2];
    const float* Wq = (const float*)d_in[3];
    const float* bq = (const float*)d_in[4];
    const float* Wk = (const float*)d_in[5];
    const float* bk = (const float*)d_in[6];
    const float* Wv = (const float*)d_in[7];
    const float* bv = (const float*)d_in[8];
    const float* Wo = (const float*)d_in[9];
    const float* bo = (const float*)d_in[10];
    float* out = (float*)d_out;

    float2* grope;
    __half *gx16, *gw16, *gq16, *gk16, *gv16, *go16;
    cudaGetSymbolAddress((void**)&grope, g_rope);
    cudaGetSymbolAddress((void**)&gx16, g_x16);
    cudaGetSymbolAddress((void**)&gw16, g_w16);
    cudaGetSymbolAddress((void**)&gq16, g_q16);
    cudaGetSymbolAddress((void**)&gk16, g_k16);
    cudaGetSymbolAddress((void**)&gv16, g_v16);
    cudaGetSymbolAddress((void**)&go16, g_o16);

    cudaFuncSetAttribute(gemm_mma16<0>, cudaFuncAttributeMaxDynamicSharedMemorySize, GEMM_SMEM);
    cudaFuncSetAttribute(gemm_mma16<2>, cudaFuncAttributeMaxDynamicSharedMemorySize, GEMM_SMEM);
    cudaFuncSetAttribute(flash_mma, cudaFuncAttributeMaxDynamicSharedMemorySize, FLASH_SMEM);

    const int n4x = NTOT / 4;
    const int n4w = (D_ * D_) / 4;
    dim3 ggrid(D_ / 128, M_ / 128);

    rope_table_kernel<<<(S_ * 32 + 255) / 256, 256>>>(grope);

    // Q projection -> fp16
    cvt16_kernel<<<(n4x + 255) / 256, 256>>>(Q, gx16, n4x);
    cvt16_kernel<<<(n4w + 255) / 256, 256>>>(Wq, gw16, n4w);
    gemm_mma16<2><<<ggrid, 256, GEMM_SMEM>>>(gx16, gw16, bq, nullptr, gq16);

    // K projection -> fp16
    cvt16_kernel<<<(n4x + 255) / 256, 256>>>(K, gx16, n4x);
    cvt16_kernel<<<(n4w + 255) / 256, 256>>>(Wk, gw16, n4w);
    gemm_mma16<2><<<ggrid, 256, GEMM_SMEM>>>(gx16, gw16, bk, nullptr, gk16);

    // V projection -> fp16
    cvt16_kernel<<<(n4x + 255) / 256, 256>>>(V, gx16, n4x);
    cvt16_kernel<<<(n4w + 255) / 256, 256>>>(Wv, gw16, n4w);
    gemm_mma16<2><<<ggrid, 256, GEMM_SMEM>>>(gx16, gw16, bv, nullptr, gv16);

    // RoPE in place on fp16 Q, K
    int items = 2 * B_ * S_ * H_ * 8;
    rope16_kernel<<<(items + 255) / 256, 256>>>(gq16, gk16, grope);

    // Flash (all fp16 MMA) -> fp16 output
    dim3 fgrid(S_ / 128, H_, B_);
    flash_mma<<<fgrid, 256, FLASH_SMEM>>>(gq16, gk16, gv16, go16);

    // Output projection -> fp32 final
    cvt16_kernel<<<(n4w + 255) / 256, 256>>>(Wo, gw16, n4w);
    gemm_mma16<0><<<ggrid, 256, GEMM_SMEM>>>(go16, gw16, bo, out, nullptr);
}

// round 11
// speedup vs baseline: 2.6153x; 1.0353x over previous
#include <cuda_runtime.h>
#include <cuda_fp16.h>
#include <math.h>
#include <stdint.h>

#define B_  4
#define S_  2048
#define D_  1024
#define H_  16
#define HD_ 64
#define M_  (B_ * S_)
#define NTOT (B_ * S_ * D_)

// Scratch (allocation-free rule: __device__ globals)
__device__ __half g_x3[3 * NTOT];        // packed Q16, K16, V16 inputs
__device__ __half g_wqkv[3 * D_ * D_];   // packed Wq, Wk, Wv fp16
__device__ __half g_w16[D_ * D_];        // Wo fp16
__device__ __half g_q16[NTOT];
__device__ __half g_k16[NTOT];
__device__ __half g_v16[NTOT];
__device__ __half g_o16[NTOT];
__device__ float2 g_rope[S_ * 32];

// ===========================================================================
// Helpers (baseline PTX only — compute_103-safe)
// ===========================================================================
__device__ __forceinline__ uint32_t smem_to_u32(const void* p) {
    uint32_t a;
    asm("{ .reg .u64 t; cvta.to.shared.u64 t, %1; cvt.u32.u64 %0, t; }" : "=r"(a) : "l"(p));
    return a;
}
#define SMEM_SWIZZLE_128B(off) ((off) ^ (((off) >> 3) & 0x70))

__device__ __forceinline__ void cpa16(uint32_t dst, const void* src) {
    asm volatile("cp.async.cg.shared.global [%0], [%1], 16;" :: "r"(dst), "l"(src));
}
__device__ __forceinline__ void ldsm4(uint32_t& r0, uint32_t& r1, uint32_t& r2, uint32_t& r3,
                                      uint32_t addr) {
    asm volatile("ldmatrix.sync.aligned.m8n8.x4.shared.b16 {%0,%1,%2,%3}, [%4];"
        : "=r"(r0), "=r"(r1), "=r"(r2), "=r"(r3) : "r"(addr));
}
__device__ __forceinline__ void ldsm4t(uint32_t& r0, uint32_t& r1, uint32_t& r2, uint32_t& r3,
                                       uint32_t addr) {
    asm volatile("ldmatrix.sync.aligned.m8n8.x4.trans.shared.b16 {%0,%1,%2,%3}, [%4];"
        : "=r"(r0), "=r"(r1), "=r"(r2), "=r"(r3) : "r"(addr));
}
__device__ __forceinline__ void mma_fp16(float* d, const uint32_t* a,
                                         uint32_t b0, uint32_t b1) {
    asm volatile(
        "mma.sync.aligned.m16n8k16.row.col.f32.f16.f16.f32 "
        "{%0,%1,%2,%3}, {%4,%5,%6,%7}, {%8,%9}, {%0,%1,%2,%3};"
        : "+f"(d[0]), "+f"(d[1]), "+f"(d[2]), "+f"(d[3])
        : "r"(a[0]), "r"(a[1]), "r"(a[2]), "r"(a[3]), "r"(b0), "r"(b1));
}
__device__ __forceinline__ uint32_t pack_h2(float f0, float f1) {
    __half2 h = __floats2half2_rn(f0, f1);
    return *(uint32_t*)&h;
}

// ===========================================================================
// fp32 -> fp16 convert (vectorized)
// ===========================================================================
__global__ __launch_bounds__(256)
void cvt16_kernel(const float* __restrict__ x, __half* __restrict__ o, int n4)
{
    int i = blockIdx.x * blockDim.x + threadIdx.x;
    if (i >= n4) return;
    float4 v = ((const float4*)x)[i];
    ((uint32_t*)o)[2 * i + 0] = pack_h2(v.x, v.y);
    ((uint32_t*)o)[2 * i + 1] = pack_h2(v.z, v.w);
}

// ===========================================================================
// fp16 GEMM building blocks: 128x128 tile, BK=64, 3-stage cp.async, 2 CTA/SM.
// ===========================================================================
#define TILE_BYTES 16384                   // 128 rows x 128 B (128x64 fp16)
#define STAGE_BYTES (2 * TILE_BYTES)       // 32 KB (A + B)
#define GEMM_SMEM (3 * STAGE_BYTES)        // 96 KB -> 2 CTAs/SM
#define NCHUNK (D_ / 64)                   // 16

__device__ __forceinline__ void gemm_load_chunk(
    uint32_t sb, int stage, int k0, int tid,
    const __half* Ab, const __half* Bb)
{
    uint32_t base = sb + stage * STAGE_BYTES;
#pragma unroll
    for (int rep = 0; rep < 4; rep++) {
        int id  = tid + rep * 256;
        int row = id >> 3;
        int seg = id & 7;
        uint32_t soff = SMEM_SWIZZLE_128B((uint32_t)(row * 128 + seg * 16));
        size_t goff = (size_t)row * D_ + k0 + seg * 8;
        cpa16(base + 0 * TILE_BYTES + soff, Ab + goff);
        cpa16(base + 1 * TILE_BYTES + soff, Bb + goff);
    }
    asm volatile("cp.async.commit_group;" ::: "memory");
}

// Mainloop shared by both GEMM kernels; returns with acc filled.
__device__ __forceinline__ void gemm_mainloop(
    uint32_t sb, int tid, const __half* Ab, const __half* Bb,
    int warp_m, int warp_n, int lane, float acc[4][4][4])
{
#pragma unroll
    for (int i = 0; i < 4; i++)
#pragma unroll
        for (int j = 0; j < 4; j++)
#pragma unroll
            for (int r = 0; r < 4; r++) acc[i][j][r] = 0.f;

    const int mat = lane >> 3;
    const int mrr = lane & 7;
    const int a_row_off = (mat & 1) * 8 + mrr;
    const int a_ks_off  = (mat >> 1) * 16;
    const int b_row_off = (mat >> 1) * 8 + mrr;
    const int b_ks_off  = (mat & 1) * 16;

    gemm_load_chunk(sb, 0, 0, tid, Ab, Bb);
    gemm_load_chunk(sb, 1, 64, tid, Ab, Bb);

    int stage = 0;
    for (int c = 0; c < NCHUNK; c++) {
        if (c + 2 < NCHUNK) {
            int ls = stage + 2; if (ls >= 3) ls -= 3;
            gemm_load_chunk(sb, ls, (c + 2) * 64, tid, Ab, Bb);
            asm volatile("cp.async.wait_group 2;" ::: "memory");
        } else if (c + 1 < NCHUNK) {
            asm volatile("cp.async.wait_group 1;" ::: "memory");
        } else {
            asm volatile("cp.async.wait_group 0;" ::: "memory");
        }
        __syncthreads();

        uint32_t stA = sb + stage * STAGE_BYTES;
#pragma unroll
        for (int ks = 0; ks < 4; ks++) {
            const int kb = ks * 32;
            uint32_t ah[4][4];
#pragma unroll
            for (int mt = 0; mt < 4; mt++) {
                int row = warp_m * 64 + mt * 16 + a_row_off;
                uint32_t off = SMEM_SWIZZLE_128B((uint32_t)(row * 128 + kb + a_ks_off));
                ldsm4(ah[mt][0], ah[mt][1], ah[mt][2], ah[mt][3], stA + 0 * TILE_BYTES + off);
            }
            uint32_t bh[2][4];
#pragma unroll
            for (int p = 0; p < 2; p++) {
                int row = warp_n * 32 + p * 16 + b_row_off;
                uint32_t off = SMEM_SWIZZLE_128B((uint32_t)(row * 128 + kb + b_ks_off));
                ldsm4(bh[p][0], bh[p][1], bh[p][2], bh[p][3], stA + 1 * TILE_BYTES + off);
            }
#pragma unroll
            for (int mt = 0; mt < 4; mt++) {
#pragma unroll
                for (int p = 0; p < 2; p++) {
#pragma unroll
                    for (int q = 0; q < 2; q++) {
                        mma_fp16(acc[mt][p * 2 + q], ah[mt], bh[p][q * 2], bh[p][q * 2 + 1]);
                    }
                }
            }
        }
        __syncthreads();
        stage++; if (stage >= 3) stage = 0;
    }
}

// ---------------------------------------------------------------------------
// Fused QKV projection: grid.x = 24 (8 each for Q, K, V outputs), grid.y = 64.
// Per-CTA select of input tensor, weight slice, bias, and output buffer.
// ---------------------------------------------------------------------------
__global__ __launch_bounds__(256, 2)
void gemm_qkv(const __half* __restrict__ X3, const __half* __restrict__ Wqkv,
              const float* __restrict__ bq, const float* __restrict__ bk,
              const float* __restrict__ bv,
              __half* __restrict__ Qo, __half* __restrict__ Ko, __half* __restrict__ Vo)
{
    extern __shared__ char smem[];
    uint32_t sb = smem_to_u32(smem);
    const int tid  = threadIdx.x;
    const int wid  = tid >> 5;
    const int lane = tid & 31;
    const int warp_m = wid >> 2;
    const int warp_n = wid & 3;
    const int bn = blockIdx.x, bm = blockIdx.y;
    const int sel = bn >> 3;          // 0=Q, 1=K, 2=V
    const int bnl = bn & 7;

    const __half* Ab = X3 + (size_t)sel * NTOT + (size_t)(bm * 128) * D_;
    const __half* Bb = Wqkv + (size_t)sel * D_ * D_ + (size_t)(bnl * 128) * D_;
    const float* bias = (sel == 0) ? bq : (sel == 1) ? bk : bv;
    __half* Co = (sel == 0) ? Qo : (sel == 1) ? Ko : Vo;

    float acc[4][4][4];
    gemm_mainloop(sb, tid, Ab, Bb, warp_m, warp_n, lane, acc);

    const int rbase = bm * 128 + warp_m * 64 + (lane >> 2);
    const int cbase = bnl * 128 + warp_n * 32 + (lane & 3) * 2;
#pragma unroll
    for (int mt = 0; mt < 4; mt++) {
#pragma unroll
        for (int nt = 0; nt < 4; nt++) {
            int col = cbase + nt * 8;
            float b0 = bias[col], b1 = bias[col + 1];
            float* d = acc[mt][nt];
            int r0 = rbase + mt * 16;
            *(uint32_t*)(Co + (size_t)r0 * D_ + col)       = pack_h2(d[0] + b0, d[1] + b1);
            *(uint32_t*)(Co + (size_t)(r0 + 8) * D_ + col) = pack_h2(d[2] + b0, d[3] + b1);
        }
    }
}

// ---------------------------------------------------------------------------
// Output projection GEMM: fp16 in, fp32 out.
// ---------------------------------------------------------------------------
__global__ __launch_bounds__(256, 2)
void gemm_out(const __half* __restrict__ A, const __half* __restrict__ W,
              const float* __restrict__ bias, float* __restrict__ C)
{
    extern __shared__ char smem[];
    uint32_t sb = smem_to_u32(smem);
    const int tid  = threadIdx.x;
    const int wid  = tid >> 5;
    const int lane = tid & 31;
    const int warp_m = wid >> 2;
    const int warp_n = wid & 3;
    const int bn = blockIdx.x, bm = blockIdx.y;

    const __half* Ab = A + (size_t)(bm * 128) * D_;
    const __half* Bb = W + (size_t)(bn * 128) * D_;

    float acc[4][4][4];
    gemm_mainloop(sb, tid, Ab, Bb, warp_m, warp_n, lane, acc);

    const int rbase = bm * 128 + warp_m * 64 + (lane >> 2);
    const int cbase = bn * 128 + warp_n * 32 + (lane & 3) * 2;
#pragma unroll
    for (int mt = 0; mt < 4; mt++) {
#pragma unroll
        for (int nt = 0; nt < 4; nt++) {
            int col = cbase + nt * 8;
            float b0 = bias[col], b1 = bias[col + 1];
            float* d = acc[mt][nt];
            int r0 = rbase + mt * 16;
            *(float2*)(C + (size_t)r0 * D_ + col)       = make_float2(d[0] + b0, d[1] + b1);
            *(float2*)(C + (size_t)(r0 + 8) * D_ + col) = make_float2(d[2] + b0, d[3] + b1);
        }
    }
}

// ---------------------------------------------------------------------------
// RoPE table (fp64 for exactness)
// ---------------------------------------------------------------------------
__global__ void rope_table_kernel(float2* __restrict__ tab)
{
    int idx = blockIdx.x * blockDim.x + threadIdx.x;
    if (idx >= S_ * 32) return;
    int s = idx >> 5;
    int d = idx & 31;
    double inv = exp(-log(10000.0) * (double)d / 32.0);
    double ang = (double)s * inv;
    double sd, cd;
    sincos(ang, &sd, &cd);
    tab[idx] = make_float2((float)cd, (float)sd);
}

// ---------------------------------------------------------------------------
// RoPE on fp16, in place (Q and K in one launch). Math in fp32.
// ---------------------------------------------------------------------------
__global__ __launch_bounds__(256)
void rope16_kernel(__half* __restrict__ q, __half* __restrict__ k,
                   const float2* __restrict__ tab)
{
    const int half = B_ * S_ * H_ * 8;
    int idx = blockIdx.x * blockDim.x + threadIdx.x;
    if (idx >= 2 * half) return;
    __half* x = (idx < half) ? q : k;
    int i = (idx < half) ? idx : idx - half;

    int dv = (i & 7) << 2;
    int h  = (i >> 3) & (H_ - 1);
    int bs = i >> 7;
    int s  = bs & (S_ - 1);

    __half* p = x + (size_t)bs * D_ + h * HD_ + dv;
    __half2 a01 = *(__half2*)p,        a23 = *(__half2*)(p + 2);
    __half2 b01 = *(__half2*)(p + 32), b23 = *(__half2*)(p + 34);
    float2 a0 = __half22float2(a01), a1 = __half22float2(a23);
    float2 b0 = __half22float2(b01), b1 = __half22float2(b23);
    const float2* t = tab + s * 32 + dv;
    float2 t0 = t[0], t1 = t[1], t2 = t[2], t3 = t[3];

    float rx0 = fmaf(a0.x, t0.x, -b0.x * t0.y), ry0 = fmaf(a0.x, t0.y, b0.x * t0.x);
    float rx1 = fmaf(a0.y, t1.x, -b0.y * t1.y), ry1 = fmaf(a0.y, t1.y, b0.y * t1.x);
    float rx2 = fmaf(a1.x, t2.x, -b1.x * t2.y), ry2 = fmaf(a1.x, t2.y, b1.x * t2.x);
    float rx3 = fmaf(a1.y, t3.x, -b1.y * t3.y), ry3 = fmaf(a1.y, t3.y, b1.y * t3.x);

    *(uint32_t*)p        = pack_h2(rx0, rx1);
    *(uint32_t*)(p + 2)  = pack_h2(rx2, rx3);
    *(uint32_t*)(p + 32) = pack_h2(ry0, ry1);
    *(uint32_t*)(p + 34) = pack_h2(ry2, ry3);
}

// ===========================================================================
// Tensor-core flash attention, all-fp16 MMA. BM=128, BN=64.
// Heavy-first scheduling: qt = nqt-1 - blockIdx.x.
// ===========================================================================
#define FQ 0
#define FST 16384
#define FK 0
#define FV 8192
#define FSTAGE 16384
#define FLASH_SMEM (16384 + 2 * FSTAGE)   // 49152

__device__ __forceinline__ void flash_load_kv(
    uint32_t sb, int stage, int kt, int tid,
    const __half* Kb, const __half* Vb)
{
    uint32_t base = sb + FST + stage * FSTAGE;
    size_t rbase = (size_t)(kt * 64) * D_;
#pragma unroll
    for (int rep = 0; rep < 2; rep++) {
        int id  = tid + rep * 256;
        int row = id >> 3;
        int seg = id & 7;
        uint32_t soff = SMEM_SWIZZLE_128B((uint32_t)(row * 128 + seg * 16));
        size_t goff = rbase + (size_t)row * D_ + seg * 8;
        cpa16(base + FK + soff, Kb + goff);
        cpa16(base + FV + soff, Vb + goff);
    }
    asm volatile("cp.async.commit_group;" ::: "memory");
}

__global__ __launch_bounds__(256, 2)
void flash_mma(const __half* __restrict__ Q_g, const __half* __restrict__ K_g,
               const __half* __restrict__ V_g, __half* __restrict__ O_g)
{
    extern __shared__ char smem[];
    uint32_t sb = smem_to_u32(smem);
    const int tid  = threadIdx.x;
    const int wid  = tid >> 5;
    const int lane = tid & 31;
    const int qt = (int)(gridDim.x - 1 - blockIdx.x);   // heavy tiles first
    const int h = blockIdx.y, b = blockIdx.z;

    const int g = lane >> 2, c = lane & 3;
    const int mat = lane >> 3, mrr = lane & 7;
    const int a_row_off = (mat & 1) * 8 + mrr;
    const int a_ks_off  = (mat >> 1) * 16;
    const int b_row_off = (mat >> 1) * 8 + mrr;
    const int b_ks_off  = (mat & 1) * 16;
    const int v_l = lane & 7, v_half = (lane >> 3) & 1, v_quad = lane >> 4;

    const size_t hoff = (size_t)(b * S_) * D_ + h * HD_;
    const __half* Qb = Q_g + hoff + (size_t)(qt * 128) * D_;
    const __half* Kb = K_g + hoff;
    const __half* Vb = V_g + hoff;

#pragma unroll
    for (int rep = 0; rep < 4; rep++) {
        int id  = tid + rep * 256;
        int row = id >> 3;
        int seg = id & 7;
        uint32_t soff = SMEM_SWIZZLE_128B((uint32_t)(row * 128 + seg * 16));
        size_t goff = (size_t)row * D_ + seg * 8;
        cpa16(sb + FQ + soff, Qb + goff);
    }
    asm volatile("cp.async.commit_group;" ::: "memory");

    flash_load_kv(sb, 0, 0, tid, Kb, Vb);
    asm volatile("cp.async.wait_group 0;" ::: "memory");
    __syncthreads();

    uint32_t qf[4][4];
#pragma unroll
    for (int t = 0; t < 4; t++) {
        int rowA = wid * 16 + a_row_off;
        uint32_t off = SMEM_SWIZZLE_128B((uint32_t)(rowA * 128 + t * 32 + a_ks_off));
        ldsm4(qf[t][0], qf[t][1], qf[t][2], qf[t][3], sb + FQ + off);
    }

    float mi0 = -INFINITY, mi1 = -INFINITY, li0 = 0.f, li1 = 0.f;
    float o[8][4];
#pragma unroll
    for (int j = 0; j < 8; j++)
#pragma unroll
        for (int r = 0; r < 4; r++) o[j][r] = 0.f;

    const int wrow = qt * 128 + wid * 16;
    const int ktmax = 2 * qt + 1;

    for (int kt = 0; kt <= ktmax; kt++) {
        int s = kt & 1;
        if (kt < ktmax) {
            flash_load_kv(sb, s ^ 1, kt + 1, tid, Kb, Vb);
            asm volatile("cp.async.wait_group 1;" ::: "memory");
        } else {
            asm volatile("cp.async.wait_group 0;" ::: "memory");
        }
        __syncthreads();

        if (kt * 64 <= wrow + 15) {
            uint32_t st = sb + FST + s * FSTAGE;
            float sc[8][4];
#pragma unroll
            for (int j = 0; j < 8; j++)
#pragma unroll
                for (int r = 0; r < 4; r++) sc[j][r] = 0.f;

#pragma unroll
            for (int t = 0; t < 4; t++) {
#pragma unroll
                for (int p = 0; p < 4; p++) {
                    uint32_t k4[4];
                    int rowB = p * 16 + b_row_off;
                    uint32_t off = SMEM_SWIZZLE_128B((uint32_t)(rowB * 128 + t * 32 + b_ks_off));
                    ldsm4(k4[0], k4[1], k4[2], k4[3], st + FK + off);
                    mma_fp16(sc[2 * p],     qf[t], k4[0], k4[1]);
                    mma_fp16(sc[2 * p + 1], qf[t], k4[2], k4[3]);
                }
            }

            const float scale = 0.125f;
            const int row0 = wrow + g, row1 = row0 + 8;
            const bool diag = (kt * 64 + 63 > wrow);
#pragma unroll
            for (int j = 0; j < 8; j++) {
                int col0 = kt * 64 + j * 8 + 2 * c, col1 = col0 + 1;
                sc[j][0] *= scale; sc[j][1] *= scale;
                sc[j][2] *= scale; sc[j][3] *= scale;
                if (diag) {
                    if (col0 > row0) sc[j][0] = -INFINITY;
                    if (col1 > row0) sc[j][1] = -INFINITY;
                    if (col0 > row1) sc[j][2] = -INFINITY;
                    if (col1 > row1) sc[j][3] = -INFINITY;
                }
            }
            float rm0 = -INFINITY, rm1 = -INFINITY;
#pragma unroll
            for (int j = 0; j < 8; j++) {
                rm0 = fmaxf(rm0, fmaxf(sc[j][0], sc[j][1]));
                rm1 = fmaxf(rm1, fmaxf(sc[j][2], sc[j][3]));
            }
            rm0 = fmaxf(rm0, __shfl_xor_sync(0xffffffffu, rm0, 1));
            rm0 = fmaxf(rm0, __shfl_xor_sync(0xffffffffu, rm0, 2));
            rm1 = fmaxf(rm1, __shfl_xor_sync(0xffffffffu, rm1, 1));
            rm1 = fmaxf(rm1, __shfl_xor_sync(0xffffffffu, rm1, 2));

            float mn0 = fmaxf(mi0, rm0), mn1 = fmaxf(mi1, rm1);
            float al0 = __expf(mi0 - mn0), al1 = __expf(mi1 - mn1);
            float rs0 = 0.f, rs1 = 0.f;
#pragma unroll
            for (int j = 0; j < 8; j++) {
                sc[j][0] = __expf(sc[j][0] - mn0);
                sc[j][1] = __expf(sc[j][1] - mn0);
                sc[j][2] = __expf(sc[j][2] - mn1);
                sc[j][3] = __expf(sc[j][3] - mn1);
                rs0 += sc[j][0] + sc[j][1];
                rs1 += sc[j][2] + sc[j][3];
            }
            rs0 += __shfl_xor_sync(0xffffffffu, rs0, 1);
            rs0 += __shfl_xor_sync(0xffffffffu, rs0, 2);
            rs1 += __shfl_xor_sync(0xffffffffu, rs1, 1);
            rs1 += __shfl_xor_sync(0xffffffffu, rs1, 2);
            li0 = li0 * al0 + rs0; li1 = li1 * al1 + rs1;
            mi0 = mn0; mi1 = mn1;
#pragma unroll
            for (int j = 0; j < 8; j++) {
                o[j][0] *= al0; o[j][1] *= al0;
                o[j][2] *= al1; o[j][3] *= al1;
            }

            uint32_t ph[4][4];
#pragma unroll
            for (int t = 0; t < 4; t++) {
                ph[t][0] = pack_h2(sc[2 * t][0],     sc[2 * t][1]);
                ph[t][1] = pack_h2(sc[2 * t][2],     sc[2 * t][3]);
                ph[t][2] = pack_h2(sc[2 * t + 1][0], sc[2 * t + 1][1]);
                ph[t][3] = pack_h2(sc[2 * t + 1][2], sc[2 * t + 1][3]);
            }

#pragma unroll
            for (int t = 0; t < 4; t++) {
#pragma unroll
                for (int jp = 0; jp < 4; jp++) {
                    uint32_t soff = SMEM_SWIZZLE_128B(
                        (uint32_t)((16 * t + v_half * 8 + v_l) * 128 + jp * 32 + v_quad * 16));
                    uint32_t v4[4];
                    ldsm4t(v4[0], v4[1], v4[2], v4[3], st + FV + soff);
                    mma_fp16(o[2 * jp],     ph[t], v4[0], v4[1]);
                    mma_fp16(o[2 * jp + 1], ph[t], v4[2], v4[3]);
                }
            }
        }
        __syncthreads();
    }

    float iv0 = 1.f / li0, iv1 = 1.f / li1;
    size_t r0off = ((size_t)(b * S_ + wrow + g)) * D_ + h * HD_;
    size_t r1off = r0off + 8 * D_;
#pragma unroll
    for (int j = 0; j < 8; j++) {
        int col = j * 8 + 2 * c;
        *(uint32_t*)(O_g + r0off + col) = pack_h2(o[j][0] * iv0, o[j][1] * iv0);
        *(uint32_t*)(O_g + r1off + col) = pack_h2(o[j][2] * iv1, o[j][3] * iv1);
    }
}

// ---------------------------------------------------------------------------
extern "C" void kernel_launch(void* const* d_in, const int* in_sizes, int n_in,
                              void* d_out, int out_size)
{
    const float* Q  = (const float*)d_in[0];
    const float* K  = (const float*)d_in[1];
    const float* V  = (const float*)d_in[2];
    const float* Wq = (const float*)d_in[3];
    const float* bq = (const float*)d_in[4];
    const float* Wk = (const float*)d_in[5];
    const float* bk = (const float*)d_in[6];
    const float* Wv = (const float*)d_in[7];
    const float* bv = (const float*)d_in[8];
    const float* Wo = (const float*)d_in[9];
    const float* bo = (const float*)d_in[10];
    float* out = (float*)d_out;

    float2* grope;
    __half *gx3, *gwqkv, *gw16, *gq16, *gk16, *gv16, *go16;
    cudaGetSymbolAddress((void**)&grope, g_rope);
    cudaGetSymbolAddress((void**)&gx3, g_x3);
    cudaGetSymbolAddress((void**)&gwqkv, g_wqkv);
    cudaGetSymbolAddress((void**)&gw16, g_w16);
    cudaGetSymbolAddress((void**)&gq16, g_q16);
    cudaGetSymbolAddress((void**)&gk16, g_k16);
    cudaGetSymbolAddress((void**)&gv16, g_v16);
    cudaGetSymbolAddress((void**)&go16, g_o16);

    cudaFuncSetAttribute(gemm_qkv, cudaFuncAttributeMaxDynamicSharedMemorySize, GEMM_SMEM);
    cudaFuncSetAttribute(gemm_out, cudaFuncAttributeMaxDynamicSharedMemorySize, GEMM_SMEM);
    cudaFuncSetAttribute(flash_mma, cudaFuncAttributeMaxDynamicSharedMemorySize, FLASH_SMEM);

    const int n4x = NTOT / 4;
    const int n4w = (D_ * D_) / 4;

    rope_table_kernel<<<(S_ * 32 + 255) / 256, 256>>>(grope);

    // Convert inputs and weights to fp16 (packed)
    cvt16_kernel<<<(n4x + 255) / 256, 256>>>(Q, gx3 + 0 * (size_t)NTOT, n4x);
    cvt16_kernel<<<(n4x + 255) / 256, 256>>>(K, gx3 + 1 * (size_t)NTOT, n4x);
    cvt16_kernel<<<(n4x + 255) / 256, 256>>>(V, gx3 + 2 * (size_t)NTOT, n4x);
    cvt16_kernel<<<(n4w + 255) / 256, 256>>>(Wq, gwqkv + 0 * (size_t)(D_ * D_), n4w);
    cvt16_kernel<<<(n4w + 255) / 256, 256>>>(Wk, gwqkv + 1 * (size_t)(D_ * D_), n4w);
    cvt16_kernel<<<(n4w + 255) / 256, 256>>>(Wv, gwqkv + 2 * (size_t)(D_ * D_), n4w);
    cvt16_kernel<<<(n4w + 255) / 256, 256>>>(Wo, gw16, n4w);

    // Fused QKV projection (one launch, 1536 CTAs)
    dim3 qkvgrid(3 * D_ / 128, M_ / 128);
    gemm_qkv<<<qkvgrid, 256, GEMM_SMEM>>>(gx3, gwqkv, bq, bk, bv, gq16, gk16, gv16);

    // RoPE in place on fp16 Q, K
    int items = 2 * B_ * S_ * H_ * 8;
    rope16_kernel<<<(items + 255) / 256, 256>>>(gq16, gk16, grope);

    // Flash (all fp16 MMA, heavy-first) -> fp16 output
    dim3 fgrid(S_ / 128, H_, B_);
    flash_mma<<<fgrid, 256, FLASH_SMEM>>>(gq16, gk16, gv16, go16);

    // Output projection -> fp32 final
    dim3 ogrid(D_ / 128, M_ / 128);
    gemm_out<<<ogrid, 256, GEMM_SMEM>>>(go16, gw16, bo, out);
}

// round 12
// speedup vs baseline: 2.7193x; 1.0398x over previous
#include <cuda_runtime.h>
#include <cuda_fp16.h>
#include <math.h>
#include <stdint.h>

#define B_  4
#define S_  2048
#define D_  1024
#define H_  16
#define HD_ 64
#define M_  (B_ * S_)
#define NTOT (B_ * S_ * D_)

// Scratch (allocation-free rule: __device__ globals)
__device__ __half g_x3[3 * NTOT];        // packed Q16, K16, V16 inputs
__device__ __half g_wqkv[3 * D_ * D_];   // packed Wq, Wk, Wv fp16
__device__ __half g_w16[D_ * D_];        // Wo fp16
__device__ __half g_q16[NTOT];
__device__ __half g_k16[NTOT];
__device__ __half g_v16[NTOT];
__device__ __half g_o16[NTOT];
__device__ float2 g_rope[S_ * 32];

// ===========================================================================
// Helpers (baseline PTX only — compute_103-safe)
// ===========================================================================
__device__ __forceinline__ uint32_t smem_to_u32(const void* p) {
    uint32_t a;
    asm("{ .reg .u64 t; cvta.to.shared.u64 t, %1; cvt.u32.u64 %0, t; }" : "=r"(a) : "l"(p));
    return a;
}
#define SMEM_SWIZZLE_128B(off) ((off) ^ (((off) >> 3) & 0x70))

__device__ __forceinline__ void cpa16(uint32_t dst, const void* src) {
    asm volatile("cp.async.cg.shared.global [%0], [%1], 16;" :: "r"(dst), "l"(src));
}
__device__ __forceinline__ void ldsm4(uint32_t& r0, uint32_t& r1, uint32_t& r2, uint32_t& r3,
                                      uint32_t addr) {
    asm volatile("ldmatrix.sync.aligned.m8n8.x4.shared.b16 {%0,%1,%2,%3}, [%4];"
        : "=r"(r0), "=r"(r1), "=r"(r2), "=r"(r3) : "r"(addr));
}
__device__ __forceinline__ void ldsm4t(uint32_t& r0, uint32_t& r1, uint32_t& r2, uint32_t& r3,
                                       uint32_t addr) {
    asm volatile("ldmatrix.sync.aligned.m8n8.x4.trans.shared.b16 {%0,%1,%2,%3}, [%4];"
        : "=r"(r0), "=r"(r1), "=r"(r2), "=r"(r3) : "r"(addr));
}
__device__ __forceinline__ void mma_fp16(float* d, const uint32_t* a,
                                         uint32_t b0, uint32_t b1) {
    asm volatile(
        "mma.sync.aligned.m16n8k16.row.col.f32.f16.f16.f32 "
        "{%0,%1,%2,%3}, {%4,%5,%6,%7}, {%8,%9}, {%0,%1,%2,%3};"
        : "+f"(d[0]), "+f"(d[1]), "+f"(d[2]), "+f"(d[3])
        : "r"(a[0]), "r"(a[1]), "r"(a[2]), "r"(a[3]), "r"(b0), "r"(b1));
}
__device__ __forceinline__ uint32_t pack_h2(float f0, float f1) {
    __half2 h = __floats2half2_rn(f0, f1);
    return *(uint32_t*)&h;
}

// ===========================================================================
// Fused fp32 -> fp16 converts (inputs x3, weights x4) — pointer-select
// ===========================================================================
__global__ __launch_bounds__(256)
void cvt16x3_kernel(const float* __restrict__ a, const float* __restrict__ b,
                    const float* __restrict__ c, __half* __restrict__ dst, int n4)
{
    int idx = blockIdx.x * blockDim.x + threadIdx.x;
    if (idx >= 3 * n4) return;
    int sel = idx / n4;
    int i = idx - sel * n4;
    const float* x = (sel == 0) ? a : (sel == 1) ? b : c;
    float4 v = ((const float4*)x)[i];
    __half* o = dst + (size_t)sel * NTOT;
    ((uint32_t*)o)[2 * i + 0] = pack_h2(v.x, v.y);
    ((uint32_t*)o)[2 * i + 1] = pack_h2(v.z, v.w);
}

__global__ __launch_bounds__(256)
void cvt16x4w_kernel(const float* __restrict__ wq, const float* __restrict__ wk,
                     const float* __restrict__ wv, const float* __restrict__ wo,
                     __half* __restrict__ dqkv, __half* __restrict__ dwo, int n4)
{
    int idx = blockIdx.x * blockDim.x + threadIdx.x;
    if (idx >= 4 * n4) return;
    int sel = idx / n4;
    int i = idx - sel * n4;
    const float* x = (sel == 0) ? wq : (sel == 1) ? wk : (sel == 2) ? wv : wo;
    __half* o = (sel == 3) ? dwo : (dqkv + (size_t)sel * (D_ * D_));
    float4 v = ((const float4*)x)[i];
    ((uint32_t*)o)[2 * i + 0] = pack_h2(v.x, v.y);
    ((uint32_t*)o)[2 * i + 1] = pack_h2(v.z, v.w);
}

// ===========================================================================
// fp16 GEMM building blocks: 128x128 tile, BK=64, 3-stage cp.async, 2 CTA/SM.
// ===========================================================================
#define TILE_BYTES 16384                   // 128 rows x 128 B (128x64 fp16)
#define STAGE_BYTES (2 * TILE_BYTES)       // 32 KB (A + B)
#define GEMM_SMEM (3 * STAGE_BYTES)        // 96 KB -> 2 CTAs/SM
#define NCHUNK (D_ / 64)                   // 16
#define EPI_STRIDE 132                     // fp16 stride for epilogue tile

__device__ __forceinline__ void gemm_load_chunk(
    uint32_t sb, int stage, int k0, int tid,
    const __half* Ab, const __half* Bb)
{
    uint32_t base = sb + stage * STAGE_BYTES;
#pragma unroll
    for (int rep = 0; rep < 4; rep++) {
        int id  = tid + rep * 256;
        int row = id >> 3;
        int seg = id & 7;
        uint32_t soff = SMEM_SWIZZLE_128B((uint32_t)(row * 128 + seg * 16));
        size_t goff = (size_t)row * D_ + k0 + seg * 8;
        cpa16(base + 0 * TILE_BYTES + soff, Ab + goff);
        cpa16(base + 1 * TILE_BYTES + soff, Bb + goff);
    }
    asm volatile("cp.async.commit_group;" ::: "memory");
}

// Mainloop shared by both GEMM kernels; returns with acc filled.
__device__ __forceinline__ void gemm_mainloop(
    uint32_t sb, int tid, const __half* Ab, const __half* Bb,
    int warp_m, int warp_n, int lane, float acc[4][4][4])
{
#pragma unroll
    for (int i = 0; i < 4; i++)
#pragma unroll
        for (int j = 0; j < 4; j++)
#pragma unroll
            for (int r = 0; r < 4; r++) acc[i][j][r] = 0.f;

    const int mat = lane >> 3;
    const int mrr = lane & 7;
    const int a_row_off = (mat & 1) * 8 + mrr;
    const int a_ks_off  = (mat >> 1) * 16;
    const int b_row_off = (mat >> 1) * 8 + mrr;
    const int b_ks_off  = (mat & 1) * 16;

    gemm_load_chunk(sb, 0, 0, tid, Ab, Bb);
    gemm_load_chunk(sb, 1, 64, tid, Ab, Bb);

    int stage = 0;
    for (int c = 0; c < NCHUNK; c++) {
        if (c + 2 < NCHUNK) {
            int ls = stage + 2; if (ls >= 3) ls -= 3;
            gemm_load_chunk(sb, ls, (c + 2) * 64, tid, Ab, Bb);
            asm volatile("cp.async.wait_group 2;" ::: "memory");
        } else if (c + 1 < NCHUNK) {
            asm volatile("cp.async.wait_group 1;" ::: "memory");
        } else {
            asm volatile("cp.async.wait_group 0;" ::: "memory");
        }
        __syncthreads();

        uint32_t stA = sb + stage * STAGE_BYTES;
#pragma unroll
        for (int ks = 0; ks < 4; ks++) {
            const int kb = ks * 32;
            uint32_t ah[4][4];
#pragma unroll
            for (int mt = 0; mt < 4; mt++) {
                int row = warp_m * 64 + mt * 16 + a_row_off;
                uint32_t off = SMEM_SWIZZLE_128B((uint32_t)(row * 128 + kb + a_ks_off));
                ldsm4(ah[mt][0], ah[mt][1], ah[mt][2], ah[mt][3], stA + 0 * TILE_BYTES + off);
            }
            uint32_t bh[2][4];
#pragma unroll
            for (int p = 0; p < 2; p++) {
                int row = warp_n * 32 + p * 16 + b_row_off;
                uint32_t off = SMEM_SWIZZLE_128B((uint32_t)(row * 128 + kb + b_ks_off));
                ldsm4(bh[p][0], bh[p][1], bh[p][2], bh[p][3], stA + 1 * TILE_BYTES + off);
            }
#pragma unroll
            for (int mt = 0; mt < 4; mt++) {
#pragma unroll
                for (int p = 0; p < 2; p++) {
#pragma unroll
                    for (int q = 0; q < 2; q++) {
                        mma_fp16(acc[mt][p * 2 + q], ah[mt], bh[p][q * 2], bh[p][q * 2 + 1]);
                    }
                }
            }
        }
        __syncthreads();
        stage++; if (stage >= 3) stage = 0;
    }
}

// ---------------------------------------------------------------------------
// Fused QKV projection + RoPE-in-epilogue for Q/K.
// grid.x = 24 (8 each for Q, K, V outputs), grid.y = 64.
// ---------------------------------------------------------------------------
__global__ __launch_bounds__(256, 2)
void gemm_qkv(const __half* __restrict__ X3, const __half* __restrict__ Wqkv,
              const float* __restrict__ bq, const float* __restrict__ bk,
              const float* __restrict__ bv, const float2* __restrict__ rope,
              __half* __restrict__ Qo, __half* __restrict__ Ko, __half* __restrict__ Vo)
{
    extern __shared__ char smem[];
    uint32_t sb = smem_to_u32(smem);
    const int tid  = threadIdx.x;
    const int wid  = tid >> 5;
    const int lane = tid & 31;
    const int warp_m = wid >> 2;
    const int warp_n = wid & 3;
    const int bn = blockIdx.x, bm = blockIdx.y;
    const int sel = bn >> 3;          // 0=Q, 1=K, 2=V
    const int bnl = bn & 7;

    const __half* Ab = X3 + (size_t)sel * NTOT + (size_t)(bm * 128) * D_;
    const __half* Bb = Wqkv + (size_t)sel * D_ * D_ + (size_t)(bnl * 128) * D_;
    const float* bias = (sel == 0) ? bq : (sel == 1) ? bk : bv;
    __half* Co = (sel == 0) ? Qo : (sel == 1) ? Ko : Vo;

    float acc[4][4][4];
    gemm_mainloop(sb, tid, Ab, Bb, warp_m, warp_n, lane, acc);

    const int rloc = warp_m * 64 + (lane >> 2);
    const int cloc = warp_n * 32 + (lane & 3) * 2;

    if (sel == 2) {
        // V: plain epilogue, direct fp16 store
        const int rbase = bm * 128 + rloc;
        const int cbase = bnl * 128 + cloc;
#pragma unroll
        for (int mt = 0; mt < 4; mt++) {
#pragma unroll
            for (int nt = 0; nt < 4; nt++) {
                int col = cbase + nt * 8;
                float b0 = bias[col], b1 = bias[col + 1];
                float* d = acc[mt][nt];
                int r0 = rbase + mt * 16;
                *(uint32_t*)(Co + (size_t)r0 * D_ + col)       = pack_h2(d[0] + b0, d[1] + b1);
                *(uint32_t*)(Co + (size_t)(r0 + 8) * D_ + col) = pack_h2(d[2] + b0, d[3] + b1);
            }
        }
    } else {
        // Q/K: stage tile in smem (pipeline smem is free now), then rope pass
        __half* T = (__half*)smem;
#pragma unroll
        for (int mt = 0; mt < 4; mt++) {
#pragma unroll
            for (int nt = 0; nt < 4; nt++) {
                int col = cloc + nt * 8;
                int gcol = bnl * 128 + col;
                float b0 = bias[gcol], b1 = bias[gcol + 1];
                float* d = acc[mt][nt];
                int r0 = rloc + mt * 16;
                *(uint32_t*)(T + (size_t)r0 * EPI_STRIDE + col)       = pack_h2(d[0] + b0, d[1] + b1);
                *(uint32_t*)(T + (size_t)(r0 + 8) * EPI_STRIDE + col) = pack_h2(d[2] + b0, d[3] + b1);
            }
        }
        __syncthreads();

        // RoPE pass: rotate (d, d+32) pairs within each 64-wide head.
        // Tile = 128 rows x 128 cols = 2 heads. Items: row(128) x hh(2) x dq(16),
        // each item handles 2 consecutive d (d = 2*dq .. 2*dq+1).
        for (int it = tid; it < 128 * 2 * 16; it += 256) {
            int dq  = it & 15;
            int hh  = (it >> 4) & 1;
            int row = it >> 5;
            int d   = dq * 2;
            int colA = hh * 64 + d;

            __half2 a2 = *(__half2*)(T + (size_t)row * EPI_STRIDE + colA);
            __half2 b2 = *(__half2*)(T + (size_t)row * EPI_STRIDE + colA + 32);
            float2 a = __half22float2(a2);
            float2 b = __half22float2(b2);

            int grow = bm * 128 + row;
            int s = grow & (S_ - 1);
            float2 t0 = rope[s * 32 + d];
            float2 t1 = rope[s * 32 + d + 1];

            float rx0 = fmaf(a.x, t0.x, -b.x * t0.y), ry0 = fmaf(a.x, t0.y, b.x * t0.x);
            float rx1 = fmaf(a.y, t1.x, -b.y * t1.y), ry1 = fmaf(a.y, t1.y, b.y * t1.x);

            size_t goff = (size_t)grow * D_ + bnl * 128 + colA;
            *(uint32_t*)(Co + goff)      = pack_h2(rx0, rx1);
            *(uint32_t*)(Co + goff + 32) = pack_h2(ry0, ry1);
        }
    }
}

// ---------------------------------------------------------------------------
// Output projection GEMM: fp16 in, fp32 out.
// ---------------------------------------------------------------------------
__global__ __launch_bounds__(256, 2)
void gemm_out(const __half* __restrict__ A, const __half* __restrict__ W,
              const float* __restrict__ bias, float* __restrict__ C)
{
    extern __shared__ char smem[];
    uint32_t sb = smem_to_u32(smem);
    const int tid  = threadIdx.x;
    const int wid  = tid >> 5;
    const int lane = tid & 31;
    const int warp_m = wid >> 2;
    const int warp_n = wid & 3;
    const int bn = blockIdx.x, bm = blockIdx.y;

    const __half* Ab = A + (size_t)(bm * 128) * D_;
    const __half* Bb = W + (size_t)(bn * 128) * D_;

    float acc[4][4][4];
    gemm_mainloop(sb, tid, Ab, Bb, warp_m, warp_n, lane, acc);

    const int rbase = bm * 128 + warp_m * 64 + (lane >> 2);
    const int cbase = bn * 128 + warp_n * 32 + (lane & 3) * 2;
#pragma unroll
    for (int mt = 0; mt < 4; mt++) {
#pragma unroll
        for (int nt = 0; nt < 4; nt++) {
            int col = cbase + nt * 8;
            float b0 = bias[col], b1 = bias[col + 1];
            float* d = acc[mt][nt];
            int r0 = rbase + mt * 16;
            *(float2*)(C + (size_t)r0 * D_ + col)       = make_float2(d[0] + b0, d[1] + b1);
            *(float2*)(C + (size_t)(r0 + 8) * D_ + col) = make_float2(d[2] + b0, d[3] + b1);
        }
    }
}

// ---------------------------------------------------------------------------
// RoPE table (fp64 for exactness)
// ---------------------------------------------------------------------------
__global__ void rope_table_kernel(float2* __restrict__ tab)
{
    int idx = blockIdx.x * blockDim.x + threadIdx.x;
    if (idx >= S_ * 32) return;
    int s = idx >> 5;
    int d = idx & 31;
    double inv = exp(-log(10000.0) * (double)d / 32.0);
    double ang = (double)s * inv;
    double sd, cd;
    sincos(ang, &sd, &cd);
    tab[idx] = make_float2((float)cd, (float)sd);
}

// ===========================================================================
// Tensor-core flash attention, all-fp16 MMA. BM=128, BN=64.
// Heavy-first scheduling: qt = nqt-1 - blockIdx.x.
// ===========================================================================
#define FQ 0
#define FST 16384
#define FK 0
#define FV 8192
#define FSTAGE 16384
#define FLASH_SMEM (16384 + 2 * FSTAGE)   // 49152

__device__ __forceinline__ void flash_load_kv(
    uint32_t sb, int stage, int kt, int tid,
    const __half* Kb, const __half* Vb)
{
    uint32_t base = sb + FST + stage * FSTAGE;
    size_t rbase = (size_t)(kt * 64) * D_;
#pragma unroll
    for (int rep = 0; rep < 2; rep++) {
        int id  = tid + rep * 256;
        int row = id >> 3;
        int seg = id & 7;
        uint32_t soff = SMEM_SWIZZLE_128B((uint32_t)(row * 128 + seg * 16));
        size_t goff = rbase + (size_t)row * D_ + seg * 8;
        cpa16(base + FK + soff, Kb + goff);
        cpa16(base + FV + soff, Vb + goff);
    }
    asm volatile("cp.async.commit_group;" ::: "memory");
}

__global__ __launch_bounds__(256, 2)
void flash_mma(const __half* __restrict__ Q_g, const __half* __restrict__ K_g,
               const __half* __restrict__ V_g, __half* __restrict__ O_g)
{
    extern __shared__ char smem[];
    uint32_t sb = smem_to_u32(smem);
    const int tid  = threadIdx.x;
    const int wid  = tid >> 5;
    const int lane = tid & 31;
    const int qt = (int)(gridDim.x - 1 - blockIdx.x);   // heavy tiles first
    const int h = blockIdx.y, b = blockIdx.z;

    const int g = lane >> 2, c = lane & 3;
    const int mat = lane >> 3, mrr = lane & 7;
    const int a_row_off = (mat & 1) * 8 + mrr;
    const int a_ks_off  = (mat >> 1) * 16;
    const int b_row_off = (mat >> 1) * 8 + mrr;
    const int b_ks_off  = (mat & 1) * 16;
    const int v_l = lane & 7, v_half = (lane >> 3) & 1, v_quad = lane >> 4;

    const size_t hoff = (size_t)(b * S_) * D_ + h * HD_;
    const __half* Qb = Q_g + hoff + (size_t)(qt * 128) * D_;
    const __half* Kb = K_g + hoff;
    const __half* Vb = V_g + hoff;

#pragma unroll
    for (int rep = 0; rep < 4; rep++) {
        int id  = tid + rep * 256;
        int row = id >> 3;
        int seg = id & 7;
        uint32_t soff = SMEM_SWIZZLE_128B((uint32_t)(row * 128 + seg * 16));
        size_t goff = (size_t)row * D_ + seg * 8;
        cpa16(sb + FQ + soff, Qb + goff);
    }
    asm volatile("cp.async.commit_group;" ::: "memory");

    flash_load_kv(sb, 0, 0, tid, Kb, Vb);
    asm volatile("cp.async.wait_group 0;" ::: "memory");
    __syncthreads();

    uint32_t qf[4][4];
#pragma unroll
    for (int t = 0; t < 4; t++) {
        int rowA = wid * 16 + a_row_off;
        uint32_t off = SMEM_SWIZZLE_128B((uint32_t)(rowA * 128 + t * 32 + a_ks_off));
        ldsm4(qf[t][0], qf[t][1], qf[t][2], qf[t][3], sb + FQ + off);
    }

    float mi0 = -INFINITY, mi1 = -INFINITY, li0 = 0.f, li1 = 0.f;
    float o[8][4];
#pragma unroll
    for (int j = 0; j < 8; j++)
#pragma unroll
        for (int r = 0; r < 4; r++) o[j][r] = 0.f;

    const int wrow = qt * 128 + wid * 16;
    const int ktmax = 2 * qt + 1;

    for (int kt = 0; kt <= ktmax; kt++) {
        int s = kt & 1;
        if (kt < ktmax) {
            flash_load_kv(sb, s ^ 1, kt + 1, tid, Kb, Vb);
            asm volatile("cp.async.wait_group 1;" ::: "memory");
        } else {
            asm volatile("cp.async.wait_group 0;" ::: "memory");
        }
        __syncthreads();

        if (kt * 64 <= wrow + 15) {
            uint32_t st = sb + FST + s * FSTAGE;
            float sc[8][4];
#pragma unroll
            for (int j = 0; j < 8; j++)
#pragma unroll
                for (int r = 0; r < 4; r++) sc[j][r] = 0.f;

#pragma unroll
            for (int t = 0; t < 4; t++) {
#pragma unroll
                for (int p = 0; p < 4; p++) {
                    uint32_t k4[4];
                    int rowB = p * 16 + b_row_off;
                    uint32_t off = SMEM_SWIZZLE_128B((uint32_t)(rowB * 128 + t * 32 + b_ks_off));
                    ldsm4(k4[0], k4[1], k4[2], k4[3], st + FK + off);
                    mma_fp16(sc[2 * p],     qf[t], k4[0], k4[1]);
                    mma_fp16(sc[2 * p + 1], qf[t], k4[2], k4[3]);
                }
            }

            const float scale = 0.125f;
            const int row0 = wrow + g, row1 = row0 + 8;
            const bool diag = (kt * 64 + 63 > wrow);
#pragma unroll
            for (int j = 0; j < 8; j++) {
                int col0 = kt * 64 + j * 8 + 2 * c, col1 = col0 + 1;
                sc[j][0] *= scale; sc[j][1] *= scale;
                sc[j][2] *= scale; sc[j][3] *= scale;
                if (diag) {
                    if (col0 > row0) sc[j][0] = -INFINITY;
                    if (col1 > row0) sc[j][1] = -INFINITY;
                    if (col0 > row1) sc[j][2] = -INFINITY;
                    if (col1 > row1) sc[j][3] = -INFINITY;
                }
            }
            float rm0 = -INFINITY, rm1 = -INFINITY;
#pragma unroll
            for (int j = 0; j < 8; j++) {
                rm0 = fmaxf(rm0, fmaxf(sc[j][0], sc[j][1]));
                rm1 = fmaxf(rm1, fmaxf(sc[j][2], sc[j][3]));
            }
            rm0 = fmaxf(rm0, __shfl_xor_sync(0xffffffffu, rm0, 1));
            rm0 = fmaxf(rm0, __shfl_xor_sync(0xffffffffu, rm0, 2));
            rm1 = fmaxf(rm1, __shfl_xor_sync(0xffffffffu, rm1, 1));
            rm1 = fmaxf(rm1, __shfl_xor_sync(0xffffffffu, rm1, 2));

            float mn0 = fmaxf(mi0, rm0), mn1 = fmaxf(mi1, rm1);
            float al0 = __expf(mi0 - mn0), al1 = __expf(mi1 - mn1);
            float rs0 = 0.f, rs1 = 0.f;
#pragma unroll
            for (int j = 0; j < 8; j++) {
                sc[j][0] = __expf(sc[j][0] - mn0);
                sc[j][1] = __expf(sc[j][1] - mn0);
                sc[j][2] = __expf(sc[j][2] - mn1);
                sc[j][3] = __expf(sc[j][3] - mn1);
                rs0 += sc[j][0] + sc[j][1];
                rs1 += sc[j][2] + sc[j][3];
            }
            rs0 += __shfl_xor_sync(0xffffffffu, rs0, 1);
            rs0 += __shfl_xor_sync(0xffffffffu, rs0, 2);
            rs1 += __shfl_xor_sync(0xffffffffu, rs1, 1);
            rs1 += __shfl_xor_sync(0xffffffffu, rs1, 2);
            li0 = li0 * al0 + rs0; li1 = li1 * al1 + rs1;
            mi0 = mn0; mi1 = mn1;
#pragma unroll
            for (int j = 0; j < 8; j++) {
                o[j][0] *= al0; o[j][1] *= al0;
                o[j][2] *= al1; o[j][3] *= al1;
            }

            uint32_t ph[4][4];
#pragma unroll
            for (int t = 0; t < 4; t++) {
                ph[t][0] = pack_h2(sc[2 * t][0],     sc[2 * t][1]);
                ph[t][1] = pack_h2(sc[2 * t][2],     sc[2 * t][3]);
                ph[t][2] = pack_h2(sc[2 * t + 1][0], sc[2 * t + 1][1]);
                ph[t][3] = pack_h2(sc[2 * t + 1][2], sc[2 * t + 1][3]);
            }

#pragma unroll
            for (int t = 0; t < 4; t++) {
#pragma unroll
                for (int jp = 0; jp < 4; jp++) {
                    uint32_t soff = SMEM_SWIZZLE_128B(
                        (uint32_t)((16 * t + v_half * 8 + v_l) * 128 + jp * 32 + v_quad * 16));
                    uint32_t v4[4];
                    ldsm4t(v4[0], v4[1], v4[2], v4[3], st + FV + soff);
                    mma_fp16(o[2 * jp],     ph[t], v4[0], v4[1]);
                    mma_fp16(o[2 * jp + 1], ph[t], v4[2], v4[3]);
                }
            }
        }
        __syncthreads();
    }

    float iv0 = 1.f / li0, iv1 = 1.f / li1;
    size_t r0off = ((size_t)(b * S_ + wrow + g)) * D_ + h * HD_;
    size_t r1off = r0off + 8 * D_;
#pragma unroll
    for (int j = 0; j < 8; j++) {
        int col = j * 8 + 2 * c;
        *(uint32_t*)(O_g + r0off + col) = pack_h2(o[j][0] * iv0, o[j][1] * iv0);
        *(uint32_t*)(O_g + r1off + col) = pack_h2(o[j][2] * iv1, o[j][3] * iv1);
    }
}

// ---------------------------------------------------------------------------
extern "C" void kernel_launch(void* const* d_in, const int* in_sizes, int n_in,
                              void* d_out, int out_size)
{
    const float* Q  = (const float*)d_in[0];
    const float* K  = (const float*)d_in[1];
    const float* V  = (const float*)d_in[2];
    const float* Wq = (const float*)d_in[3];
    const float* bq = (const float*)d_in[4];
    const float* Wk = (const float*)d_in[5];
    const float* bk = (const float*)d_in[6];
    const float* Wv = (const float*)d_in[7];
    const float* bv = (const float*)d_in[8];
    const float* Wo = (const float*)d_in[9];
    const float* bo = (const float*)d_in[10];
    float* out = (float*)d_out;

    float2* grope;
    __half *gx3, *gwqkv, *gw16, *gq16, *gk16, *gv16, *go16;
    cudaGetSymbolAddress((void**)&grope, g_rope);
    cudaGetSymbolAddress((void**)&gx3, g_x3);
    cudaGetSymbolAddress((void**)&gwqkv, g_wqkv);
    cudaGetSymbolAddress((void**)&gw16, g_w16);
    cudaGetSymbolAddress((void**)&gq16, g_q16);
    cudaGetSymbolAddress((void**)&gk16, g_k16);
    cudaGetSymbolAddress((void**)&gv16, g_v16);
    cudaGetSymbolAddress((void**)&go16, g_o16);

    cudaFuncSetAttribute(gemm_qkv, cudaFuncAttributeMaxDynamicSharedMemorySize, GEMM_SMEM);
    cudaFuncSetAttribute(gemm_out, cudaFuncAttributeMaxDynamicSharedMemorySize, GEMM_SMEM);
    cudaFuncSetAttribute(flash_mma, cudaFuncAttributeMaxDynamicSharedMemorySize, FLASH_SMEM);

    const int n4x = NTOT / 4;
    const int n4w = (D_ * D_) / 4;

    rope_table_kernel<<<(S_ * 32 + 255) / 256, 256>>>(grope);

    // Fused converts: 3 inputs in one launch, 4 weights in one launch
    cvt16x3_kernel<<<(3 * n4x + 255) / 256, 256>>>(Q, K, V, gx3, n4x);
    cvt16x4w_kernel<<<(4 * n4w + 255) / 256, 256>>>(Wq, Wk, Wv, Wo, gwqkv, gw16, n4w);

    // Fused QKV projection with RoPE-in-epilogue for Q/K (one launch, 1536 CTAs)
    dim3 qkvgrid(3 * D_ / 128, M_ / 128);
    gemm_qkv<<<qkvgrid, 256, GEMM_SMEM>>>(gx3, gwqkv, bq, bk, bv, grope,
                                          gq16, gk16, gv16);

    // Flash (all fp16 MMA, heavy-first) -> fp16 output
    dim3 fgrid(S_ / 128, H_, B_);
    flash_mma<<<fgrid, 256, FLASH_SMEM>>>(gq16, gk16, gv16, go16);

    // Output projection -> fp32 final
    dim3 ogrid(D_ / 128, M_ / 128);
    gemm_out<<<ogrid, 256, GEMM_SMEM>>>(go16, gw16, bo, out);
}

// round 13
// speedup vs baseline: 2.7690x; 1.0183x over previous
#include <cuda_runtime.h>
#include <cuda_fp16.h>
#include <math.h>
#include <stdint.h>

#define B_  4
#define S_  2048
#define D_  1024
#define H_  16
#define HD_ 64
#define M_  (B_ * S_)
#define NTOT (B_ * S_ * D_)

// Scratch (allocation-free rule: __device__ globals)
__device__ __half g_x3[3 * NTOT];        // packed Q16, K16, V16 inputs
__device__ __half g_wqkv[3 * D_ * D_];   // packed Wq, Wk, Wv fp16
__device__ __half g_w16[D_ * D_];        // Wo fp16
__device__ __half g_q16[NTOT];
__device__ __half g_k16[NTOT];
__device__ __half g_v16[NTOT];
__device__ __half g_o16[NTOT];
__device__ float2 g_rope[S_ * 32];

// ===========================================================================
// Helpers (baseline PTX only — compute_103-safe)
// ===========================================================================
__device__ __forceinline__ uint32_t smem_to_u32(const void* p) {
    uint32_t a;
    asm("{ .reg .u64 t; cvta.to.shared.u64 t, %1; cvt.u32.u64 %0, t; }" : "=r"(a) : "l"(p));
    return a;
}
#define SMEM_SWIZZLE_128B(off) ((off) ^ (((off) >> 3) & 0x70))

__device__ __forceinline__ void cpa16(uint32_t dst, const void* src) {
    asm volatile("cp.async.cg.shared.global [%0], [%1], 16;" :: "r"(dst), "l"(src));
}
__device__ __forceinline__ void ldsm4(uint32_t& r0, uint32_t& r1, uint32_t& r2, uint32_t& r3,
                                      uint32_t addr) {
    asm volatile("ldmatrix.sync.aligned.m8n8.x4.shared.b16 {%0,%1,%2,%3}, [%4];"
        : "=r"(r0), "=r"(r1), "=r"(r2), "=r"(r3) : "r"(addr));
}
__device__ __forceinline__ void ldsm4t(uint32_t& r0, uint32_t& r1, uint32_t& r2, uint32_t& r3,
                                       uint32_t addr) {
    asm volatile("ldmatrix.sync.aligned.m8n8.x4.trans.shared.b16 {%0,%1,%2,%3}, [%4];"
        : "=r"(r0), "=r"(r1), "=r"(r2), "=r"(r3) : "r"(addr));
}
__device__ __forceinline__ void mma_fp16(float* d, const uint32_t* a,
                                         uint32_t b0, uint32_t b1) {
    asm volatile(
        "mma.sync.aligned.m16n8k16.row.col.f32.f16.f16.f32 "
        "{%0,%1,%2,%3}, {%4,%5,%6,%7}, {%8,%9}, {%0,%1,%2,%3};"
        : "+f"(d[0]), "+f"(d[1]), "+f"(d[2]), "+f"(d[3])
        : "r"(a[0]), "r"(a[1]), "r"(a[2]), "r"(a[3]), "r"(b0), "r"(b1));
}
__device__ __forceinline__ uint32_t pack_h2(float f0, float f1) {
    __half2 h = __floats2half2_rn(f0, f1);
    return *(uint32_t*)&h;
}

// ===========================================================================
// Fused fp32 -> fp16 converts (inputs x3, weights x4) — pointer-select
// ===========================================================================
__global__ __launch_bounds__(256)
void cvt16x3_kernel(const float* __restrict__ a, const float* __restrict__ b,
                    const float* __restrict__ c, __half* __restrict__ dst, int n4)
{
    int idx = blockIdx.x * blockDim.x + threadIdx.x;
    if (idx >= 3 * n4) return;
    int sel = idx / n4;
    int i = idx - sel * n4;
    const float* x = (sel == 0) ? a : (sel == 1) ? b : c;
    float4 v = ((const float4*)x)[i];
    __half* o = dst + (size_t)sel * NTOT;
    ((uint32_t*)o)[2 * i + 0] = pack_h2(v.x, v.y);
    ((uint32_t*)o)[2 * i + 1] = pack_h2(v.z, v.w);
}

__global__ __launch_bounds__(256)
void cvt16x4w_kernel(const float* __restrict__ wq, const float* __restrict__ wk,
                     const float* __restrict__ wv, const float* __restrict__ wo,
                     __half* __restrict__ dqkv, __half* __restrict__ dwo, int n4)
{
    int idx = blockIdx.x * blockDim.x + threadIdx.x;
    if (idx >= 4 * n4) return;
    int sel = idx / n4;
    int i = idx - sel * n4;
    const float* x = (sel == 0) ? wq : (sel == 1) ? wk : (sel == 2) ? wv : wo;
    __half* o = (sel == 3) ? dwo : (dqkv + (size_t)sel * (D_ * D_));
    float4 v = ((const float4*)x)[i];
    ((uint32_t*)o)[2 * i + 0] = pack_h2(v.x, v.y);
    ((uint32_t*)o)[2 * i + 1] = pack_h2(v.z, v.w);
}

// ===========================================================================
// fp16 GEMM building blocks: 128x128 tile, BK=64, 3-stage cp.async, 2 CTA/SM.
// ===========================================================================
#define TILE_BYTES 16384                   // 128 rows x 128 B (128x64 fp16)
#define STAGE_BYTES (2 * TILE_BYTES)       // 32 KB (A + B)
#define GEMM_SMEM (3 * STAGE_BYTES)        // 96 KB -> 2 CTAs/SM
#define NCHUNK (D_ / 64)                   // 16
#define EPI_STRIDE 132                     // fp16 stride for epilogue tile

__device__ __forceinline__ void gemm_load_chunk(
    uint32_t sb, int stage, int k0, int tid,
    const __half* Ab, const __half* Bb)
{
    uint32_t base = sb + stage * STAGE_BYTES;
#pragma unroll
    for (int rep = 0; rep < 4; rep++) {
        int id  = tid + rep * 256;
        int row = id >> 3;
        int seg = id & 7;
        uint32_t soff = SMEM_SWIZZLE_128B((uint32_t)(row * 128 + seg * 16));
        size_t goff = (size_t)row * D_ + k0 + seg * 8;
        cpa16(base + 0 * TILE_BYTES + soff, Ab + goff);
        cpa16(base + 1 * TILE_BYTES + soff, Bb + goff);
    }
    asm volatile("cp.async.commit_group;" ::: "memory");
}

// Mainloop shared by both GEMM kernels; returns with acc filled.
__device__ __forceinline__ void gemm_mainloop(
    uint32_t sb, int tid, const __half* Ab, const __half* Bb,
    int warp_m, int warp_n, int lane, float acc[4][4][4])
{
#pragma unroll
    for (int i = 0; i < 4; i++)
#pragma unroll
        for (int j = 0; j < 4; j++)
#pragma unroll
            for (int r = 0; r < 4; r++) acc[i][j][r] = 0.f;

    const int mat = lane >> 3;
    const int mrr = lane & 7;
    const int a_row_off = (mat & 1) * 8 + mrr;
    const int a_ks_off  = (mat >> 1) * 16;
    const int b_row_off = (mat >> 1) * 8 + mrr;
    const int b_ks_off  = (mat & 1) * 16;

    gemm_load_chunk(sb, 0, 0, tid, Ab, Bb);
    gemm_load_chunk(sb, 1, 64, tid, Ab, Bb);

    int stage = 0;
    for (int c = 0; c < NCHUNK; c++) {
        if (c + 2 < NCHUNK) {
            int ls = stage + 2; if (ls >= 3) ls -= 3;
            gemm_load_chunk(sb, ls, (c + 2) * 64, tid, Ab, Bb);
            asm volatile("cp.async.wait_group 2;" ::: "memory");
        } else if (c + 1 < NCHUNK) {
            asm volatile("cp.async.wait_group 1;" ::: "memory");
        } else {
            asm volatile("cp.async.wait_group 0;" ::: "memory");
        }
        __syncthreads();

        uint32_t stA = sb + stage * STAGE_BYTES;
#pragma unroll
        for (int ks = 0; ks < 4; ks++) {
            const int kb = ks * 32;
            uint32_t ah[4][4];
#pragma unroll
            for (int mt = 0; mt < 4; mt++) {
                int row = warp_m * 64 + mt * 16 + a_row_off;
                uint32_t off = SMEM_SWIZZLE_128B((uint32_t)(row * 128 + kb + a_ks_off));
                ldsm4(ah[mt][0], ah[mt][1], ah[mt][2], ah[mt][3], stA + 0 * TILE_BYTES + off);
            }
            uint32_t bh[2][4];
#pragma unroll
            for (int p = 0; p < 2; p++) {
                int row = warp_n * 32 + p * 16 + b_row_off;
                uint32_t off = SMEM_SWIZZLE_128B((uint32_t)(row * 128 + kb + b_ks_off));
                ldsm4(bh[p][0], bh[p][1], bh[p][2], bh[p][3], stA + 1 * TILE_BYTES + off);
            }
#pragma unroll
            for (int mt = 0; mt < 4; mt++) {
#pragma unroll
                for (int p = 0; p < 2; p++) {
#pragma unroll
                    for (int q = 0; q < 2; q++) {
                        mma_fp16(acc[mt][p * 2 + q], ah[mt], bh[p][q * 2], bh[p][q * 2 + 1]);
                    }
                }
            }
        }
        __syncthreads();
        stage++; if (stage >= 3) stage = 0;
    }
}

// ---------------------------------------------------------------------------
// Fused QKV projection + RoPE-in-epilogue for Q/K.
// grid.x = 24 (8 each for Q, K, V outputs), grid.y = 64.
// ---------------------------------------------------------------------------
__global__ __launch_bounds__(256, 2)
void gemm_qkv(const __half* __restrict__ X3, const __half* __restrict__ Wqkv,
              const float* __restrict__ bq, const float* __restrict__ bk,
              const float* __restrict__ bv, const float2* __restrict__ rope,
              __half* __restrict__ Qo, __half* __restrict__ Ko, __half* __restrict__ Vo)
{
    extern __shared__ char smem[];
    uint32_t sb = smem_to_u32(smem);
    const int tid  = threadIdx.x;
    const int wid  = tid >> 5;
    const int lane = tid & 31;
    const int warp_m = wid >> 2;
    const int warp_n = wid & 3;
    const int bn = blockIdx.x, bm = blockIdx.y;
    const int sel = bn >> 3;          // 0=Q, 1=K, 2=V
    const int bnl = bn & 7;

    const __half* Ab = X3 + (size_t)sel * NTOT + (size_t)(bm * 128) * D_;
    const __half* Bb = Wqkv + (size_t)sel * D_ * D_ + (size_t)(bnl * 128) * D_;
    const float* bias = (sel == 0) ? bq : (sel == 1) ? bk : bv;
    __half* Co = (sel == 0) ? Qo : (sel == 1) ? Ko : Vo;

    float acc[4][4][4];
    gemm_mainloop(sb, tid, Ab, Bb, warp_m, warp_n, lane, acc);

    const int rloc = warp_m * 64 + (lane >> 2);
    const int cloc = warp_n * 32 + (lane & 3) * 2;

    if (sel == 2) {
        const int rbase = bm * 128 + rloc;
        const int cbase = bnl * 128 + cloc;
#pragma unroll
        for (int mt = 0; mt < 4; mt++) {
#pragma unroll
            for (int nt = 0; nt < 4; nt++) {
                int col = cbase + nt * 8;
                float b0 = bias[col], b1 = bias[col + 1];
                float* d = acc[mt][nt];
                int r0 = rbase + mt * 16;
                *(uint32_t*)(Co + (size_t)r0 * D_ + col)       = pack_h2(d[0] + b0, d[1] + b1);
                *(uint32_t*)(Co + (size_t)(r0 + 8) * D_ + col) = pack_h2(d[2] + b0, d[3] + b1);
            }
        }
    } else {
        __half* T = (__half*)smem;
#pragma unroll
        for (int mt = 0; mt < 4; mt++) {
#pragma unroll
            for (int nt = 0; nt < 4; nt++) {
                int col = cloc + nt * 8;
                int gcol = bnl * 128 + col;
                float b0 = bias[gcol], b1 = bias[gcol + 1];
                float* d = acc[mt][nt];
                int r0 = rloc + mt * 16;
                *(uint32_t*)(T + (size_t)r0 * EPI_STRIDE + col)       = pack_h2(d[0] + b0, d[1] + b1);
                *(uint32_t*)(T + (size_t)(r0 + 8) * EPI_STRIDE + col) = pack_h2(d[2] + b0, d[3] + b1);
            }
        }
        __syncthreads();

        for (int it = tid; it < 128 * 2 * 16; it += 256) {
            int dq  = it & 15;
            int hh  = (it >> 4) & 1;
            int row = it >> 5;
            int d   = dq * 2;
            int colA = hh * 64 + d;

            __half2 a2 = *(__half2*)(T + (size_t)row * EPI_STRIDE + colA);
            __half2 b2 = *(__half2*)(T + (size_t)row * EPI_STRIDE + colA + 32);
            float2 a = __half22float2(a2);
            float2 b = __half22float2(b2);

            int grow = bm * 128 + row;
            int s = grow & (S_ - 1);
            float2 t0 = rope[s * 32 + d];
            float2 t1 = rope[s * 32 + d + 1];

            float rx0 = fmaf(a.x, t0.x, -b.x * t0.y), ry0 = fmaf(a.x, t0.y, b.x * t0.x);
            float rx1 = fmaf(a.y, t1.x, -b.y * t1.y), ry1 = fmaf(a.y, t1.y, b.y * t1.x);

            size_t goff = (size_t)grow * D_ + bnl * 128 + colA;
            *(uint32_t*)(Co + goff)      = pack_h2(rx0, rx1);
            *(uint32_t*)(Co + goff + 32) = pack_h2(ry0, ry1);
        }
    }
}

// ---------------------------------------------------------------------------
// Output projection GEMM: fp16 in, fp32 out.
// ---------------------------------------------------------------------------
__global__ __launch_bounds__(256, 2)
void gemm_out(const __half* __restrict__ A, const __half* __restrict__ W,
              const float* __restrict__ bias, float* __restrict__ C)
{
    extern __shared__ char smem[];
    uint32_t sb = smem_to_u32(smem);
    const int tid  = threadIdx.x;
    const int wid  = tid >> 5;
    const int lane = tid & 31;
    const int warp_m = wid >> 2;
    const int warp_n = wid & 3;
    const int bn = blockIdx.x, bm = blockIdx.y;

    const __half* Ab = A + (size_t)(bm * 128) * D_;
    const __half* Bb = W + (size_t)(bn * 128) * D_;

    float acc[4][4][4];
    gemm_mainloop(sb, tid, Ab, Bb, warp_m, warp_n, lane, acc);

    const int rbase = bm * 128 + warp_m * 64 + (lane >> 2);
    const int cbase = bn * 128 + warp_n * 32 + (lane & 3) * 2;
#pragma unroll
    for (int mt = 0; mt < 4; mt++) {
#pragma unroll
        for (int nt = 0; nt < 4; nt++) {
            int col = cbase + nt * 8;
            float b0 = bias[col], b1 = bias[col + 1];
            float* d = acc[mt][nt];
            int r0 = rbase + mt * 16;
            *(float2*)(C + (size_t)r0 * D_ + col)       = make_float2(d[0] + b0, d[1] + b1);
            *(float2*)(C + (size_t)(r0 + 8) * D_ + col) = make_float2(d[2] + b0, d[3] + b1);
        }
    }
}

// ---------------------------------------------------------------------------
// RoPE table (fp64 for exactness)
// ---------------------------------------------------------------------------
__global__ void rope_table_kernel(float2* __restrict__ tab)
{
    int idx = blockIdx.x * blockDim.x + threadIdx.x;
    if (idx >= S_ * 32) return;
    int s = idx >> 5;
    int d = idx & 31;
    double inv = exp(-log(10000.0) * (double)d / 32.0);
    double ang = (double)s * inv;
    double sd, cd;
    sincos(ang, &sd, &cd);
    tab[idx] = make_float2((float)cd, (float)sd);
}

// ===========================================================================
// Tensor-core flash attention, all-fp16 MMA. BM=128.
// Stages cover 128 K-rows (two 64-wide sub-tiles processed per sync window).
// Heavy-first scheduling: qt = nqt-1 - blockIdx.x.
// ===========================================================================
#define FQ 0
#define FST 16384
#define FK 0
#define FV 16384
#define FSTAGE 32768
#define FLASH_SMEM (16384 + 2 * FSTAGE)   // 81920 -> 2 CTA/SM

__device__ __forceinline__ void flash_load_kv128(
    uint32_t sb, int stage, int kt2, int tid,
    const __half* Kb, const __half* Vb)
{
    uint32_t base = sb + FST + stage * FSTAGE;
    size_t rbase = (size_t)(kt2 * 128) * D_;
#pragma unroll
    for (int rep = 0; rep < 4; rep++) {
        int id  = tid + rep * 256;
        int row = id >> 3;
        int seg = id & 7;
        uint32_t soff = SMEM_SWIZZLE_128B((uint32_t)(row * 128 + seg * 16));
        size_t goff = rbase + (size_t)row * D_ + seg * 8;
        cpa16(base + FK + soff, Kb + goff);
        cpa16(base + FV + soff, Vb + goff);
    }
    asm volatile("cp.async.commit_group;" ::: "memory");
}

__global__ __launch_bounds__(256, 2)
void flash_mma(const __half* __restrict__ Q_g, const __half* __restrict__ K_g,
               const __half* __restrict__ V_g, __half* __restrict__ O_g)
{
    extern __shared__ char smem[];
    uint32_t sb = smem_to_u32(smem);
    const int tid  = threadIdx.x;
    const int wid  = tid >> 5;
    const int lane = tid & 31;
    const int qt = (int)(gridDim.x - 1 - blockIdx.x);   // heavy tiles first
    const int h = blockIdx.y, b = blockIdx.z;

    const int g = lane >> 2, c = lane & 3;
    const int mat = lane >> 3, mrr = lane & 7;
    const int a_row_off = (mat & 1) * 8 + mrr;
    const int a_ks_off  = (mat >> 1) * 16;
    const int b_row_off = (mat >> 1) * 8 + mrr;
    const int b_ks_off  = (mat & 1) * 16;
    const int v_l = lane & 7, v_half = (lane >> 3) & 1, v_quad = lane >> 4;

    const size_t hoff = (size_t)(b * S_) * D_ + h * HD_;
    const __half* Qb = Q_g + hoff + (size_t)(qt * 128) * D_;
    const __half* Kb = K_g + hoff;
    const __half* Vb = V_g + hoff;

    // Q tile: 128 rows x 128 B (fp16)
#pragma unroll
    for (int rep = 0; rep < 4; rep++) {
        int id  = tid + rep * 256;
        int row = id >> 3;
        int seg = id & 7;
        uint32_t soff = SMEM_SWIZZLE_128B((uint32_t)(row * 128 + seg * 16));
        size_t goff = (size_t)row * D_ + seg * 8;
        cpa16(sb + FQ + soff, Qb + goff);
    }
    asm volatile("cp.async.commit_group;" ::: "memory");

    flash_load_kv128(sb, 0, 0, tid, Kb, Vb);
    asm volatile("cp.async.wait_group 0;" ::: "memory");
    __syncthreads();

    uint32_t qf[4][4];
#pragma unroll
    for (int t = 0; t < 4; t++) {
        int rowA = wid * 16 + a_row_off;
        uint32_t off = SMEM_SWIZZLE_128B((uint32_t)(rowA * 128 + t * 32 + a_ks_off));
        ldsm4(qf[t][0], qf[t][1], qf[t][2], qf[t][3], sb + FQ + off);
    }

    float mi0 = -INFINITY, mi1 = -INFINITY, li0 = 0.f, li1 = 0.f;
    float o[8][4];
#pragma unroll
    for (int j = 0; j < 8; j++)
#pragma unroll
        for (int r = 0; r < 4; r++) o[j][r] = 0.f;

    const int wrow = qt * 128 + wid * 16;

    for (int kt2 = 0; kt2 <= qt; kt2++) {
        int s = kt2 & 1;
        if (kt2 < qt) {
            flash_load_kv128(sb, s ^ 1, kt2 + 1, tid, Kb, Vb);
            asm volatile("cp.async.wait_group 1;" ::: "memory");
        } else {
            asm volatile("cp.async.wait_group 0;" ::: "memory");
        }
        __syncthreads();

        uint32_t st = sb + FST + s * FSTAGE;

#pragma unroll
        for (int sub = 0; sub < 2; sub++) {
            const int kbase = kt2 * 128 + sub * 64;   // first k-row of sub-tile
            if (kbase > wrow + 15) continue;          // fully masked for this warp

            float sc[8][4];
#pragma unroll
            for (int j = 0; j < 8; j++)
#pragma unroll
                for (int r = 0; r < 4; r++) sc[j][r] = 0.f;

            // S = Q K^T (single fp16), K rows sub*64 .. sub*64+63 of the stage
#pragma unroll
            for (int t = 0; t < 4; t++) {
#pragma unroll
                for (int p = 0; p < 4; p++) {
                    uint32_t k4[4];
                    int rowB = sub * 64 + p * 16 + b_row_off;
                    uint32_t off = SMEM_SWIZZLE_128B((uint32_t)(rowB * 128 + t * 32 + b_ks_off));
                    ldsm4(k4[0], k4[1], k4[2], k4[3], st + FK + off);
                    mma_fp16(sc[2 * p],     qf[t], k4[0], k4[1]);
                    mma_fp16(sc[2 * p + 1], qf[t], k4[2], k4[3]);
                }
            }

            const float scale = 0.125f;
            const int row0 = wrow + g, row1 = row0 + 8;
            const bool diag = (kbase + 63 > wrow);
#pragma unroll
            for (int j = 0; j < 8; j++) {
                int col0 = kbase + j * 8 + 2 * c, col1 = col0 + 1;
                sc[j][0] *= scale; sc[j][1] *= scale;
                sc[j][2] *= scale; sc[j][3] *= scale;
                if (diag) {
                    if (col0 > row0) sc[j][0] = -INFINITY;
                    if (col1 > row0) sc[j][1] = -INFINITY;
                    if (col0 > row1) sc[j][2] = -INFINITY;
                    if (col1 > row1) sc[j][3] = -INFINITY;
                }
            }
            float rm0 = -INFINITY, rm1 = -INFINITY;
#pragma unroll
            for (int j = 0; j < 8; j++) {
                rm0 = fmaxf(rm0, fmaxf(sc[j][0], sc[j][1]));
                rm1 = fmaxf(rm1, fmaxf(sc[j][2], sc[j][3]));
            }
            rm0 = fmaxf(rm0, __shfl_xor_sync(0xffffffffu, rm0, 1));
            rm0 = fmaxf(rm0, __shfl_xor_sync(0xffffffffu, rm0, 2));
            rm1 = fmaxf(rm1, __shfl_xor_sync(0xffffffffu, rm1, 1));
            rm1 = fmaxf(rm1, __shfl_xor_sync(0xffffffffu, rm1, 2));

            float mn0 = fmaxf(mi0, rm0), mn1 = fmaxf(mi1, rm1);
            float al0 = __expf(mi0 - mn0), al1 = __expf(mi1 - mn1);
            float rs0 = 0.f, rs1 = 0.f;
#pragma unroll
            for (int j = 0; j < 8; j++) {
                sc[j][0] = __expf(sc[j][0] - mn0);
                sc[j][1] = __expf(sc[j][1] - mn0);
                sc[j][2] = __expf(sc[j][2] - mn1);
                sc[j][3] = __expf(sc[j][3] - mn1);
                rs0 += sc[j][0] + sc[j][1];
                rs1 += sc[j][2] + sc[j][3];
            }
            rs0 += __shfl_xor_sync(0xffffffffu, rs0, 1);
            rs0 += __shfl_xor_sync(0xffffffffu, rs0, 2);
            rs1 += __shfl_xor_sync(0xffffffffu, rs1, 1);
            rs1 += __shfl_xor_sync(0xffffffffu, rs1, 2);
            li0 = li0 * al0 + rs0; li1 = li1 * al1 + rs1;
            mi0 = mn0; mi1 = mn1;
#pragma unroll
            for (int j = 0; j < 8; j++) {
                o[j][0] *= al0; o[j][1] *= al0;
                o[j][2] *= al1; o[j][3] *= al1;
            }

            uint32_t ph[4][4];
#pragma unroll
            for (int t = 0; t < 4; t++) {
                ph[t][0] = pack_h2(sc[2 * t][0],     sc[2 * t][1]);
                ph[t][1] = pack_h2(sc[2 * t][2],     sc[2 * t][3]);
                ph[t][2] = pack_h2(sc[2 * t + 1][0], sc[2 * t + 1][1]);
                ph[t][3] = pack_h2(sc[2 * t + 1][2], sc[2 * t + 1][3]);
            }

            // O += P V, V rows sub*64 .. sub*64+63 of the stage
#pragma unroll
            for (int t = 0; t < 4; t++) {
#pragma unroll
                for (int jp = 0; jp < 4; jp++) {
                    uint32_t soff = SMEM_SWIZZLE_128B(
                        (uint32_t)((sub * 64 + 16 * t + v_half * 8 + v_l) * 128 + jp * 32 + v_quad * 16));
                    uint32_t v4[4];
                    ldsm4t(v4[0], v4[1], v4[2], v4[3], st + FV + soff);
                    mma_fp16(o[2 * jp],     ph[t], v4[0], v4[1]);
                    mma_fp16(o[2 * jp + 1], ph[t], v4[2], v4[3]);
                }
            }
        }
        __syncthreads();
    }

    // epilogue: normalize + fp16, feeds output projection directly
    float iv0 = 1.f / li0, iv1 = 1.f / li1;
    size_t r0off = ((size_t)(b * S_ + wrow + g)) * D_ + h * HD_;
    size_t r1off = r0off + 8 * D_;
#pragma unroll
    for (int j = 0; j < 8; j++) {
        int col = j * 8 + 2 * c;
        *(uint32_t*)(O_g + r0off + col) = pack_h2(o[j][0] * iv0, o[j][1] * iv0);
        *(uint32_t*)(O_g + r1off + col) = pack_h2(o[j][2] * iv1, o[j][3] * iv1);
    }
}

// ---------------------------------------------------------------------------
extern "C" void kernel_launch(void* const* d_in, const int* in_sizes, int n_in,
                              void* d_out, int out_size)
{
    const float* Q  = (const float*)d_in[0];
    const float* K  = (const float*)d_in[1];
    const float* V  = (const float*)d_in[2];
    const float* Wq = (const float*)d_in[3];
    const float* bq = (const float*)d_in[4];
    const float* Wk = (const float*)d_in[5];
    const float* bk = (const float*)d_in[6];
    const float* Wv = (const float*)d_in[7];
    const float* bv = (const float*)d_in[8];
    const float* Wo = (const float*)d_in[9];
    const float* bo = (const float*)d_in[10];
    float* out = (float*)d_out;

    float2* grope;
    __half *gx3, *gwqkv, *gw16, *gq16, *gk16, *gv16, *go16;
    cudaGetSymbolAddress((void**)&grope, g_rope);
    cudaGetSymbolAddress((void**)&gx3, g_x3);
    cudaGetSymbolAddress((void**)&gwqkv, g_wqkv);
    cudaGetSymbolAddress((void**)&gw16, g_w16);
    cudaGetSymbolAddress((void**)&gq16, g_q16);
    cudaGetSymbolAddress((void**)&gk16, g_k16);
    cudaGetSymbolAddress((void**)&gv16, g_v16);
    cudaGetSymbolAddress((void**)&go16, g_o16);

    cudaFuncSetAttribute(gemm_qkv, cudaFuncAttributeMaxDynamicSharedMemorySize, GEMM_SMEM);
    cudaFuncSetAttribute(gemm_out, cudaFuncAttributeMaxDynamicSharedMemorySize, GEMM_SMEM);
    cudaFuncSetAttribute(flash_mma, cudaFuncAttributeMaxDynamicSharedMemorySize, FLASH_SMEM);

    const int n4x = NTOT / 4;
    const int n4w = (D_ * D_) / 4;

    rope_table_kernel<<<(S_ * 32 + 255) / 256, 256>>>(grope);

    // Fused converts: 3 inputs in one launch, 4 weights in one launch
    cvt16x3_kernel<<<(3 * n4x + 255) / 256, 256>>>(Q, K, V, gx3, n4x);
    cvt16x4w_kernel<<<(4 * n4w + 255) / 256, 256>>>(Wq, Wk, Wv, Wo, gwqkv, gw16, n4w);

    // Fused QKV projection with RoPE-in-epilogue for Q/K (one launch, 1536 CTAs)
    dim3 qkvgrid(3 * D_ / 128, M_ / 128);
    gemm_qkv<<<qkvgrid, 256, GEMM_SMEM>>>(gx3, gwqkv, bq, bk, bv, grope,
                                          gq16, gk16, gv16);

    // Flash (all fp16 MMA, 128-row stages, heavy-first) -> fp16 output
    dim3 fgrid(S_ / 128, H_, B_);
    flash_mma<<<fgrid, 256, FLASH_SMEM>>>(gq16, gk16, gv16, go16);

    // Output projection -> fp32 final
    dim3 ogrid(D_ / 128, M_ / 128);
    gemm_out<<<ogrid, 256, GEMM_SMEM>>>(go16, gw16, bo, out);
}

// round 14
// speedup vs baseline: 2.7971x; 1.0102x over previous
#include <cuda_runtime.h>
#include <cuda_fp16.h>
#include <math.h>
#include <stdint.h>

#define B_  4
#define S_  2048
#define D_  1024
#define H_  16
#define HD_ 64
#define M_  (B_ * S_)
#define NTOT (B_ * S_ * D_)

// Scratch (allocation-free rule: __device__ globals)
__device__ __half g_x3[3 * NTOT];        // packed Q16, K16, V16 inputs
__device__ __half g_wqkv[3 * D_ * D_];   // packed Wq, Wk, Wv fp16
__device__ __half g_w16[D_ * D_];        // Wo fp16
__device__ __half g_q16[NTOT];
__device__ __half g_k16[NTOT];
__device__ __half g_v16[NTOT];
__device__ __half g_o16[NTOT];
__device__ float2 g_rope[S_ * 32];

// ===========================================================================
// Helpers (baseline PTX only — compute_103-safe)
// ===========================================================================
__device__ __forceinline__ uint32_t smem_to_u32(const void* p) {
    uint32_t a;
    asm("{ .reg .u64 t; cvta.to.shared.u64 t, %1; cvt.u32.u64 %0, t; }" : "=r"(a) : "l"(p));
    return a;
}
#define SMEM_SWIZZLE_128B(off) ((off) ^ (((off) >> 3) & 0x70))

__device__ __forceinline__ void cpa16(uint32_t dst, const void* src) {
    asm volatile("cp.async.cg.shared.global [%0], [%1], 16;" :: "r"(dst), "l"(src));
}
__device__ __forceinline__ void ldsm4(uint32_t& r0, uint32_t& r1, uint32_t& r2, uint32_t& r3,
                                      uint32_t addr) {
    asm volatile("ldmatrix.sync.aligned.m8n8.x4.shared.b16 {%0,%1,%2,%3}, [%4];"
        : "=r"(r0), "=r"(r1), "=r"(r2), "=r"(r3) : "r"(addr));
}
__device__ __forceinline__ void ldsm4t(uint32_t& r0, uint32_t& r1, uint32_t& r2, uint32_t& r3,
                                       uint32_t addr) {
    asm volatile("ldmatrix.sync.aligned.m8n8.x4.trans.shared.b16 {%0,%1,%2,%3}, [%4];"
        : "=r"(r0), "=r"(r1), "=r"(r2), "=r"(r3) : "r"(addr));
}
__device__ __forceinline__ void mma_fp16(float* d, const uint32_t* a,
                                         uint32_t b0, uint32_t b1) {
    asm volatile(
        "mma.sync.aligned.m16n8k16.row.col.f32.f16.f16.f32 "
        "{%0,%1,%2,%3}, {%4,%5,%6,%7}, {%8,%9}, {%0,%1,%2,%3};"
        : "+f"(d[0]), "+f"(d[1]), "+f"(d[2]), "+f"(d[3])
        : "r"(a[0]), "r"(a[1]), "r"(a[2]), "r"(a[3]), "r"(b0), "r"(b1));
}
__device__ __forceinline__ uint32_t pack_h2(float f0, float f1) {
    __half2 h = __floats2half2_rn(f0, f1);
    return *(uint32_t*)&h;
}

// ===========================================================================
// Fused fp32 -> fp16 converts. cvt16x3 also builds the RoPE table.
// ===========================================================================
__global__ __launch_bounds__(256)
void cvt16x3_kernel(const float* __restrict__ a, const float* __restrict__ b,
                    const float* __restrict__ c, __half* __restrict__ dst,
                    float2* __restrict__ tab, int n4)
{
    int idx = blockIdx.x * blockDim.x + threadIdx.x;
    if (idx < S_ * 32) {
        int s = idx >> 5;
        int d = idx & 31;
        double inv = exp(-log(10000.0) * (double)d / 32.0);
        double ang = (double)s * inv;
        double sd, cd;
        sincos(ang, &sd, &cd);
        tab[idx] = make_float2((float)cd, (float)sd);
    }
    if (idx >= 3 * n4) return;
    int sel = idx / n4;
    int i = idx - sel * n4;
    const float* x = (sel == 0) ? a : (sel == 1) ? b : c;
    float4 v = ((const float4*)x)[i];
    __half* o = dst + (size_t)sel * NTOT;
    ((uint32_t*)o)[2 * i + 0] = pack_h2(v.x, v.y);
    ((uint32_t*)o)[2 * i + 1] = pack_h2(v.z, v.w);
}

__global__ __launch_bounds__(256)
void cvt16x4w_kernel(const float* __restrict__ wq, const float* __restrict__ wk,
                     const float* __restrict__ wv, const float* __restrict__ wo,
                     __half* __restrict__ dqkv, __half* __restrict__ dwo, int n4)
{
    int idx = blockIdx.x * blockDim.x + threadIdx.x;
    if (idx >= 4 * n4) return;
    int sel = idx / n4;
    int i = idx - sel * n4;
    const float* x = (sel == 0) ? wq : (sel == 1) ? wk : (sel == 2) ? wv : wo;
    __half* o = (sel == 3) ? dwo : (dqkv + (size_t)sel * (D_ * D_));
    float4 v = ((const float4*)x)[i];
    ((uint32_t*)o)[2 * i + 0] = pack_h2(v.x, v.y);
    ((uint32_t*)o)[2 * i + 1] = pack_h2(v.z, v.w);
}

// ===========================================================================
// fp16 GEMM building blocks: 128x128 tile, BK=64, 3-stage cp.async, 2 CTA/SM.
// One __syncthreads per chunk (load-issue moved after the sync; overlap kept).
// ===========================================================================
#define TILE_BYTES 16384                   // 128 rows x 128 B (128x64 fp16)
#define STAGE_BYTES (2 * TILE_BYTES)       // 32 KB (A + B)
#define GEMM_SMEM (3 * STAGE_BYTES)        // 96 KB -> 2 CTAs/SM
#define NCHUNK (D_ / 64)                   // 16
#define EPI_STRIDE 132                     // fp16 stride for epilogue tile

__device__ __forceinline__ void gemm_load_chunk(
    uint32_t sb, int stage, int k0, int tid,
    const __half* Ab, const __half* Bb)
{
    uint32_t base = sb + stage * STAGE_BYTES;
#pragma unroll
    for (int rep = 0; rep < 4; rep++) {
        int id  = tid + rep * 256;
        int row = id >> 3;
        int seg = id & 7;
        uint32_t soff = SMEM_SWIZZLE_128B((uint32_t)(row * 128 + seg * 16));
        size_t goff = (size_t)row * D_ + k0 + seg * 8;
        cpa16(base + 0 * TILE_BYTES + soff, Ab + goff);
        cpa16(base + 1 * TILE_BYTES + soff, Bb + goff);
    }
    asm volatile("cp.async.commit_group;" ::: "memory");
}

// Mainloop shared by both GEMM kernels; returns with acc filled.
__device__ __forceinline__ void gemm_mainloop(
    uint32_t sb, int tid, const __half* Ab, const __half* Bb,
    int warp_m, int warp_n, int lane, float acc[4][4][4])
{
#pragma unroll
    for (int i = 0; i < 4; i++)
#pragma unroll
        for (int j = 0; j < 4; j++)
#pragma unroll
            for (int r = 0; r < 4; r++) acc[i][j][r] = 0.f;

    const int mat = lane >> 3;
    const int mrr = lane & 7;
    const int a_row_off = (mat & 1) * 8 + mrr;
    const int a_ks_off  = (mat >> 1) * 16;
    const int b_row_off = (mat >> 1) * 8 + mrr;
    const int b_ks_off  = (mat & 1) * 16;

    gemm_load_chunk(sb, 0, 0, tid, Ab, Bb);
    gemm_load_chunk(sb, 1, 64, tid, Ab, Bb);

    int stage = 0;
    for (int c = 0; c < NCHUNK; c++) {
        // Stage c's group is complete when at most 1 newer group is pending.
        if (c + 1 < NCHUNK) {
            asm volatile("cp.async.wait_group 1;" ::: "memory");
        } else {
            asm volatile("cp.async.wait_group 0;" ::: "memory");
        }
        __syncthreads();   // stage c visible to all; compute(c-1) done by all

        // Issue prefetch for c+2 (overwrites stage last read at c-1: safe).
        if (c + 2 < NCHUNK) {
            int ls = stage + 2; if (ls >= 3) ls -= 3;
            gemm_load_chunk(sb, ls, (c + 2) * 64, tid, Ab, Bb);
        }

        uint32_t stA = sb + stage * STAGE_BYTES;
#pragma unroll
        for (int ks = 0; ks < 4; ks++) {
            const int kb = ks * 32;
            uint32_t ah[4][4];
#pragma unroll
            for (int mt = 0; mt < 4; mt++) {
                int row = warp_m * 64 + mt * 16 + a_row_off;
                uint32_t off = SMEM_SWIZZLE_128B((uint32_t)(row * 128 + kb + a_ks_off));
                ldsm4(ah[mt][0], ah[mt][1], ah[mt][2], ah[mt][3], stA + 0 * TILE_BYTES + off);
            }
            uint32_t bh[2][4];
#pragma unroll
            for (int p = 0; p < 2; p++) {
                int row = warp_n * 32 + p * 16 + b_row_off;
                uint32_t off = SMEM_SWIZZLE_128B((uint32_t)(row * 128 + kb + b_ks_off));
                ldsm4(bh[p][0], bh[p][1], bh[p][2], bh[p][3], stA + 1 * TILE_BYTES + off);
            }
#pragma unroll
            for (int mt = 0; mt < 4; mt++) {
#pragma unroll
                for (int p = 0; p < 2; p++) {
#pragma unroll
                    for (int q = 0; q < 2; q++) {
                        mma_fp16(acc[mt][p * 2 + q], ah[mt], bh[p][q * 2], bh[p][q * 2 + 1]);
                    }
                }
            }
        }
        stage++; if (stage >= 3) stage = 0;
    }
    __syncthreads();   // protect smem reuse by epilogue (Q/K rope staging)
}

// ---------------------------------------------------------------------------
// Fused QKV projection + RoPE-in-epilogue for Q/K.
// grid.x = 24 (8 each for Q, K, V outputs), grid.y = 64.
// ---------------------------------------------------------------------------
__global__ __launch_bounds__(256, 2)
void gemm_qkv(const __half* __restrict__ X3, const __half* __restrict__ Wqkv,
              const float* __restrict__ bq, const float* __restrict__ bk,
              const float* __restrict__ bv, const float2* __restrict__ rope,
              __half* __restrict__ Qo, __half* __restrict__ Ko, __half* __restrict__ Vo)
{
    extern __shared__ char smem[];
    uint32_t sb = smem_to_u32(smem);
    const int tid  = threadIdx.x;
    const int wid  = tid >> 5;
    const int lane = tid & 31;
    const int warp_m = wid >> 2;
    const int warp_n = wid & 3;
    const int bn = blockIdx.x, bm = blockIdx.y;
    const int sel = bn >> 3;          // 0=Q, 1=K, 2=V
    const int bnl = bn & 7;

    const __half* Ab = X3 + (size_t)sel * NTOT + (size_t)(bm * 128) * D_;
    const __half* Bb = Wqkv + (size_t)sel * D_ * D_ + (size_t)(bnl * 128) * D_;
    const float* bias = (sel == 0) ? bq : (sel == 1) ? bk : bv;
    __half* Co = (sel == 0) ? Qo : (sel == 1) ? Ko : Vo;

    float acc[4][4][4];
    gemm_mainloop(sb, tid, Ab, Bb, warp_m, warp_n, lane, acc);

    const int rloc = warp_m * 64 + (lane >> 2);
    const int cloc = warp_n * 32 + (lane & 3) * 2;

    if (sel == 2) {
        const int rbase = bm * 128 + rloc;
        const int cbase = bnl * 128 + cloc;
#pragma unroll
        for (int mt = 0; mt < 4; mt++) {
#pragma unroll
            for (int nt = 0; nt < 4; nt++) {
                int col = cbase + nt * 8;
                float b0 = bias[col], b1 = bias[col + 1];
                float* d = acc[mt][nt];
                int r0 = rbase + mt * 16;
                *(uint32_t*)(Co + (size_t)r0 * D_ + col)       = pack_h2(d[0] + b0, d[1] + b1);
                *(uint32_t*)(Co + (size_t)(r0 + 8) * D_ + col) = pack_h2(d[2] + b0, d[3] + b1);
            }
        }
    } else {
        __half* T = (__half*)smem;
#pragma unroll
        for (int mt = 0; mt < 4; mt++) {
#pragma unroll
            for (int nt = 0; nt < 4; nt++) {
                int col = cloc + nt * 8;
                int gcol = bnl * 128 + col;
                float b0 = bias[gcol], b1 = bias[gcol + 1];
                float* d = acc[mt][nt];
                int r0 = rloc + mt * 16;
                *(uint32_t*)(T + (size_t)r0 * EPI_STRIDE + col)       = pack_h2(d[0] + b0, d[1] + b1);
                *(uint32_t*)(T + (size_t)(r0 + 8) * EPI_STRIDE + col) = pack_h2(d[2] + b0, d[3] + b1);
            }
        }
        __syncthreads();

        for (int it = tid; it < 128 * 2 * 16; it += 256) {
            int dq  = it & 15;
            int hh  = (it >> 4) & 1;
            int row = it >> 5;
            int d   = dq * 2;
            int colA = hh * 64 + d;

            __half2 a2 = *(__half2*)(T + (size_t)row * EPI_STRIDE + colA);
            __half2 b2 = *(__half2*)(T + (size_t)row * EPI_STRIDE + colA + 32);
            float2 a = __half22float2(a2);
            float2 b = __half22float2(b2);

            int grow = bm * 128 + row;
            int s = grow & (S_ - 1);
            float2 t0 = rope[s * 32 + d];
            float2 t1 = rope[s * 32 + d + 1];

            float rx0 = fmaf(a.x, t0.x, -b.x * t0.y), ry0 = fmaf(a.x, t0.y, b.x * t0.x);
            float rx1 = fmaf(a.y, t1.x, -b.y * t1.y), ry1 = fmaf(a.y, t1.y, b.y * t1.x);

            size_t goff = (size_t)grow * D_ + bnl * 128 + colA;
            *(uint32_t*)(Co + goff)      = pack_h2(rx0, rx1);
            *(uint32_t*)(Co + goff + 32) = pack_h2(ry0, ry1);
        }
    }
}

// ---------------------------------------------------------------------------
// Output projection GEMM: fp16 in, fp32 out.
// ---------------------------------------------------------------------------
__global__ __launch_bounds__(256, 2)
void gemm_out(const __half* __restrict__ A, const __half* __restrict__ W,
              const float* __restrict__ bias, float* __restrict__ C)
{
    extern __shared__ char smem[];
    uint32_t sb = smem_to_u32(smem);
    const int tid  = threadIdx.x;
    const int wid  = tid >> 5;
    const int lane = tid & 31;
    const int warp_m = wid >> 2;
    const int warp_n = wid & 3;
    const int bn = blockIdx.x, bm = blockIdx.y;

    const __half* Ab = A + (size_t)(bm * 128) * D_;
    const __half* Bb = W + (size_t)(bn * 128) * D_;

    float acc[4][4][4];
    gemm_mainloop(sb, tid, Ab, Bb, warp_m, warp_n, lane, acc);

    const int rbase = bm * 128 + warp_m * 64 + (lane >> 2);
    const int cbase = bn * 128 + warp_n * 32 + (lane & 3) * 2;
#pragma unroll
    for (int mt = 0; mt < 4; mt++) {
#pragma unroll
        for (int nt = 0; nt < 4; nt++) {
            int col = cbase + nt * 8;
            float b0 = bias[col], b1 = bias[col + 1];
            float* d = acc[mt][nt];
            int r0 = rbase + mt * 16;
            *(float2*)(C + (size_t)r0 * D_ + col)       = make_float2(d[0] + b0, d[1] + b1);
            *(float2*)(C + (size_t)(r0 + 8) * D_ + col) = make_float2(d[2] + b0, d[3] + b1);
        }
    }
}

// ===========================================================================
// Tensor-core flash attention, all-fp16 MMA. BM=128.
// 128-row KV stages, two 64-wide sub-tiles per sync window, ONE sync/window.
// Heavy-first scheduling: qt = nqt-1 - blockIdx.x.
// ===========================================================================
#define FQ 0
#define FST 16384
#define FK 0
#define FV 16384
#define FSTAGE 32768
#define FLASH_SMEM (16384 + 2 * FSTAGE)   // 81920 -> 2 CTA/SM

__device__ __forceinline__ void flash_load_kv128(
    uint32_t sb, int stage, int kt2, int tid,
    const __half* Kb, const __half* Vb)
{
    uint32_t base = sb + FST + stage * FSTAGE;
    size_t rbase = (size_t)(kt2 * 128) * D_;
#pragma unroll
    for (int rep = 0; rep < 4; rep++) {
        int id  = tid + rep * 256;
        int row = id >> 3;
        int seg = id & 7;
        uint32_t soff = SMEM_SWIZZLE_128B((uint32_t)(row * 128 + seg * 16));
        size_t goff = rbase + (size_t)row * D_ + seg * 8;
        cpa16(base + FK + soff, Kb + goff);
        cpa16(base + FV + soff, Vb + goff);
    }
    asm volatile("cp.async.commit_group;" ::: "memory");
}

__global__ __launch_bounds__(256, 2)
void flash_mma(const __half* __restrict__ Q_g, const __half* __restrict__ K_g,
               const __half* __restrict__ V_g, __half* __restrict__ O_g)
{
    extern __shared__ char smem[];
    uint32_t sb = smem_to_u32(smem);
    const int tid  = threadIdx.x;
    const int wid  = tid >> 5;
    const int lane = tid & 31;
    const int qt = (int)(gridDim.x - 1 - blockIdx.x);   // heavy tiles first
    const int h = blockIdx.y, b = blockIdx.z;

    const int g = lane >> 2, c = lane & 3;
    const int mat = lane >> 3, mrr = lane & 7;
    const int a_row_off = (mat & 1) * 8 + mrr;
    const int a_ks_off  = (mat >> 1) * 16;
    const int b_row_off = (mat >> 1) * 8 + mrr;
    const int b_ks_off  = (mat & 1) * 16;
    const int v_l = lane & 7, v_half = (lane >> 3) & 1, v_quad = lane >> 4;

    const size_t hoff = (size_t)(b * S_) * D_ + h * HD_;
    const __half* Qb = Q_g + hoff + (size_t)(qt * 128) * D_;
    const __half* Kb = K_g + hoff;
    const __half* Vb = V_g + hoff;

    // Q tile: 128 rows x 128 B (fp16)
#pragma unroll
    for (int rep = 0; rep < 4; rep++) {
        int id  = tid + rep * 256;
        int row = id >> 3;
        int seg = id & 7;
        uint32_t soff = SMEM_SWIZZLE_128B((uint32_t)(row * 128 + seg * 16));
        size_t goff = (size_t)row * D_ + seg * 8;
        cpa16(sb + FQ + soff, Qb + goff);
    }
    asm volatile("cp.async.commit_group;" ::: "memory");

    flash_load_kv128(sb, 0, 0, tid, Kb, Vb);
    asm volatile("cp.async.wait_group 0;" ::: "memory");
    __syncthreads();

    uint32_t qf[4][4];
#pragma unroll
    for (int t = 0; t < 4; t++) {
        int rowA = wid * 16 + a_row_off;
        uint32_t off = SMEM_SWIZZLE_128B((uint32_t)(rowA * 128 + t * 32 + a_ks_off));
        ldsm4(qf[t][0], qf[t][1], qf[t][2], qf[t][3], sb + FQ + off);
    }

    float mi0 = -INFINITY, mi1 = -INFINITY, li0 = 0.f, li1 = 0.f;
    float o[8][4];
#pragma unroll
    for (int j = 0; j < 8; j++)
#pragma unroll
        for (int r = 0; r < 4; r++) o[j][r] = 0.f;

    const int wrow = qt * 128 + wid * 16;

    for (int kt2 = 0; kt2 <= qt; kt2++) {
        int s = kt2 & 1;
        if (kt2 > 0) {
            asm volatile("cp.async.wait_group 0;" ::: "memory");
            __syncthreads();   // stage s visible; compute(kt2-1) done
        }
        if (kt2 < qt) {
            // Prefetch next stage (overwrites buffer last read at kt2-1: safe).
            flash_load_kv128(sb, s ^ 1, kt2 + 1, tid, Kb, Vb);
        }

        uint32_t st = sb + FST + s * FSTAGE;

#pragma unroll
        for (int sub = 0; sub < 2; sub++) {
            const int kbase = kt2 * 128 + sub * 64;   // first k-row of sub-tile
            if (kbase > wrow + 15) continue;          // fully masked for this warp

            float sc[8][4];
#pragma unroll
            for (int j = 0; j < 8; j++)
#pragma unroll
                for (int r = 0; r < 4; r++) sc[j][r] = 0.f;

#pragma unroll
            for (int t = 0; t < 4; t++) {
#pragma unroll
                for (int p = 0; p < 4; p++) {
                    uint32_t k4[4];
                    int rowB = sub * 64 + p * 16 + b_row_off;
                    uint32_t off = SMEM_SWIZZLE_128B((uint32_t)(rowB * 128 + t * 32 + b_ks_off));
                    ldsm4(k4[0], k4[1], k4[2], k4[3], st + FK + off);
                    mma_fp16(sc[2 * p],     qf[t], k4[0], k4[1]);
                    mma_fp16(sc[2 * p + 1], qf[t], k4[2], k4[3]);
                }
            }

            const float scale = 0.125f;
            const int row0 = wrow + g, row1 = row0 + 8;
            const bool diag = (kbase + 63 > wrow);
#pragma unroll
            for (int j = 0; j < 8; j++) {
                int col0 = kbase + j * 8 + 2 * c, col1 = col0 + 1;
                sc[j][0] *= scale; sc[j][1] *= scale;
                sc[j][2] *= scale; sc[j][3] *= scale;
                if (diag) {
                    if (col0 > row0) sc[j][0] = -INFINITY;
                    if (col1 > row0) sc[j][1] = -INFINITY;
                    if (col0 > row1) sc[j][2] = -INFINITY;
                    if (col1 > row1) sc[j][3] = -INFINITY;
                }
            }
            float rm0 = -INFINITY, rm1 = -INFINITY;
#pragma unroll
            for (int j = 0; j < 8; j++) {
                rm0 = fmaxf(rm0, fmaxf(sc[j][0], sc[j][1]));
                rm1 = fmaxf(rm1, fmaxf(sc[j][2], sc[j][3]));
            }
            rm0 = fmaxf(rm0, __shfl_xor_sync(0xffffffffu, rm0, 1));
            rm0 = fmaxf(rm0, __shfl_xor_sync(0xffffffffu, rm0, 2));
            rm1 = fmaxf(rm1, __shfl_xor_sync(0xffffffffu, rm1, 1));
            rm1 = fmaxf(rm1, __shfl_xor_sync(0xffffffffu, rm1, 2));

            float mn0 = fmaxf(mi0, rm0), mn1 = fmaxf(mi1, rm1);
            float al0 = __expf(mi0 - mn0), al1 = __expf(mi1 - mn1);
            float rs0 = 0.f, rs1 = 0.f;
#pragma unroll
            for (int j = 0; j < 8; j++) {
                sc[j][0] = __expf(sc[j][0] - mn0);
                sc[j][1] = __expf(sc[j][1] - mn0);
                sc[j][2] = __expf(sc[j][2] - mn1);
                sc[j][3] = __expf(sc[j][3] - mn1);
                rs0 += sc[j][0] + sc[j][1];
                rs1 += sc[j][2] + sc[j][3];
            }
            rs0 += __shfl_xor_sync(0xffffffffu, rs0, 1);
            rs0 += __shfl_xor_sync(0xffffffffu, rs0, 2);
            rs1 += __shfl_xor_sync(0xffffffffu, rs1, 1);
            rs1 += __shfl_xor_sync(0xffffffffu, rs1, 2);
            li0 = li0 * al0 + rs0; li1 = li1 * al1 + rs1;
            mi0 = mn0; mi1 = mn1;
#pragma unroll
            for (int j = 0; j < 8; j++) {
                o[j][0] *= al0; o[j][1] *= al0;
                o[j][2] *= al1; o[j][3] *= al1;
            }

            uint32_t ph[4][4];
#pragma unroll
            for (int t = 0; t < 4; t++) {
                ph[t][0] = pack_h2(sc[2 * t][0],     sc[2 * t][1]);
                ph[t][1] = pack_h2(sc[2 * t][2],     sc[2 * t][3]);
                ph[t][2] = pack_h2(sc[2 * t + 1][0], sc[2 * t + 1][1]);
                ph[t][3] = pack_h2(sc[2 * t + 1][2], sc[2 * t + 1][3]);
            }

#pragma unroll
            for (int t = 0; t < 4; t++) {
#pragma unroll
                for (int jp = 0; jp < 4; jp++) {
                    uint32_t soff = SMEM_SWIZZLE_128B(
                        (uint32_t)((sub * 64 + 16 * t + v_half * 8 + v_l) * 128 + jp * 32 + v_quad * 16));
                    uint32_t v4[4];
                    ldsm4t(v4[0], v4[1], v4[2], v4[3], st + FV + soff);
                    mma_fp16(o[2 * jp],     ph[t], v4[0], v4[1]);
                    mma_fp16(o[2 * jp + 1], ph[t], v4[2], v4[3]);
                }
            }
        }
    }

    // epilogue: normalize + fp16, feeds output projection directly
    float iv0 = 1.f / li0, iv1 = 1.f / li1;
    size_t r0off = ((size_t)(b * S_ + wrow + g)) * D_ + h * HD_;
    size_t r1off = r0off + 8 * D_;
#pragma unroll
    for (int j = 0; j < 8; j++) {
        int col = j * 8 + 2 * c;
        *(uint32_t*)(O_g + r0off + col) = pack_h2(o[j][0] * iv0, o[j][1] * iv0);
        *(uint32_t*)(O_g + r1off + col) = pack_h2(o[j][2] * iv1, o[j][3] * iv1);
    }
}

// ---------------------------------------------------------------------------
extern "C" void kernel_launch(void* const* d_in, const int* in_sizes, int n_in,
                              void* d_out, int out_size)
{
    const float* Q  = (const float*)d_in[0];
    const float* K  = (const float*)d_in[1];
    const float* V  = (const float*)d_in[2];
    const float* Wq = (const float*)d_in[3];
    const float* bq = (const float*)d_in[4];
    const float* Wk = (const float*)d_in[5];
    const float* bk = (const float*)d_in[6];
    const float* Wv = (const float*)d_in[7];
    const float* bv = (const float*)d_in[8];
    const float* Wo = (const float*)d_in[9];
    const float* bo = (const float*)d_in[10];
    float* out = (float*)d_out;

    float2* grope;
    __half *gx3, *gwqkv, *gw16, *gq16, *gk16, *gv16, *go16;
    cudaGetSymbolAddress((void**)&grope, g_rope);
    cudaGetSymbolAddress((void**)&gx3, g_x3);
    cudaGetSymbolAddress((void**)&gwqkv, g_wqkv);
    cudaGetSymbolAddress((void**)&gw16, g_w16);
    cudaGetSymbolAddress((void**)&gq16, g_q16);
    cudaGetSymbolAddress((void**)&gk16, g_k16);
    cudaGetSymbolAddress((void**)&gv16, g_v16);
    cudaGetSymbolAddress((void**)&go16, g_o16);

    cudaFuncSetAttribute(gemm_qkv, cudaFuncAttributeMaxDynamicSharedMemorySize, GEMM_SMEM);
    cudaFuncSetAttribute(gemm_out, cudaFuncAttributeMaxDynamicSharedMemorySize, GEMM_SMEM);
    cudaFuncSetAttribute(flash_mma, cudaFuncAttributeMaxDynamicSharedMemorySize, FLASH_SMEM);

    const int n4x = NTOT / 4;
    const int n4w = (D_ * D_) / 4;

    // Fused converts (cvt16x3 also builds the RoPE table)
    cvt16x3_kernel<<<(3 * n4x + 255) / 256, 256>>>(Q, K, V, gx3, grope, n4x);
    cvt16x4w_kernel<<<(4 * n4w + 255) / 256, 256>>>(Wq, Wk, Wv, Wo, gwqkv, gw16, n4w);

    // Fused QKV projection with RoPE-in-epilogue for Q/K (one launch, 1536 CTAs)
    dim3 qkvgrid(3 * D_ / 128, M_ / 128);
    gemm_qkv<<<qkvgrid, 256, GEMM_SMEM>>>(gx3, gwqkv, bq, bk, bv, grope,
                                          gq16, gk16, gv16);

    // Flash (all fp16 MMA, 128-row stages, one sync/window, heavy-first)
    dim3 fgrid(S_ / 128, H_, B_);
    flash_mma<<<fgrid, 256, FLASH_SMEM>>>(gq16, gk16, gv16, go16);

    // Output projection -> fp32 final
    dim3 ogrid(D_ / 128, M_ / 128);
    gemm_out<<<ogrid, 256, GEMM_SMEM>>>(go16, gw16, bo, out);
}

// round 15
// speedup vs baseline: 2.8500x; 1.0189x over previous
#include <cuda_runtime.h>
#include <cuda_fp16.h>
#include <math.h>
#include <stdint.h>

#define B_  4
#define S_  2048
#define D_  1024
#define H_  16
#define HD_ 64
#define M_  (B_ * S_)
#define NTOT (B_ * S_ * D_)

// Scratch (allocation-free rule: __device__ globals)
__device__ __half g_x3[3 * NTOT];        // packed Q16, K16, V16 inputs
__device__ __half g_wqkv[3 * D_ * D_];   // packed Wq, Wk, Wv fp16
__device__ __half g_w16[D_ * D_];        // Wo fp16
__device__ __half g_q16[NTOT];
__device__ __half g_k16[NTOT];
__device__ __half g_v16[NTOT];
__device__ __half g_o16[NTOT];
__device__ float2 g_rope[S_ * 32];

// ===========================================================================
// Helpers (baseline PTX only — compute_103-safe)
// ===========================================================================
__device__ __forceinline__ uint32_t smem_to_u32(const void* p) {
    uint32_t a;
    asm("{ .reg .u64 t; cvta.to.shared.u64 t, %1; cvt.u32.u64 %0, t; }" : "=r"(a) : "l"(p));
    return a;
}
#define SMEM_SWIZZLE_128B(off) ((off) ^ (((off) >> 3) & 0x70))

__device__ __forceinline__ void cpa16(uint32_t dst, const void* src) {
    asm volatile("cp.async.cg.shared.global [%0], [%1], 16;" :: "r"(dst), "l"(src));
}
__device__ __forceinline__ void ldsm4(uint32_t& r0, uint32_t& r1, uint32_t& r2, uint32_t& r3,
                                      uint32_t addr) {
    asm volatile("ldmatrix.sync.aligned.m8n8.x4.shared.b16 {%0,%1,%2,%3}, [%4];"
        : "=r"(r0), "=r"(r1), "=r"(r2), "=r"(r3) : "r"(addr));
}
__device__ __forceinline__ void ldsm4t(uint32_t& r0, uint32_t& r1, uint32_t& r2, uint32_t& r3,
                                       uint32_t addr) {
    asm volatile("ldmatrix.sync.aligned.m8n8.x4.trans.shared.b16 {%0,%1,%2,%3}, [%4];"
        : "=r"(r0), "=r"(r1), "=r"(r2), "=r"(r3) : "r"(addr));
}
__device__ __forceinline__ void mma_fp16(float* d, const uint32_t* a,
                                         uint32_t b0, uint32_t b1) {
    asm volatile(
        "mma.sync.aligned.m16n8k16.row.col.f32.f16.f16.f32 "
        "{%0,%1,%2,%3}, {%4,%5,%6,%7}, {%8,%9}, {%0,%1,%2,%3};"
        : "+f"(d[0]), "+f"(d[1]), "+f"(d[2]), "+f"(d[3])
        : "r"(a[0]), "r"(a[1]), "r"(a[2]), "r"(a[3]), "r"(b0), "r"(b1));
}
__device__ __forceinline__ uint32_t pack_h2(float f0, float f1) {
    __half2 h = __floats2half2_rn(f0, f1);
    return *(uint32_t*)&h;
}

// ===========================================================================
// Fused fp32 -> fp16 converts. cvt16x3 also builds the RoPE table.
// ===========================================================================
__global__ __launch_bounds__(256)
void cvt16x3_kernel(const float* __restrict__ a, const float* __restrict__ b,
                    const float* __restrict__ c, __half* __restrict__ dst,
                    float2* __restrict__ tab, int n4)
{
    int idx = blockIdx.x * blockDim.x + threadIdx.x;
    if (idx < S_ * 32) {
        int s = idx >> 5;
        int d = idx & 31;
        double inv = exp(-log(10000.0) * (double)d / 32.0);
        double ang = (double)s * inv;
        double sd, cd;
        sincos(ang, &sd, &cd);
        tab[idx] = make_float2((float)cd, (float)sd);
    }
    if (idx >= 3 * n4) return;
    int sel = idx / n4;
    int i = idx - sel * n4;
    const float* x = (sel == 0) ? a : (sel == 1) ? b : c;
    float4 v = ((const float4*)x)[i];
    __half* o = dst + (size_t)sel * NTOT;
    ((uint32_t*)o)[2 * i + 0] = pack_h2(v.x, v.y);
    ((uint32_t*)o)[2 * i + 1] = pack_h2(v.z, v.w);
}

__global__ __launch_bounds__(256)
void cvt16x4w_kernel(const float* __restrict__ wq, const float* __restrict__ wk,
                     const float* __restrict__ wv, const float* __restrict__ wo,
                     __half* __restrict__ dqkv, __half* __restrict__ dwo, int n4)
{
    int idx = blockIdx.x * blockDim.x + threadIdx.x;
    if (idx >= 4 * n4) return;
    int sel = idx / n4;
    int i = idx - sel * n4;
    const float* x = (sel == 0) ? wq : (sel == 1) ? wk : (sel == 2) ? wv : wo;
    __half* o = (sel == 3) ? dwo : (dqkv + (size_t)sel * (D_ * D_));
    float4 v = ((const float4*)x)[i];
    ((uint32_t*)o)[2 * i + 0] = pack_h2(v.x, v.y);
    ((uint32_t*)o)[2 * i + 1] = pack_h2(v.z, v.w);
}

// ===========================================================================
// fp16 GEMM building blocks: 128x128 tile, BK=64, 3-stage cp.async, 2 CTA/SM.
// One __syncthreads per chunk.
// ===========================================================================
#define TILE_BYTES 16384                   // 128 rows x 128 B (128x64 fp16)
#define STAGE_BYTES (2 * TILE_BYTES)       // 32 KB (A + B)
#define GEMM_SMEM (3 * STAGE_BYTES)        // 96 KB -> 2 CTAs/SM
#define NCHUNK (D_ / 64)                   // 16
#define EPI_STRIDE 132                     // fp16 stride for epilogue tile

__device__ __forceinline__ void gemm_load_chunk(
    uint32_t sb, int stage, int k0, int tid,
    const __half* Ab, const __half* Bb)
{
    uint32_t base = sb + stage * STAGE_BYTES;
#pragma unroll
    for (int rep = 0; rep < 4; rep++) {
        int id  = tid + rep * 256;
        int row = id >> 3;
        int seg = id & 7;
        uint32_t soff = SMEM_SWIZZLE_128B((uint32_t)(row * 128 + seg * 16));
        size_t goff = (size_t)row * D_ + k0 + seg * 8;
        cpa16(base + 0 * TILE_BYTES + soff, Ab + goff);
        cpa16(base + 1 * TILE_BYTES + soff, Bb + goff);
    }
    asm volatile("cp.async.commit_group;" ::: "memory");
}

__device__ __forceinline__ void gemm_mainloop(
    uint32_t sb, int tid, const __half* Ab, const __half* Bb,
    int warp_m, int warp_n, int lane, float acc[4][4][4])
{
#pragma unroll
    for (int i = 0; i < 4; i++)
#pragma unroll
        for (int j = 0; j < 4; j++)
#pragma unroll
            for (int r = 0; r < 4; r++) acc[i][j][r] = 0.f;

    const int mat = lane >> 3;
    const int mrr = lane & 7;
    const int a_row_off = (mat & 1) * 8 + mrr;
    const int a_ks_off  = (mat >> 1) * 16;
    const int b_row_off = (mat >> 1) * 8 + mrr;
    const int b_ks_off  = (mat & 1) * 16;

    gemm_load_chunk(sb, 0, 0, tid, Ab, Bb);
    gemm_load_chunk(sb, 1, 64, tid, Ab, Bb);

    int stage = 0;
    for (int c = 0; c < NCHUNK; c++) {
        if (c + 1 < NCHUNK) {
            asm volatile("cp.async.wait_group 1;" ::: "memory");
        } else {
            asm volatile("cp.async.wait_group 0;" ::: "memory");
        }
        __syncthreads();

        if (c + 2 < NCHUNK) {
            int ls = stage + 2; if (ls >= 3) ls -= 3;
            gemm_load_chunk(sb, ls, (c + 2) * 64, tid, Ab, Bb);
        }

        uint32_t stA = sb + stage * STAGE_BYTES;
#pragma unroll
        for (int ks = 0; ks < 4; ks++) {
            const int kb = ks * 32;
            uint32_t ah[4][4];
#pragma unroll
            for (int mt = 0; mt < 4; mt++) {
                int row = warp_m * 64 + mt * 16 + a_row_off;
                uint32_t off = SMEM_SWIZZLE_128B((uint32_t)(row * 128 + kb + a_ks_off));
                ldsm4(ah[mt][0], ah[mt][1], ah[mt][2], ah[mt][3], stA + 0 * TILE_BYTES + off);
            }
            uint32_t bh[2][4];
#pragma unroll
            for (int p = 0; p < 2; p++) {
                int row = warp_n * 32 + p * 16 + b_row_off;
                uint32_t off = SMEM_SWIZZLE_128B((uint32_t)(row * 128 + kb + b_ks_off));
                ldsm4(bh[p][0], bh[p][1], bh[p][2], bh[p][3], stA + 1 * TILE_BYTES + off);
            }
#pragma unroll
            for (int mt = 0; mt < 4; mt++) {
#pragma unroll
                for (int p = 0; p < 2; p++) {
#pragma unroll
                    for (int q = 0; q < 2; q++) {
                        mma_fp16(acc[mt][p * 2 + q], ah[mt], bh[p][q * 2], bh[p][q * 2 + 1]);
                    }
                }
            }
        }
        stage++; if (stage >= 3) stage = 0;
    }
    __syncthreads();   // protect smem reuse by epilogue
}

// ---------------------------------------------------------------------------
// Fused QKV projection + RoPE-in-epilogue for Q/K. Q additionally pre-scaled
// by 1/sqrt(HD)=0.125 (exact power-of-2: commutes with fp16 rounding).
// ---------------------------------------------------------------------------
__global__ __launch_bounds__(256, 2)
void gemm_qkv(const __half* __restrict__ X3, const __half* __restrict__ Wqkv,
              const float* __restrict__ bq, const float* __restrict__ bk,
              const float* __restrict__ bv, const float2* __restrict__ rope,
              __half* __restrict__ Qo, __half* __restrict__ Ko, __half* __restrict__ Vo)
{
    extern __shared__ char smem[];
    uint32_t sb = smem_to_u32(smem);
    const int tid  = threadIdx.x;
    const int wid  = tid >> 5;
    const int lane = tid & 31;
    const int warp_m = wid >> 2;
    const int warp_n = wid & 3;
    const int bn = blockIdx.x, bm = blockIdx.y;
    const int sel = bn >> 3;          // 0=Q, 1=K, 2=V
    const int bnl = bn & 7;

    const __half* Ab = X3 + (size_t)sel * NTOT + (size_t)(bm * 128) * D_;
    const __half* Bb = Wqkv + (size_t)sel * D_ * D_ + (size_t)(bnl * 128) * D_;
    const float* bias = (sel == 0) ? bq : (sel == 1) ? bk : bv;
    __half* Co = (sel == 0) ? Qo : (sel == 1) ? Ko : Vo;

    float acc[4][4][4];
    gemm_mainloop(sb, tid, Ab, Bb, warp_m, warp_n, lane, acc);

    const int rloc = warp_m * 64 + (lane >> 2);
    const int cloc = warp_n * 32 + (lane & 3) * 2;

    if (sel == 2) {
        const int rbase = bm * 128 + rloc;
        const int cbase = bnl * 128 + cloc;
#pragma unroll
        for (int mt = 0; mt < 4; mt++) {
#pragma unroll
            for (int nt = 0; nt < 4; nt++) {
                int col = cbase + nt * 8;
                float b0 = bias[col], b1 = bias[col + 1];
                float* d = acc[mt][nt];
                int r0 = rbase + mt * 16;
                *(uint32_t*)(Co + (size_t)r0 * D_ + col)       = pack_h2(d[0] + b0, d[1] + b1);
                *(uint32_t*)(Co + (size_t)(r0 + 8) * D_ + col) = pack_h2(d[2] + b0, d[3] + b1);
            }
        }
    } else {
        __half* T = (__half*)smem;
#pragma unroll
        for (int mt = 0; mt < 4; mt++) {
#pragma unroll
            for (int nt = 0; nt < 4; nt++) {
                int col = cloc + nt * 8;
                int gcol = bnl * 128 + col;
                float b0 = bias[gcol], b1 = bias[gcol + 1];
                float* d = acc[mt][nt];
                int r0 = rloc + mt * 16;
                *(uint32_t*)(T + (size_t)r0 * EPI_STRIDE + col)       = pack_h2(d[0] + b0, d[1] + b1);
                *(uint32_t*)(T + (size_t)(r0 + 8) * EPI_STRIDE + col) = pack_h2(d[2] + b0, d[3] + b1);
            }
        }
        __syncthreads();

        const float qs = (sel == 0) ? 0.125f : 1.0f;   // fold 1/sqrt(HD) into Q
        for (int it = tid; it < 128 * 2 * 16; it += 256) {
            int dq  = it & 15;
            int hh  = (it >> 4) & 1;
            int row = it >> 5;
            int d   = dq * 2;
            int colA = hh * 64 + d;

            __half2 a2 = *(__half2*)(T + (size_t)row * EPI_STRIDE + colA);
            __half2 b2 = *(__half2*)(T + (size_t)row * EPI_STRIDE + colA + 32);
            float2 a = __half22float2(a2);
            float2 b = __half22float2(b2);

            int grow = bm * 128 + row;
            int s = grow & (S_ - 1);
            float2 t0 = rope[s * 32 + d];
            float2 t1 = rope[s * 32 + d + 1];

            float rx0 = fmaf(a.x, t0.x, -b.x * t0.y) * qs, ry0 = fmaf(a.x, t0.y, b.x * t0.x) * qs;
            float rx1 = fmaf(a.y, t1.x, -b.y * t1.y) * qs, ry1 = fmaf(a.y, t1.y, b.y * t1.x) * qs;

            size_t goff = (size_t)grow * D_ + bnl * 128 + colA;
            *(uint32_t*)(Co + goff)      = pack_h2(rx0, rx1);
            *(uint32_t*)(Co + goff + 32) = pack_h2(ry0, ry1);
        }
    }
}

// ---------------------------------------------------------------------------
// Output projection GEMM: fp16 in, fp32 out.
// ---------------------------------------------------------------------------
__global__ __launch_bounds__(256, 2)
void gemm_out(const __half* __restrict__ A, const __half* __restrict__ W,
              const float* __restrict__ bias, float* __restrict__ C)
{
    extern __shared__ char smem[];
    uint32_t sb = smem_to_u32(smem);
    const int tid  = threadIdx.x;
    const int wid  = tid >> 5;
    const int lane = tid & 31;
    const int warp_m = wid >> 2;
    const int warp_n = wid & 3;
    const int bn = blockIdx.x, bm = blockIdx.y;

    const __half* Ab = A + (size_t)(bm * 128) * D_;
    const __half* Bb = W + (size_t)(bn * 128) * D_;

    float acc[4][4][4];
    gemm_mainloop(sb, tid, Ab, Bb, warp_m, warp_n, lane, acc);

    const int rbase = bm * 128 + warp_m * 64 + (lane >> 2);
    const int cbase = bn * 128 + warp_n * 32 + (lane & 3) * 2;
#pragma unroll
    for (int mt = 0; mt < 4; mt++) {
#pragma unroll
        for (int nt = 0; nt < 4; nt++) {
            int col = cbase + nt * 8;
            float b0 = bias[col], b1 = bias[col + 1];
            float* d = acc[mt][nt];
            int r0 = rbase + mt * 16;
            *(float2*)(C + (size_t)r0 * D_ + col)       = make_float2(d[0] + b0, d[1] + b1);
            *(float2*)(C + (size_t)(r0 + 8) * D_ + col) = make_float2(d[2] + b0, d[3] + b1);
        }
    }
}

// ===========================================================================
// Tensor-core flash attention, all-fp16 MMA. BM=128.
// Scores arrive pre-scaled (Q carries 1/sqrt(HD)). Mask only on diag tiles.
// 128-row KV stages, two 64-wide sub-tiles per window, one sync/window.
// ===========================================================================
#define FQ 0
#define FST 16384
#define FK 0
#define FV 16384
#define FSTAGE 32768
#define FLASH_SMEM (16384 + 2 * FSTAGE)   // 81920 -> 2 CTA/SM

__device__ __forceinline__ void flash_load_kv128(
    uint32_t sb, int stage, int kt2, int tid,
    const __half* Kb, const __half* Vb)
{
    uint32_t base = sb + FST + stage * FSTAGE;
    size_t rbase = (size_t)(kt2 * 128) * D_;
#pragma unroll
    for (int rep = 0; rep < 4; rep++) {
        int id  = tid + rep * 256;
        int row = id >> 3;
        int seg = id & 7;
        uint32_t soff = SMEM_SWIZZLE_128B((uint32_t)(row * 128 + seg * 16));
        size_t goff = rbase + (size_t)row * D_ + seg * 8;
        cpa16(base + FK + soff, Kb + goff);
        cpa16(base + FV + soff, Vb + goff);
    }
    asm volatile("cp.async.commit_group;" ::: "memory");
}

__global__ __launch_bounds__(256, 2)
void flash_mma(const __half* __restrict__ Q_g, const __half* __restrict__ K_g,
               const __half* __restrict__ V_g, __half* __restrict__ O_g)
{
    extern __shared__ char smem[];
    uint32_t sb = smem_to_u32(smem);
    const int tid  = threadIdx.x;
    const int wid  = tid >> 5;
    const int lane = tid & 31;
    const int qt = (int)(gridDim.x - 1 - blockIdx.x);   // heavy tiles first
    const int h = blockIdx.y, b = blockIdx.z;

    const int g = lane >> 2, c = lane & 3;
    const int mat = lane >> 3, mrr = lane & 7;
    const int a_row_off = (mat & 1) * 8 + mrr;
    const int a_ks_off  = (mat >> 1) * 16;
    const int b_row_off = (mat >> 1) * 8 + mrr;
    const int b_ks_off  = (mat & 1) * 16;
    const int v_l = lane & 7, v_half = (lane >> 3) & 1, v_quad = lane >> 4;

    const size_t hoff = (size_t)(b * S_) * D_ + h * HD_;
    const __half* Qb = Q_g + hoff + (size_t)(qt * 128) * D_;
    const __half* Kb = K_g + hoff;
    const __half* Vb = V_g + hoff;

#pragma unroll
    for (int rep = 0; rep < 4; rep++) {
        int id  = tid + rep * 256;
        int row = id >> 3;
        int seg = id & 7;
        uint32_t soff = SMEM_SWIZZLE_128B((uint32_t)(row * 128 + seg * 16));
        size_t goff = (size_t)row * D_ + seg * 8;
        cpa16(sb + FQ + soff, Qb + goff);
    }
    asm volatile("cp.async.commit_group;" ::: "memory");

    flash_load_kv128(sb, 0, 0, tid, Kb, Vb);
    asm volatile("cp.async.wait_group 0;" ::: "memory");
    __syncthreads();

    uint32_t qf[4][4];
#pragma unroll
    for (int t = 0; t < 4; t++) {
        int rowA = wid * 16 + a_row_off;
        uint32_t off = SMEM_SWIZZLE_128B((uint32_t)(rowA * 128 + t * 32 + a_ks_off));
        ldsm4(qf[t][0], qf[t][1], qf[t][2], qf[t][3], sb + FQ + off);
    }

    float mi0 = -INFINITY, mi1 = -INFINITY, li0 = 0.f, li1 = 0.f;
    float o[8][4];
#pragma unroll
    for (int j = 0; j < 8; j++)
#pragma unroll
        for (int r = 0; r < 4; r++) o[j][r] = 0.f;

    const int wrow = qt * 128 + wid * 16;

    for (int kt2 = 0; kt2 <= qt; kt2++) {
        int s = kt2 & 1;
        if (kt2 > 0) {
            asm volatile("cp.async.wait_group 0;" ::: "memory");
            __syncthreads();
        }
        if (kt2 < qt) {
            flash_load_kv128(sb, s ^ 1, kt2 + 1, tid, Kb, Vb);
        }

        uint32_t st = sb + FST + s * FSTAGE;

#pragma unroll
        for (int sub = 0; sub < 2; sub++) {
            const int kbase = kt2 * 128 + sub * 64;
            if (kbase > wrow + 15) continue;

            float sc[8][4];
#pragma unroll
            for (int j = 0; j < 8; j++)
#pragma unroll
                for (int r = 0; r < 4; r++) sc[j][r] = 0.f;

#pragma unroll
            for (int t = 0; t < 4; t++) {
#pragma unroll
                for (int p = 0; p < 4; p++) {
                    uint32_t k4[4];
                    int rowB = sub * 64 + p * 16 + b_row_off;
                    uint32_t off = SMEM_SWIZZLE_128B((uint32_t)(rowB * 128 + t * 32 + b_ks_off));
                    ldsm4(k4[0], k4[1], k4[2], k4[3], st + FK + off);
                    mma_fp16(sc[2 * p],     qf[t], k4[0], k4[1]);
                    mma_fp16(sc[2 * p + 1], qf[t], k4[2], k4[3]);
                }
            }

            // Scores arrive pre-scaled; mask only on diagonal sub-tiles.
            const int row0 = wrow + g, row1 = row0 + 8;
            if (kbase + 63 > wrow) {
#pragma unroll
                for (int j = 0; j < 8; j++) {
                    int col0 = kbase + j * 8 + 2 * c, col1 = col0 + 1;
                    if (col0 > row0) sc[j][0] = -INFINITY;
                    if (col1 > row0) sc[j][1] = -INFINITY;
                    if (col0 > row1) sc[j][2] = -INFINITY;
                    if (col1 > row1) sc[j][3] = -INFINITY;
                }
            }
            float rm0 = -INFINITY, rm1 = -INFINITY;
#pragma unroll
            for (int j = 0; j < 8; j++) {
                rm0 = fmaxf(rm0, fmaxf(sc[j][0], sc[j][1]));
                rm1 = fmaxf(rm1, fmaxf(sc[j][2], sc[j][3]));
            }
            rm0 = fmaxf(rm0, __shfl_xor_sync(0xffffffffu, rm0, 1));
            rm0 = fmaxf(rm0, __shfl_xor_sync(0xffffffffu, rm0, 2));
            rm1 = fmaxf(rm1, __shfl_xor_sync(0xffffffffu, rm1, 1));
            rm1 = fmaxf(rm1, __shfl_xor_sync(0xffffffffu, rm1, 2));

            float mn0 = fmaxf(mi0, rm0), mn1 = fmaxf(mi1, rm1);
            float al0 = __expf(mi0 - mn0), al1 = __expf(mi1 - mn1);
            float rs0 = 0.f, rs1 = 0.f;
#pragma unroll
            for (int j = 0; j < 8; j++) {
                sc[j][0] = __expf(sc[j][0] - mn0);
                sc[j][1] = __expf(sc[j][1] - mn0);
                sc[j][2] = __expf(sc[j][2] - mn1);
                sc[j][3] = __expf(sc[j][3] - mn1);
                rs0 += sc[j][0] + sc[j][1];
                rs1 += sc[j][2] + sc[j][3];
            }
            rs0 += __shfl_xor_sync(0xffffffffu, rs0, 1);
            rs0 += __shfl_xor_sync(0xffffffffu, rs0, 2);
            rs1 += __shfl_xor_sync(0xffffffffu, rs1, 1);
            rs1 += __shfl_xor_sync(0xffffffffu, rs1, 2);
            li0 = li0 * al0 + rs0; li1 = li1 * al1 + rs1;
            mi0 = mn0; mi1 = mn1;
#pragma unroll
            for (int j = 0; j < 8; j++) {
                o[j][0] *= al0; o[j][1] *= al0;
                o[j][2] *= al1; o[j][3] *= al1;
            }

            uint32_t ph[4][4];
#pragma unroll
            for (int t = 0; t < 4; t++) {
                ph[t][0] = pack_h2(sc[2 * t][0],     sc[2 * t][1]);
                ph[t][1] = pack_h2(sc[2 * t][2],     sc[2 * t][3]);
                ph[t][2] = pack_h2(sc[2 * t + 1][0], sc[2 * t + 1][1]);
                ph[t][3] = pack_h2(sc[2 * t + 1][2], sc[2 * t + 1][3]);
            }

#pragma unroll
            for (int t = 0; t < 4; t++) {
#pragma unroll
                for (int jp = 0; jp < 4; jp++) {
                    uint32_t soff = SMEM_SWIZZLE_128B(
                        (uint32_t)((sub * 64 + 16 * t + v_half * 8 + v_l) * 128 + jp * 32 + v_quad * 16));
                    uint32_t v4[4];
                    ldsm4t(v4[0], v4[1], v4[2], v4[3], st + FV + soff);
                    mma_fp16(o[2 * jp],     ph[t], v4[0], v4[1]);
                    mma_fp16(o[2 * jp + 1], ph[t], v4[2], v4[3]);
                }
            }
        }
    }

    float iv0 = 1.f / li0, iv1 = 1.f / li1;
    size_t r0off = ((size_t)(b * S_ + wrow + g)) * D_ + h * HD_;
    size_t r1off = r0off + 8 * D_;
#pragma unroll
    for (int j = 0; j < 8; j++) {
        int col = j * 8 + 2 * c;
        *(uint32_t*)(O_g + r0off + col) = pack_h2(o[j][0] * iv0, o[j][1] * iv0);
        *(uint32_t*)(O_g + r1off + col) = pack_h2(o[j][2] * iv1, o[j][3] * iv1);
    }
}

// ---------------------------------------------------------------------------
extern "C" void kernel_launch(void* const* d_in, const int* in_sizes, int n_in,
                              void* d_out, int out_size)
{
    const float* Q  = (const float*)d_in[0];
    const float* K  = (const float*)d_in[1];
    const float* V  = (const float*)d_in[2];
    const float* Wq = (const float*)d_in[3];
    const float* bq = (const float*)d_in[4];
    const float* Wk = (const float*)d_in[5];
    const float* bk = (const float*)d_in[6];
    const float* Wv = (const float*)d_in[7];
    const float* bv = (const float*)d_in[8];
    const float* Wo = (const float*)d_in[9];
    const float* bo = (const float*)d_in[10];
    float* out = (float*)d_out;

    float2* grope;
    __half *gx3, *gwqkv, *gw16, *gq16, *gk16, *gv16, *go16;
    cudaGetSymbolAddress((void**)&grope, g_rope);
    cudaGetSymbolAddress((void**)&gx3, g_x3);
    cudaGetSymbolAddress((void**)&gwqkv, g_wqkv);
    cudaGetSymbolAddress((void**)&gw16, g_w16);
    cudaGetSymbolAddress((void**)&gq16, g_q16);
    cudaGetSymbolAddress((void**)&gk16, g_k16);
    cudaGetSymbolAddress((void**)&gv16, g_v16);
    cudaGetSymbolAddress((void**)&go16, g_o16);

    cudaFuncSetAttribute(gemm_qkv, cudaFuncAttributeMaxDynamicSharedMemorySize, GEMM_SMEM);
    cudaFuncSetAttribute(gemm_out, cudaFuncAttributeMaxDynamicSharedMemorySize, GEMM_SMEM);
    cudaFuncSetAttribute(flash_mma, cudaFuncAttributeMaxDynamicSharedMemorySize, FLASH_SMEM);

    const int n4x = NTOT / 4;
    const int n4w = (D_ * D_) / 4;

    cvt16x3_kernel<<<(3 * n4x + 255) / 256, 256>>>(Q, K, V, gx3, grope, n4x);
    cvt16x4w_kernel<<<(4 * n4w + 255) / 256, 256>>>(Wq, Wk, Wv, Wo, gwqkv, gw16, n4w);

    dim3 qkvgrid(3 * D_ / 128, M_ / 128);
    gemm_qkv<<<qkvgrid, 256, GEMM_SMEM>>>(gx3, gwqkv, bq, bk, bv, grope,
                                          gq16, gk16, gv16);

    dim3 fgrid(S_ / 128, H_, B_);
    flash_mma<<<fgrid, 256, FLASH_SMEM>>>(gq16, gk16, gv16, go16);

    dim3 ogrid(D_ / 128, M_ / 128);
    gemm_out<<<ogrid, 256, GEMM_SMEM>>>(go16, gw16, bo, out);
}

// round 16
// speedup vs baseline: 2.9391x; 1.0313x over previous
#include <cuda_runtime.h>
#include <cuda_fp16.h>
#include <math.h>
#include <stdint.h>

#define B_  4
#define S_  2048
#define D_  1024
#define H_  16
#define HD_ 64
#define M_  (B_ * S_)
#define NTOT (B_ * S_ * D_)

// Scratch (allocation-free rule: __device__ globals)
__device__ __half g_x3[3 * NTOT];        // packed Q16, K16, V16 inputs
__device__ __half g_wqkv[3 * D_ * D_];   // packed Wq, Wk, Wv fp16
__device__ __half g_w16[D_ * D_];        // Wo fp16
__device__ __half g_q16[NTOT];
__device__ __half g_k16[NTOT];
__device__ __half g_v16[NTOT];
__device__ __half g_o16[NTOT];
__device__ float2 g_rope[S_ * 32];

// ===========================================================================
// Helpers (baseline PTX only — compute_103-safe)
// ===========================================================================
__device__ __forceinline__ uint32_t smem_to_u32(const void* p) {
    uint32_t a;
    asm("{ .reg .u64 t; cvta.to.shared.u64 t, %1; cvt.u32.u64 %0, t; }" : "=r"(a) : "l"(p));
    return a;
}
#define SMEM_SWIZZLE_128B(off) ((off) ^ (((off) >> 3) & 0x70))

__device__ __forceinline__ void cpa16(uint32_t dst, const void* src) {
    asm volatile("cp.async.cg.shared.global [%0], [%1], 16;" :: "r"(dst), "l"(src));
}
__device__ __forceinline__ void ldsm4(uint32_t& r0, uint32_t& r1, uint32_t& r2, uint32_t& r3,
                                      uint32_t addr) {
    asm volatile("ldmatrix.sync.aligned.m8n8.x4.shared.b16 {%0,%1,%2,%3}, [%4];"
        : "=r"(r0), "=r"(r1), "=r"(r2), "=r"(r3) : "r"(addr));
}
__device__ __forceinline__ void ldsm4t(uint32_t& r0, uint32_t& r1, uint32_t& r2, uint32_t& r3,
                                       uint32_t addr) {
    asm volatile("ldmatrix.sync.aligned.m8n8.x4.trans.shared.b16 {%0,%1,%2,%3}, [%4];"
        : "=r"(r0), "=r"(r1), "=r"(r2), "=r"(r3) : "r"(addr));
}
__device__ __forceinline__ void mma_fp16(float* d, const uint32_t* a,
                                         uint32_t b0, uint32_t b1) {
    asm volatile(
        "mma.sync.aligned.m16n8k16.row.col.f32.f16.f16.f32 "
        "{%0,%1,%2,%3}, {%4,%5,%6,%7}, {%8,%9}, {%0,%1,%2,%3};"
        : "+f"(d[0]), "+f"(d[1]), "+f"(d[2]), "+f"(d[3])
        : "r"(a[0]), "r"(a[1]), "r"(a[2]), "r"(a[3]), "r"(b0), "r"(b1));
}
__device__ __forceinline__ uint32_t pack_h2(float f0, float f1) {
    __half2 h = __floats2half2_rn(f0, f1);
    return *(uint32_t*)&h;
}

// ===========================================================================
// Fused fp32 -> fp16 converts. cvt16x3 also builds the RoPE table.
// ===========================================================================
__global__ __launch_bounds__(256)
void cvt16x3_kernel(const float* __restrict__ a, const float* __restrict__ b,
                    const float* __restrict__ c, __half* __restrict__ dst,
                    float2* __restrict__ tab, int n4)
{
    int idx = blockIdx.x * blockDim.x + threadIdx.x;
    if (idx < S_ * 32) {
        int s = idx >> 5;
        int d = idx & 31;
        double inv = exp(-log(10000.0) * (double)d / 32.0);
        double ang = (double)s * inv;
        double sd, cd;
        sincos(ang, &sd, &cd);
        tab[idx] = make_float2((float)cd, (float)sd);
    }
    if (idx >= 3 * n4) return;
    int sel = idx / n4;
    int i = idx - sel * n4;
    const float* x = (sel == 0) ? a : (sel == 1) ? b : c;
    float4 v = ((const float4*)x)[i];
    __half* o = dst + (size_t)sel * NTOT;
    ((uint32_t*)o)[2 * i + 0] = pack_h2(v.x, v.y);
    ((uint32_t*)o)[2 * i + 1] = pack_h2(v.z, v.w);
}

__global__ __launch_bounds__(256)
void cvt16x4w_kernel(const float* __restrict__ wq, const float* __restrict__ wk,
                     const float* __restrict__ wv, const float* __restrict__ wo,
                     __half* __restrict__ dqkv, __half* __restrict__ dwo, int n4)
{
    int idx = blockIdx.x * blockDim.x + threadIdx.x;
    if (idx >= 4 * n4) return;
    int sel = idx / n4;
    int i = idx - sel * n4;
    const float* x = (sel == 0) ? wq : (sel == 1) ? wk : (sel == 2) ? wv : wo;
    __half* o = (sel == 3) ? dwo : (dqkv + (size_t)sel * (D_ * D_));
    float4 v = ((const float4*)x)[i];
    ((uint32_t*)o)[2 * i + 0] = pack_h2(v.x, v.y);
    ((uint32_t*)o)[2 * i + 1] = pack_h2(v.z, v.w);
}

// ===========================================================================
// fp16 GEMM building blocks: 128x128 tile, BK=64, 3-stage cp.async, 2 CTA/SM.
// ===========================================================================
#define TILE_BYTES 16384                   // 128 rows x 128 B (128x64 fp16)
#define STAGE_BYTES (2 * TILE_BYTES)       // 32 KB (A + B)
#define GEMM_SMEM (3 * STAGE_BYTES)        // 96 KB -> 2 CTAs/SM
#define NCHUNK (D_ / 64)                   // 16
#define EPI_STRIDE 132                     // fp16 stride for epilogue tile

__device__ __forceinline__ void gemm_load_chunk(
    uint32_t sb, int stage, int k0, int tid,
    const __half* Ab, const __half* Bb)
{
    uint32_t base = sb + stage * STAGE_BYTES;
#pragma unroll
    for (int rep = 0; rep < 4; rep++) {
        int id  = tid + rep * 256;
        int row = id >> 3;
        int seg = id & 7;
        uint32_t soff = SMEM_SWIZZLE_128B((uint32_t)(row * 128 + seg * 16));
        size_t goff = (size_t)row * D_ + k0 + seg * 8;
        cpa16(base + 0 * TILE_BYTES + soff, Ab + goff);
        cpa16(base + 1 * TILE_BYTES + soff, Bb + goff);
    }
    asm volatile("cp.async.commit_group;" ::: "memory");
}

__device__ __forceinline__ void gemm_mainloop(
    uint32_t sb, int tid, const __half* Ab, const __half* Bb,
    int warp_m, int warp_n, int lane, float acc[4][4][4])
{
#pragma unroll
    for (int i = 0; i < 4; i++)
#pragma unroll
        for (int j = 0; j < 4; j++)
#pragma unroll
            for (int r = 0; r < 4; r++) acc[i][j][r] = 0.f;

    const int mat = lane >> 3;
    const int mrr = lane & 7;
    const int a_row_off = (mat & 1) * 8 + mrr;
    const int a_ks_off  = (mat >> 1) * 16;
    const int b_row_off = (mat >> 1) * 8 + mrr;
    const int b_ks_off  = (mat & 1) * 16;

    gemm_load_chunk(sb, 0, 0, tid, Ab, Bb);
    gemm_load_chunk(sb, 1, 64, tid, Ab, Bb);

    int stage = 0;
    for (int c = 0; c < NCHUNK; c++) {
        if (c + 1 < NCHUNK) {
            asm volatile("cp.async.wait_group 1;" ::: "memory");
        } else {
            asm volatile("cp.async.wait_group 0;" ::: "memory");
        }
        __syncthreads();

        if (c + 2 < NCHUNK) {
            int ls = stage + 2; if (ls >= 3) ls -= 3;
            gemm_load_chunk(sb, ls, (c + 2) * 64, tid, Ab, Bb);
        }

        uint32_t stA = sb + stage * STAGE_BYTES;
#pragma unroll
        for (int ks = 0; ks < 4; ks++) {
            const int kb = ks * 32;
            uint32_t ah[4][4];
#pragma unroll
            for (int mt = 0; mt < 4; mt++) {
                int row = warp_m * 64 + mt * 16 + a_row_off;
                uint32_t off = SMEM_SWIZZLE_128B((uint32_t)(row * 128 + kb + a_ks_off));
                ldsm4(ah[mt][0], ah[mt][1], ah[mt][2], ah[mt][3], stA + 0 * TILE_BYTES + off);
            }
            uint32_t bh[2][4];
#pragma unroll
            for (int p = 0; p < 2; p++) {
                int row = warp_n * 32 + p * 16 + b_row_off;
                uint32_t off = SMEM_SWIZZLE_128B((uint32_t)(row * 128 + kb + b_ks_off));
                ldsm4(bh[p][0], bh[p][1], bh[p][2], bh[p][3], stA + 1 * TILE_BYTES + off);
            }
#pragma unroll
            for (int mt = 0; mt < 4; mt++) {
#pragma unroll
                for (int p = 0; p < 2; p++) {
#pragma unroll
                    for (int q = 0; q < 2; q++) {
                        mma_fp16(acc[mt][p * 2 + q], ah[mt], bh[p][q * 2], bh[p][q * 2 + 1]);
                    }
                }
            }
        }
        stage++; if (stage >= 3) stage = 0;
    }
    __syncthreads();   // protect smem reuse by epilogue
}

// ---------------------------------------------------------------------------
// Fused QKV projection + RoPE-in-epilogue for Q/K. Q pre-scaled by
// log2(e)/sqrt(HD) so flash scores are in log2 domain (exp2f = 1 MUFU).
// ---------------------------------------------------------------------------
__global__ __launch_bounds__(256, 2)
void gemm_qkv(const __half* __restrict__ X3, const __half* __restrict__ Wqkv,
              const float* __restrict__ bq, const float* __restrict__ bk,
              const float* __restrict__ bv, const float2* __restrict__ rope,
              __half* __restrict__ Qo, __half* __restrict__ Ko, __half* __restrict__ Vo)
{
    extern __shared__ char smem[];
    uint32_t sb = smem_to_u32(smem);
    const int tid  = threadIdx.x;
    const int wid  = tid >> 5;
    const int lane = tid & 31;
    const int warp_m = wid >> 2;
    const int warp_n = wid & 3;
    const int bn = blockIdx.x, bm = blockIdx.y;
    const int sel = bn >> 3;          // 0=Q, 1=K, 2=V
    const int bnl = bn & 7;

    const __half* Ab = X3 + (size_t)sel * NTOT + (size_t)(bm * 128) * D_;
    const __half* Bb = Wqkv + (size_t)sel * D_ * D_ + (size_t)(bnl * 128) * D_;
    const float* bias = (sel == 0) ? bq : (sel == 1) ? bk : bv;
    __half* Co = (sel == 0) ? Qo : (sel == 1) ? Ko : Vo;

    float acc[4][4][4];
    gemm_mainloop(sb, tid, Ab, Bb, warp_m, warp_n, lane, acc);

    const int rloc = warp_m * 64 + (lane >> 2);
    const int cloc = warp_n * 32 + (lane & 3) * 2;

    if (sel == 2) {
        const int rbase = bm * 128 + rloc;
        const int cbase = bnl * 128 + cloc;
#pragma unroll
        for (int mt = 0; mt < 4; mt++) {
#pragma unroll
            for (int nt = 0; nt < 4; nt++) {
                int col = cbase + nt * 8;
                float b0 = bias[col], b1 = bias[col + 1];
                float* d = acc[mt][nt];
                int r0 = rbase + mt * 16;
                *(uint32_t*)(Co + (size_t)r0 * D_ + col)       = pack_h2(d[0] + b0, d[1] + b1);
                *(uint32_t*)(Co + (size_t)(r0 + 8) * D_ + col) = pack_h2(d[2] + b0, d[3] + b1);
            }
        }
    } else {
        __half* T = (__half*)smem;
#pragma unroll
        for (int mt = 0; mt < 4; mt++) {
#pragma unroll
            for (int nt = 0; nt < 4; nt++) {
                int col = cloc + nt * 8;
                int gcol = bnl * 128 + col;
                float b0 = bias[gcol], b1 = bias[gcol + 1];
                float* d = acc[mt][nt];
                int r0 = rloc + mt * 16;
                *(uint32_t*)(T + (size_t)r0 * EPI_STRIDE + col)       = pack_h2(d[0] + b0, d[1] + b1);
                *(uint32_t*)(T + (size_t)(r0 + 8) * EPI_STRIDE + col) = pack_h2(d[2] + b0, d[3] + b1);
            }
        }
        __syncthreads();

        // Q scale: 1/sqrt(HD) * log2(e) -> flash works in exp2 domain.
        const float qs = (sel == 0) ? 0.125f * 1.4426950408889634f : 1.0f;
        for (int it = tid; it < 128 * 2 * 16; it += 256) {
            int dq  = it & 15;
            int hh  = (it >> 4) & 1;
            int row = it >> 5;
            int d   = dq * 2;
            int colA = hh * 64 + d;

            __half2 a2 = *(__half2*)(T + (size_t)row * EPI_STRIDE + colA);
            __half2 b2 = *(__half2*)(T + (size_t)row * EPI_STRIDE + colA + 32);
            float2 a = __half22float2(a2);
            float2 b = __half22float2(b2);

            int grow = bm * 128 + row;
            int s = grow & (S_ - 1);
            float2 t0 = rope[s * 32 + d];
            float2 t1 = rope[s * 32 + d + 1];

            float rx0 = fmaf(a.x, t0.x, -b.x * t0.y) * qs, ry0 = fmaf(a.x, t0.y, b.x * t0.x) * qs;
            float rx1 = fmaf(a.y, t1.x, -b.y * t1.y) * qs, ry1 = fmaf(a.y, t1.y, b.y * t1.x) * qs;

            size_t goff = (size_t)grow * D_ + bnl * 128 + colA;
            *(uint32_t*)(Co + goff)      = pack_h2(rx0, rx1);
            *(uint32_t*)(Co + goff + 32) = pack_h2(ry0, ry1);
        }
    }
}

// ---------------------------------------------------------------------------
// Output projection GEMM: fp16 in, fp32 out.
// ---------------------------------------------------------------------------
__global__ __launch_bounds__(256, 2)
void gemm_out(const __half* __restrict__ A, const __half* __restrict__ W,
              const float* __restrict__ bias, float* __restrict__ C)
{
    extern __shared__ char smem[];
    uint32_t sb = smem_to_u32(smem);
    const int tid  = threadIdx.x;
    const int wid  = tid >> 5;
    const int lane = tid & 31;
    const int warp_m = wid >> 2;
    const int warp_n = wid & 3;
    const int bn = blockIdx.x, bm = blockIdx.y;

    const __half* Ab = A + (size_t)(bm * 128) * D_;
    const __half* Bb = W + (size_t)(bn * 128) * D_;

    float acc[4][4][4];
    gemm_mainloop(sb, tid, Ab, Bb, warp_m, warp_n, lane, acc);

    const int rbase = bm * 128 + warp_m * 64 + (lane >> 2);
    const int cbase = bn * 128 + warp_n * 32 + (lane & 3) * 2;
#pragma unroll
    for (int mt = 0; mt < 4; mt++) {
#pragma unroll
        for (int nt = 0; nt < 4; nt++) {
            int col = cbase + nt * 8;
            float b0 = bias[col], b1 = bias[col + 1];
            float* d = acc[mt][nt];
            int r0 = rbase + mt * 16;
            *(float2*)(C + (size_t)r0 * D_ + col)       = make_float2(d[0] + b0, d[1] + b1);
            *(float2*)(C + (size_t)(r0 + 8) * D_ + col) = make_float2(d[2] + b0, d[3] + b1);
        }
    }
}

// ===========================================================================
// Tensor-core flash attention, all-fp16 MMA. BM=128.
// exp2 domain (Q carries log2e/sqrt(HD)). Row-sums via ones-MMA.
// 128-row KV stages, two 64-wide sub-tiles per window, one sync/window.
// ===========================================================================
#define FQ 0
#define FST 16384
#define FK 0
#define FV 16384
#define FSTAGE 32768
#define FLASH_SMEM (16384 + 2 * FSTAGE)   // 81920 -> 2 CTA/SM
#define H2_ONES 0x3C003C00u

__device__ __forceinline__ void flash_load_kv128(
    uint32_t sb, int stage, int kt2, int tid,
    const __half* Kb, const __half* Vb)
{
    uint32_t base = sb + FST + stage * FSTAGE;
    size_t rbase = (size_t)(kt2 * 128) * D_;
#pragma unroll
    for (int rep = 0; rep < 4; rep++) {
        int id  = tid + rep * 256;
        int row = id >> 3;
        int seg = id & 7;
        uint32_t soff = SMEM_SWIZZLE_128B((uint32_t)(row * 128 + seg * 16));
        size_t goff = rbase + (size_t)row * D_ + seg * 8;
        cpa16(base + FK + soff, Kb + goff);
        cpa16(base + FV + soff, Vb + goff);
    }
    asm volatile("cp.async.commit_group;" ::: "memory");
}

__global__ __launch_bounds__(256, 2)
void flash_mma(const __half* __restrict__ Q_g, const __half* __restrict__ K_g,
               const __half* __restrict__ V_g, __half* __restrict__ O_g)
{
    extern __shared__ char smem[];
    uint32_t sb = smem_to_u32(smem);
    const int tid  = threadIdx.x;
    const int wid  = tid >> 5;
    const int lane = tid & 31;
    const int qt = (int)(gridDim.x - 1 - blockIdx.x);   // heavy tiles first
    const int h = blockIdx.y, b = blockIdx.z;

    const int g = lane >> 2, c = lane & 3;
    const int mat = lane >> 3, mrr = lane & 7;
    const int a_row_off = (mat & 1) * 8 + mrr;
    const int a_ks_off  = (mat >> 1) * 16;
    const int b_row_off = (mat >> 1) * 8 + mrr;
    const int b_ks_off  = (mat & 1) * 16;
    const int v_l = lane & 7, v_half = (lane >> 3) & 1, v_quad = lane >> 4;

    const size_t hoff = (size_t)(b * S_) * D_ + h * HD_;
    const __half* Qb = Q_g + hoff + (size_t)(qt * 128) * D_;
    const __half* Kb = K_g + hoff;
    const __half* Vb = V_g + hoff;

#pragma unroll
    for (int rep = 0; rep < 4; rep++) {
        int id  = tid + rep * 256;
        int row = id >> 3;
        int seg = id & 7;
        uint32_t soff = SMEM_SWIZZLE_128B((uint32_t)(row * 128 + seg * 16));
        size_t goff = (size_t)row * D_ + seg * 8;
        cpa16(sb + FQ + soff, Qb + goff);
    }
    asm volatile("cp.async.commit_group;" ::: "memory");

    flash_load_kv128(sb, 0, 0, tid, Kb, Vb);
    asm volatile("cp.async.wait_group 0;" ::: "memory");
    __syncthreads();

    uint32_t qf[4][4];
#pragma unroll
    for (int t = 0; t < 4; t++) {
        int rowA = wid * 16 + a_row_off;
        uint32_t off = SMEM_SWIZZLE_128B((uint32_t)(rowA * 128 + t * 32 + a_ks_off));
        ldsm4(qf[t][0], qf[t][1], qf[t][2], qf[t][3], sb + FQ + off);
    }

    float mi0 = -INFINITY, mi1 = -INFINITY, li0 = 0.f, li1 = 0.f;
    float o[8][4];
#pragma unroll
    for (int j = 0; j < 8; j++)
#pragma unroll
        for (int r = 0; r < 4; r++) o[j][r] = 0.f;

    const int wrow = qt * 128 + wid * 16;

    for (int kt2 = 0; kt2 <= qt; kt2++) {
        int s = kt2 & 1;
        if (kt2 > 0) {
            asm volatile("cp.async.wait_group 0;" ::: "memory");
            __syncthreads();
        }
        if (kt2 < qt) {
            flash_load_kv128(sb, s ^ 1, kt2 + 1, tid, Kb, Vb);
        }

        uint32_t st = sb + FST + s * FSTAGE;

#pragma unroll
        for (int sub = 0; sub < 2; sub++) {
            const int kbase = kt2 * 128 + sub * 64;
            if (kbase > wrow + 15) continue;

            float sc[8][4];
#pragma unroll
            for (int j = 0; j < 8; j++)
#pragma unroll
                for (int r = 0; r < 4; r++) sc[j][r] = 0.f;

#pragma unroll
            for (int t = 0; t < 4; t++) {
#pragma unroll
                for (int p = 0; p < 4; p++) {
                    uint32_t k4[4];
                    int rowB = sub * 64 + p * 16 + b_row_off;
                    uint32_t off = SMEM_SWIZZLE_128B((uint32_t)(rowB * 128 + t * 32 + b_ks_off));
                    ldsm4(k4[0], k4[1], k4[2], k4[3], st + FK + off);
                    mma_fp16(sc[2 * p],     qf[t], k4[0], k4[1]);
                    mma_fp16(sc[2 * p + 1], qf[t], k4[2], k4[3]);
                }
            }

            // Scores pre-scaled to log2 domain; mask only on diagonal sub-tiles.
            const int row0 = wrow + g, row1 = row0 + 8;
            if (kbase + 63 > wrow) {
#pragma unroll
                for (int j = 0; j < 8; j++) {
                    int col0 = kbase + j * 8 + 2 * c, col1 = col0 + 1;
                    if (col0 > row0) sc[j][0] = -INFINITY;
                    if (col1 > row0) sc[j][1] = -INFINITY;
                    if (col0 > row1) sc[j][2] = -INFINITY;
                    if (col1 > row1) sc[j][3] = -INFINITY;
                }
            }
            float rm0 = -INFINITY, rm1 = -INFINITY;
#pragma unroll
            for (int j = 0; j < 8; j++) {
                rm0 = fmaxf(rm0, fmaxf(sc[j][0], sc[j][1]));
                rm1 = fmaxf(rm1, fmaxf(sc[j][2], sc[j][3]));
            }
            rm0 = fmaxf(rm0, __shfl_xor_sync(0xffffffffu, rm0, 1));
            rm0 = fmaxf(rm0, __shfl_xor_sync(0xffffffffu, rm0, 2));
            rm1 = fmaxf(rm1, __shfl_xor_sync(0xffffffffu, rm1, 1));
            rm1 = fmaxf(rm1, __shfl_xor_sync(0xffffffffu, rm1, 2));

            float mn0 = fmaxf(mi0, rm0), mn1 = fmaxf(mi1, rm1);
            float al0 = exp2f(mi0 - mn0), al1 = exp2f(mi1 - mn1);
#pragma unroll
            for (int j = 0; j < 8; j++) {
                sc[j][0] = exp2f(sc[j][0] - mn0);
                sc[j][1] = exp2f(sc[j][1] - mn0);
                sc[j][2] = exp2f(sc[j][2] - mn1);
                sc[j][3] = exp2f(sc[j][3] - mn1);
            }

            uint32_t ph[4][4];
#pragma unroll
            for (int t = 0; t < 4; t++) {
                ph[t][0] = pack_h2(sc[2 * t][0],     sc[2 * t][1]);
                ph[t][1] = pack_h2(sc[2 * t][2],     sc[2 * t][3]);
                ph[t][2] = pack_h2(sc[2 * t + 1][0], sc[2 * t + 1][1]);
                ph[t][3] = pack_h2(sc[2 * t + 1][2], sc[2 * t + 1][3]);
            }

            // Row-sums via ones-MMA: every output column = row sum of fp16 P.
            float ssum[4] = {0.f, 0.f, 0.f, 0.f};
#pragma unroll
            for (int t = 0; t < 4; t++)
                mma_fp16(ssum, ph[t], H2_ONES, H2_ONES);

            li0 = li0 * al0 + ssum[0];
            li1 = li1 * al1 + ssum[2];
            mi0 = mn0; mi1 = mn1;
#pragma unroll
            for (int j = 0; j < 8; j++) {
                o[j][0] *= al0; o[j][1] *= al0;
                o[j][2] *= al1; o[j][3] *= al1;
            }

#pragma unroll
            for (int t = 0; t < 4; t++) {
#pragma unroll
                for (int jp = 0; jp < 4; jp++) {
                    uint32_t soff = SMEM_SWIZZLE_128B(
                        (uint32_t)((sub * 64 + 16 * t + v_half * 8 + v_l) * 128 + jp * 32 + v_quad * 16));
                    uint32_t v4[4];
                    ldsm4t(v4[0], v4[1], v4[2], v4[3], st + FV + soff);
                    mma_fp16(o[2 * jp],     ph[t], v4[0], v4[1]);
                    mma_fp16(o[2 * jp + 1], ph[t], v4[2], v4[3]);
                }
            }
        }
    }

    float iv0 = 1.f / li0, iv1 = 1.f / li1;
    size_t r0off = ((size_t)(b * S_ + wrow + g)) * D_ + h * HD_;
    size_t r1off = r0off + 8 * D_;
#pragma unroll
    for (int j = 0; j < 8; j++) {
        int col = j * 8 + 2 * c;
        *(uint32_t*)(O_g + r0off + col) = pack_h2(o[j][0] * iv0, o[j][1] * iv0);
        *(uint32_t*)(O_g + r1off + col) = pack_h2(o[j][2] * iv1, o[j][3] * iv1);
    }
}

// ---------------------------------------------------------------------------
extern "C" void kernel_launch(void* const* d_in, const int* in_sizes, int n_in,
                              void* d_out, int out_size)
{
    const float* Q  = (const float*)d_in[0];
    const float* K  = (const float*)d_in[1];
    const float* V  = (const float*)d_in[2];
    const float* Wq = (const float*)d_in[3];
    const float* bq = (const float*)d_in[4];
    const float* Wk = (const float*)d_in[5];
    const float* bk = (const float*)d_in[6];
    const float* Wv = (const float*)d_in[7];
    const float* bv = (const float*)d_in[8];
    const float* Wo = (const float*)d_in[9];
    const float* bo = (const float*)d_in[10];
    float* out = (float*)d_out;

    float2* grope;
    __half *gx3, *gwqkv, *gw16, *gq16, *gk16, *gv16, *go16;
    cudaGetSymbolAddress((void**)&grope, g_rope);
    cudaGetSymbolAddress((void**)&gx3, g_x3);
    cudaGetSymbolAddress((void**)&gwqkv, g_wqkv);
    cudaGetSymbolAddress((void**)&gw16, g_w16);
    cudaGetSymbolAddress((void**)&gq16, g_q16);
    cudaGetSymbolAddress((void**)&gk16, g_k16);
    cudaGetSymbolAddress((void**)&gv16, g_v16);
    cudaGetSymbolAddress((void**)&go16, g_o16);

    cudaFuncSetAttribute(gemm_qkv, cudaFuncAttributeMaxDynamicSharedMemorySize, GEMM_SMEM);
    cudaFuncSetAttribute(gemm_out, cudaFuncAttributeMaxDynamicSharedMemorySize, GEMM_SMEM);
    cudaFuncSetAttribute(flash_mma, cudaFuncAttributeMaxDynamicSharedMemorySize, FLASH_SMEM);

    const int n4x = NTOT / 4;
    const int n4w = (D_ * D_) / 4;

    cvt16x3_kernel<<<(3 * n4x + 255) / 256, 256>>>(Q, K, V, gx3, grope, n4x);
    cvt16x4w_kernel<<<(4 * n4w + 255) / 256, 256>>>(Wq, Wk, Wv, Wo, gwqkv, gw16, n4w);

    dim3 qkvgrid(3 * D_ / 128, M_ / 128);
    gemm_qkv<<<qkvgrid, 256, GEMM_SMEM>>>(gx3, gwqkv, bq, bk, bv, grope,
                                          gq16, gk16, gv16);

    dim3 fgrid(S_ / 128, H_, B_);
    flash_mma<<<fgrid, 256, FLASH_SMEM>>>(gq16, gk16, gv16, go16);

    dim3 ogrid(D_ / 128, M_ / 128);
    gemm_out<<<ogrid, 256, GEMM_SMEM>>>(go16, gw16, bo, out);
}